// round 10
// baseline (speedup 1.0000x reference)
#include <cuda_runtime.h>
#include <cuda_bf16.h>
#include <math.h>
#include <cstdint>

#define TTOT 131072
#define SCALE 0.17677669529663687f
#define GN_N 1048576.0f

typedef unsigned long long ull;

__device__ __forceinline__ ull pack2(float a, float b) {
    ull r; asm("mov.b64 %0, {%1, %2};" : "=l"(r) : "f"(a), "f"(b)); return r;
}
__device__ __forceinline__ void unpack2(ull p, float& a, float& b) {
    asm("mov.b64 {%0, %1}, %2;" : "=f"(a), "=f"(b) : "l"(p));
}
__device__ __forceinline__ void ffma2(ull& d, ull a, ull b) {
    asm("fma.rn.f32x2 %0, %1, %2, %0;" : "+l"(d) : "l"(a), "l"(b));
}
__device__ __forceinline__ void mma16816(float* d, const uint32_t* a, const uint32_t* b) {
    asm volatile("mma.sync.aligned.m16n8k16.row.col.f32.bf16.bf16.f32 "
        "{%0,%1,%2,%3}, {%4,%5,%6,%7}, {%8,%9}, {%0,%1,%2,%3};"
        : "+f"(d[0]), "+f"(d[1]), "+f"(d[2]), "+f"(d[3])
        : "r"(a[0]), "r"(a[1]), "r"(a[2]), "r"(a[3]), "r"(b[0]), "r"(b[1]));
}
__device__ __forceinline__ void ldsm4(uint32_t& r0, uint32_t& r1, uint32_t& r2, uint32_t& r3,
                                      uint32_t addr) {
    asm volatile("ldmatrix.sync.aligned.m8n8.x4.shared.b16 {%0,%1,%2,%3}, [%4];"
                 : "=r"(r0), "=r"(r1), "=r"(r2), "=r"(r3) : "r"(addr));
}
__device__ __forceinline__ uint32_t smem_u32(const void* p) {
    uint32_t a;
    asm("{ .reg .u64 t; cvta.to.shared.u64 t, %1; cvt.u32.u64 %0, t; }" : "=r"(a) : "l"(p));
    return a;
}
__device__ __forceinline__ float bf2f(__nv_bfloat16 h) { return __bfloat162float(h); }

#define CP_A16(d, s) asm volatile("cp.async.cg.shared.global [%0], [%1], 16;" :: "r"(d), "l"(s) : "memory")
#define CP_COMMIT()  asm volatile("cp.async.commit_group;" ::: "memory")
#define CP_WAIT3()   asm volatile("cp.async.wait_group 3;" ::: "memory")

// ---------------- scratch ----------------
__device__ __nv_bfloat16 g_xs  [(size_t)TTOT*768];
__device__ __nv_bfloat16 g_ks  [(size_t)TTOT*768];
__device__ __nv_bfloat16 g_atts[(size_t)TTOT*768];
__device__ __nv_bfloat16 g_uphi[(size_t)TTOT*64];
__device__ __nv_bfloat16 g_uplo[(size_t)TTOT*64];
__device__ __nv_bfloat16 g_uls2[(size_t)TTOT*192];
__device__ float g_q  [(size_t)TTOT*256];
__device__ float g_v  [(size_t)TTOT*256];
__device__ float g_qa [(size_t)TTOT*256];
__device__ float g_ka [(size_t)TTOT*256];
__device__ float g_y1 [(size_t)TTOT*256];
__device__ float g_y2 [(size_t)TTOT*192];
__device__ __nv_bfloat16 g_bq    [768*768];
__device__ __nv_bfloat16 g_bout  [256*768];
__device__ __nv_bfloat16 g_bsq   [128*768];
__device__ __nv_bfloat16 g_bconv2[2*128*1088];
__device__ __nv_bfloat16 g_bpwc2n[256*192];
__device__ float g_gnstats[2*16*2];
__device__ float g_pool[2*512];
__device__ float g_misc[4];

// ---------------- small utilities ----------------
__global__ void zero_small() {
    int i = blockIdx.x*256 + threadIdx.x;
    if (i < 1024) g_pool[i] = 0.f;
    if (i < 64)   g_gnstats[i] = 0.f;
}
__global__ void sum_gnw(const float* __restrict__ gn_w) {
    __shared__ float sh[256];
    sh[threadIdx.x] = gn_w[threadIdx.x];
    __syncthreads();
    for (int st = 128; st > 0; st >>= 1) {
        if (threadIdx.x < st) sh[threadIdx.x] += sh[threadIdx.x + st];
        __syncthreads();
    }
    if (threadIdx.x == 0) g_misc[0] = sh[0];
}
__global__ void prep_bw(const float* __restrict__ w, __nv_bfloat16* __restrict__ dst, int N) {
    int i = blockIdx.x*256 + threadIdx.x;
    if (i >= N*768) return;
    int n = i / 768, kp = i % 768;
    int seg = kp >> 8, kk = kp & 255;
    float v = w[n*256 + kk];
    __nv_bfloat16 h = __float2bfloat16(v);
    dst[i] = (seg == 2) ? __float2bfloat16(v - bf2f(h)) : h;
}
__global__ void prep_bsq(const float* __restrict__ sq1, const float* __restrict__ sq2) {
    int i = blockIdx.x*256 + threadIdx.x;
    if (i >= 128*768) return;
    int n = i / 768, kp = i % 768;
    int seg = kp >> 8, kk = kp & 255;
    float w = 0.f;
    if (n < 64)  { if (kk < 128)  w = sq1[n*128 + kk]; }
    else         { if (kk >= 128) w = sq2[(n-64)*128 + (kk-128)]; }
    __nv_bfloat16 h = __float2bfloat16(w);
    g_bsq[i] = (seg == 2) ? __float2bfloat16(w - bf2f(h)) : h;
}
__global__ void prep_bconv2(const float* __restrict__ gwc, const float* __restrict__ pwc1) {
    int i = blockIdx.x*256 + threadIdx.x;
    if (i >= 2*128*1088) return;
    int z = i / (128*1088), r = i % (128*1088);
    int n = r / 1088, kp = r % 1088;
    float w = 0.f; int seg = 0;
    if (kp < 1056) {
        seg = kp / 352;
        int kk = kp - seg*352;
        int c = z*128 + n;
        if (kk < 288) { int tap = kk >> 5, kl = kk & 31; w = gwc[c*288 + kl*9 + tap]; }
        else          w = pwc1[c*64 + kk - 288];
    }
    __nv_bfloat16 h = __float2bfloat16(w);
    g_bconv2[i] = (seg == 2) ? __float2bfloat16(w - bf2f(h)) : h;
}
__global__ void prep_bpwc2n(const float* __restrict__ pwc2) {
    int i = blockIdx.x*256 + threadIdx.x;
    if (i >= 256*192) return;
    int n = i / 192, kp = i % 192;
    int seg = kp >> 6, kk = kp & 63;
    float w = (n < 192) ? pwc2[n*64 + kk] : 0.f;
    __nv_bfloat16 h = __float2bfloat16(w);
    g_bpwc2n[i] = (seg == 2) ? __float2bfloat16(w - bf2f(h)) : h;
}

// ---------------- roll + split x ----------------
__global__ __launch_bounds__(256) void xsplit(const float* __restrict__ x) {
    __shared__ float s[256][33];
    int bid = blockIdx.x;
    int b = bid >> 11, rem = bid & 2047;
    int hr = rem >> 3, w0 = (rem & 7) << 5;
    int tid = threadIdx.x, wid = tid >> 5, lane = tid & 31;
    int hs = ((hr + 4) & 255) << 8;
    for (int i = 0; i < 32; i++) {
        int idx = (i << 8) + tid;
        int c = idx >> 5, wp = idx & 31;
        s[c][wp] = x[(size_t)((b << 8) + c)*65536 + hs + ((w0 + wp + 4) & 255)];
    }
    __syncthreads();
    size_t t = (size_t)(b << 16) + (hr << 8) + w0 + lane;
    int c0 = wid << 5;
    __nv_bfloat16* dst = &g_xs[t*768];
    for (int j = 0; j < 32; j += 8) {
        __nv_bfloat16 hv[8], lv[8];
#pragma unroll
        for (int e = 0; e < 8; e++) {
            float a = s[c0 + j + e][lane];
            hv[e] = __float2bfloat16(a);
            lv[e] = __float2bfloat16(a - bf2f(hv[e]));
        }
        *(uint4*)&dst[c0 + j]       = *(uint4*)hv;
        *(uint4*)&dst[256 + c0 + j] = *(uint4*)lv;
        *(uint4*)&dst[512 + c0 + j] = *(uint4*)hv;
    }
}

// ---------------- epilogues ----------------
struct EQKVt {
    const float* bias;
    __device__ void st2(int m, int n, int z, float v0, float v1) const {
        v0 += bias[n]; v1 += bias[n+1];
        if (n < 256) {
            *(float2*)&g_q[(size_t)m*256 + n] = make_float2(v0, v1);
        } else if (n < 512) {
            int c = n - 256;
            __nv_bfloat16 h0 = __float2bfloat16(v0), h1 = __float2bfloat16(v1);
            __nv_bfloat162 hh = __halves2bfloat162(h0, h1);
            *(__nv_bfloat162*)&g_ks[(size_t)m*768 + c] = hh;
            *(__nv_bfloat162*)&g_ks[(size_t)m*768 + 256 + c] = __halves2bfloat162(
                __float2bfloat16(v0 - bf2f(h0)), __float2bfloat16(v1 - bf2f(h1)));
            *(__nv_bfloat162*)&g_ks[(size_t)m*768 + 512 + c] = hh;
        } else {
            *(float2*)&g_v[(size_t)m*256 + n - 512] = make_float2(v0, v1);
        }
    }
};
struct EOutT {
    const float* bias;
    __device__ void st2(int m, int n, int z, float v0, float v1) const {
        *(float2*)&g_qa[(size_t)m*256 + n] = make_float2(v0 + bias[n], v1 + bias[n+1]);
    }
};
struct ESQ {
    __device__ void st2(int m, int n, int z, float v0, float v1) const {
        __nv_bfloat16 h0 = __float2bfloat16(v0), h1 = __float2bfloat16(v1);
        __nv_bfloat16 l0 = __float2bfloat16(v0 - bf2f(h0)), l1 = __float2bfloat16(v1 - bf2f(h1));
        if (n < 64) {
            *(__nv_bfloat162*)&g_uphi[(size_t)m*64 + n] = __halves2bfloat162(h0, h1);
            *(__nv_bfloat162*)&g_uplo[(size_t)m*64 + n] = __halves2bfloat162(l0, l1);
        } else {
            int nl = n - 64;
            __nv_bfloat162 hh = __halves2bfloat162(h0, h1);
            *(__nv_bfloat162*)&g_uls2[(size_t)m*192 + nl]       = hh;
            *(__nv_bfloat162*)&g_uls2[(size_t)m*192 + 64 + nl]  = __halves2bfloat162(l0, l1);
            *(__nv_bfloat162*)&g_uls2[(size_t)m*192 + 128 + nl] = hh;
        }
    }
};
struct EY2h {
    __device__ void st2(int m, int n, int z, float v0, float v1) const {
        if (n < 192) *(float2*)&g_y2[(size_t)m*192 + n] = make_float2(v0, v1);
    }
};

// ---------------- 4-stage async HMMA GEMM (K32 chunks, ldmatrix frags) ----------------
// stage layout (elems): [A: 2 groups x 128 x 24 = 6144 | B: same 6144] = 12288 elems = 24KB
template<class EF>
__global__ __launch_bounds__(256, 2) void hgemmA(const __nv_bfloat16* __restrict__ A, int lda,
                                                 const __nv_bfloat16* __restrict__ B, int ldb,
                                                 int nch, EF ef) {
    extern __shared__ __nv_bfloat16 sm[];
    int tid = threadIdx.x, lane = tid & 31, wid = tid >> 5;
    int m0 = blockIdx.y << 7, n0 = blockIdx.x << 7;
    uint32_t sbase = smem_u32(sm);
    int wm = (wid & 3) << 5, wn = (wid >> 2) << 6;
    int gid = lane >> 2, tig = lane & 3;
    int lr = lane & 7, lh = (lane >> 3) & 1, lk = lane >> 4;
    uint32_t offA[2];
#pragma unroll
    for (int mf = 0; mf < 2; mf++)
        offA[mf] = (uint32_t)(((wm + (mf << 4) + lr + lh*8)*24 + lk*8) << 1);
    int lq = lane >> 3;
    uint32_t offB[4];
#pragma unroll
    for (int p = 0; p < 4; p++)
        offB[p] = (uint32_t)(((wn + (p << 4) + lr + (lq >> 1)*8)*24 + (lq & 1)*8) << 1);

    float acc[2][8][4];
#pragma unroll
    for (int mf = 0; mf < 2; mf++)
#pragma unroll
        for (int nf = 0; nf < 8; nf++)
#pragma unroll
            for (int e = 0; e < 4; e++) acc[mf][nf][e] = 0.f;

    auto prefetch = [&](int ch, int s) {
        int k0 = ch << 5;
#pragma unroll
        for (int i = 0; i < 2; i++) {
            int idx = (i << 8) + tid;
            int r = idx >> 2, c4 = idx & 3;
            int g = c4 >> 1, c8 = c4 & 1;
            uint32_t da = sbase + (uint32_t)((s*12288 + (g*128 + r)*24 + c8*8) << 1);
            CP_A16(da, A + (size_t)(m0 + r)*lda + k0 + (c4 << 3));
            CP_A16(da + 12288, B + (size_t)(n0 + r)*ldb + k0 + (c4 << 3));
        }
        CP_COMMIT();
    };
#pragma unroll
    for (int p = 0; p < 3; p++) {
        if (p < nch) prefetch(p, p);
        else CP_COMMIT();
    }
    for (int ch = 0; ch < nch; ch++) {
        if (ch + 3 < nch) prefetch(ch + 3, (ch + 3) & 3);
        else CP_COMMIT();
        CP_WAIT3();
        __syncthreads();
        uint32_t stb = sbase + (uint32_t)(((ch & 3)*12288) << 1);
#pragma unroll
        for (int g = 0; g < 2; g++) {
            uint32_t abase = stb + (uint32_t)(g*6144);
            uint32_t bbase = abase + 12288;   // B region of the SAME stage (+6144 elems)
            uint32_t a[2][4], b[8][2];
            ldsm4(a[0][0], a[0][1], a[0][2], a[0][3], abase + offA[0]);
            ldsm4(a[1][0], a[1][1], a[1][2], a[1][3], abase + offA[1]);
            ldsm4(b[0][0], b[0][1], b[1][0], b[1][1], bbase + offB[0]);
            ldsm4(b[2][0], b[2][1], b[3][0], b[3][1], bbase + offB[1]);
            ldsm4(b[4][0], b[4][1], b[5][0], b[5][1], bbase + offB[2]);
            ldsm4(b[6][0], b[6][1], b[7][0], b[7][1], bbase + offB[3]);
#pragma unroll
            for (int mf = 0; mf < 2; mf++)
#pragma unroll
                for (int nf = 0; nf < 8; nf++)
                    mma16816(acc[mf][nf], a[mf], b[nf]);
        }
        __syncthreads();
    }
#pragma unroll
    for (int mf = 0; mf < 2; mf++) {
        int row0 = m0 + wm + (mf << 4) + gid;
#pragma unroll
        for (int nf = 0; nf < 8; nf++) {
            int col = n0 + wn + (nf << 3) + (tig << 1);
            ef.st2(row0,     col, 0, acc[mf][nf][0], acc[mf][nf][1]);
            ef.st2(row0 + 8, col, 0, acc[mf][nf][2], acc[mf][nf][3]);
        }
    }
}

// ---------------- sync gather HMMA GEMM (conv, ldmatrix frags) ----------------
struct AConv2 {
    __device__ uint4 ld8(int m, int k8, int z) const {
        uint4 zr = make_uint4(0, 0, 0, 0);
        if (k8 >= 1056) return zr;
        int seg = (k8 >= 704) ? 2 : ((k8 >= 352) ? 1 : 0);
        int kk = k8 - seg*352;
        const __nv_bfloat16* src = (seg == 1) ? g_uplo : g_uphi;
        if (kk >= 288)
            return *(const uint4*)(src + (size_t)m*64 + (kk - 288));
        int tap = kk >> 5, ki = (z << 5) + (kk & 31);
        int dy = tap/3 - 1, dx = tap - (tap/3)*3 - 1;
        int b = m >> 16, pixi = m & 65535;
        int hr = (pixi >> 8) + dy, wr = (pixi & 255) + dx;
        if ((unsigned)hr > 255u || (unsigned)wr > 255u) return zr;
        return *(const uint4*)(src + (size_t)((b << 16) + (hr << 8) + wr)*64 + ki);
    }
};
__global__ __launch_bounds__(256, 2) void hgemmS(AConv2 af, const __nv_bfloat16* __restrict__ B,
                                                 const float* __restrict__ bias) {
    __shared__ __align__(16) __nv_bfloat16 As[4][128][24];
    __shared__ __align__(16) __nv_bfloat16 Bs[4][128][24];
    int tid = threadIdx.x, lane = tid & 31, wid = tid >> 5;
    int z = blockIdx.z;
    int m0 = blockIdx.y << 7;
    const __nv_bfloat16* Bz = B + (size_t)z*128*1088;
    int wm = (wid & 3) << 5, wn = (wid >> 2) << 6;
    int gid = lane >> 2, tig = lane & 3;
    uint32_t sA = smem_u32(&As[0][0][0]), sB = smem_u32(&Bs[0][0][0]);
    int lr = lane & 7, lh = (lane >> 3) & 1, lk = lane >> 4;
    uint32_t offA[2];
#pragma unroll
    for (int mf = 0; mf < 2; mf++)
        offA[mf] = (uint32_t)(((wm + (mf << 4) + lr + lh*8)*24 + lk*8) << 1);
    int lq = lane >> 3;
    uint32_t offB[4];
#pragma unroll
    for (int p = 0; p < 4; p++)
        offB[p] = (uint32_t)(((wn + (p << 4) + lr + (lq >> 1)*8)*24 + (lq & 1)*8) << 1);

    float acc[2][8][4];
#pragma unroll
    for (int mf = 0; mf < 2; mf++)
#pragma unroll
        for (int nf = 0; nf < 8; nf++)
#pragma unroll
            for (int e = 0; e < 4; e++) acc[mf][nf][e] = 0.f;

    for (int ch = 0; ch < 17; ch++) {
        int k0 = ch << 6;
#pragma unroll
        for (int i = 0; i < 4; i++) {
            int idx = (i << 8) + tid;
            int r = idx >> 3, c8 = idx & 7;
            *(uint4*)&As[c8 >> 1][r][(c8 & 1) << 3] = af.ld8(m0 + r, k0 + (c8 << 3), z);
            *(uint4*)&Bs[c8 >> 1][r][(c8 & 1) << 3] = *(const uint4*)(Bz + (size_t)r*1088 + k0 + (c8 << 3));
        }
        __syncthreads();
#pragma unroll
        for (int g = 0; g < 4; g++) {
            uint32_t abase = sA + (uint32_t)(g*6144);
            uint32_t bbase = sB + (uint32_t)(g*6144);
            uint32_t a[2][4], b[8][2];
            ldsm4(a[0][0], a[0][1], a[0][2], a[0][3], abase + offA[0]);
            ldsm4(a[1][0], a[1][1], a[1][2], a[1][3], abase + offA[1]);
            ldsm4(b[0][0], b[0][1], b[1][0], b[1][1], bbase + offB[0]);
            ldsm4(b[2][0], b[2][1], b[3][0], b[3][1], bbase + offB[1]);
            ldsm4(b[4][0], b[4][1], b[5][0], b[5][1], bbase + offB[2]);
            ldsm4(b[6][0], b[6][1], b[7][0], b[7][1], bbase + offB[3]);
#pragma unroll
            for (int mf = 0; mf < 2; mf++)
#pragma unroll
                for (int nf = 0; nf < 8; nf++)
                    mma16816(acc[mf][nf], a[mf], b[nf]);
        }
        __syncthreads();
    }
#pragma unroll
    for (int mf = 0; mf < 2; mf++) {
        int row0 = m0 + wm + (mf << 4) + gid;
#pragma unroll
        for (int nf = 0; nf < 8; nf++) {
            int col = wn + (nf << 3) + (tig << 1);
            int c = (z << 7) + col;
            *(float2*)&g_y1[(size_t)row0*256 + c] =
                make_float2(acc[mf][nf][0] + bias[c], acc[mf][nf][1] + bias[c+1]);
            *(float2*)&g_y1[(size_t)(row0 + 8)*256 + c] =
                make_float2(acc[mf][nf][2] + bias[c], acc[mf][nf][3] + bias[c+1]);
        }
    }
}

// ---------------- GN stats / SRU / CRU glue ----------------
__global__ void gn_stats() {
    int t0 = blockIdx.x * 512;
    int c = threadIdx.x;
    const float* p = g_q + (size_t)t0*256 + c;
    float s = 0.f, s2 = 0.f;
#pragma unroll 4
    for (int i = 0; i < 512; i++) { float v = p[(size_t)i*256]; s += v; s2 += v*v; }
#pragma unroll
    for (int off = 8; off > 0; off >>= 1) {
        s  += __shfl_down_sync(0xffffffff, s,  off, 16);
        s2 += __shfl_down_sync(0xffffffff, s2, off, 16);
    }
    if ((c & 15) == 0) {
        int b = t0 >> 16, g = c >> 4;
        atomicAdd(&g_gnstats[((b << 4) + g)*2],     s);
        atomicAdd(&g_gnstats[((b << 4) + g)*2 + 1], s2);
    }
}
__global__ void sru_elem(const float* __restrict__ gn_w, const float* __restrict__ gn_b) {
    int i = blockIdx.x*256 + threadIdx.x;
    int t = i >> 7, cp = i & 127;
    int b = t >> 16;
    int c1 = cp, c2 = cp + 128;
    float wsum = g_misc[0];
    int g1 = c1 >> 4, g2 = c2 >> 4;
    float m1 = g_gnstats[((b<<4)+g1)*2] / GN_N;
    float v1 = g_gnstats[((b<<4)+g1)*2+1] / GN_N - m1*m1;
    float m2 = g_gnstats[((b<<4)+g2)*2] / GN_N;
    float v2 = g_gnstats[((b<<4)+g2)*2+1] / GN_N - m2*m2;
    float w1c = gn_w[c1], w2c = gn_w[c2];
    float A1 = rsqrtf(v1 + 1e-5f)*w1c, B1 = gn_b[c1] - m1*rsqrtf(v1 + 1e-5f)*w1c;
    float A2 = rsqrtf(v2 + 1e-5f)*w2c, B2 = gn_b[c2] - m2*rsqrtf(v2 + 1e-5f)*w2c;
    float x1 = g_q[(size_t)t*256 + c1], x2 = g_q[(size_t)t*256 + c2];
    float rw1 = 1.0f/(1.0f + expf(-(x1*A1 + B1)*(w1c/wsum)));
    float rw2 = 1.0f/(1.0f + expf(-(x2*A2 + B2)*(w2c/wsum)));
    float w11 = rw1 > 0.5f ? 1.0f : rw1, w21 = rw1 > 0.5f ? 0.0f : rw1;
    float w12 = rw2 > 0.5f ? 1.0f : rw2, w22 = rw2 > 0.5f ? 0.0f : rw2;
    g_qa[(size_t)t*256 + c1] = w11*x1 + w22*x2;
    g_qa[(size_t)t*256 + c2] = w12*x2 + w21*x1;
}
__global__ void pool_kernel() {
    int t0 = blockIdx.x * 256;
    int b = t0 >> 16;
    int tid = threadIdx.x;
    float a1 = 0.f, a2 = 0.f, a3 = 0.f;
    for (int t = t0; t < t0 + 256; t++) {
        a1 += g_y1[(size_t)t*256 + tid];
        if (tid < 192) a2 += g_y2[(size_t)t*192 + tid];
        if (tid < 64)  a3 += bf2f(g_uls2[(size_t)t*192 + tid]) + bf2f(g_uls2[(size_t)t*192 + 64 + tid]);
    }
    atomicAdd(&g_pool[(b << 9) + tid], a1);
    if (tid < 192) atomicAdd(&g_pool[(b << 9) + 256 + tid], a2);
    if (tid < 64)  atomicAdd(&g_pool[(b << 9) + 448 + tid], a3);
}
__global__ void softmax512() {
    int b = blockIdx.x, t = threadIdx.x;
    __shared__ float sh[512];
    float v = g_pool[(b << 9) + t] * (1.0f/65536.0f);
    sh[t] = v;
    __syncthreads();
    for (int st = 256; st > 0; st >>= 1) { if (t < st) sh[t] = fmaxf(sh[t], sh[t + st]); __syncthreads(); }
    float mx = sh[0];
    __syncthreads();
    float e = expf(v - mx);
    sh[t] = e;
    __syncthreads();
    for (int st = 256; st > 0; st >>= 1) { if (t < st) sh[t] += sh[t + st]; __syncthreads(); }
    float sum = sh[0];
    __syncthreads();
    g_pool[(b << 9) + t] = e / sum;
}
__global__ void cru_combine() {
    int i = blockIdx.x*256 + threadIdx.x;
    int t = i >> 8, c = i & 255;
    int b = t >> 16;
    float y1 = g_y1[i];
    float y2v;
    if (c < 192) y2v = g_y2[(size_t)t*192 + c];
    else {
        int nl = c - 192;
        y2v = bf2f(g_uls2[(size_t)t*192 + nl]) + bf2f(g_uls2[(size_t)t*192 + 64 + nl]);
    }
    g_ka[(size_t)t*256 + c] = g_pool[(b << 9) + c]*y1 + g_pool[(b << 9) + 256 + c]*y2v;
}

// ---------------- windowed attention ----------------
__global__ __launch_bounds__(64) void attn(const float* __restrict__ rel_pos) {
    int win = blockIdx.x, h = blockIdx.y, b = blockIdx.z;
    __shared__ __align__(16) float ksh[2048];
    __shared__ __align__(16) float vsh[2048];
    __shared__ float rp[225];
    int wy = win >> 5, wx = win & 31;
    int t0 = (b << 16) + (wy << 11) + (wx << 3);
    int tid = threadIdx.x;
    int hb = h << 5;
    for (int i = tid; i < 2048; i += 64) {
        int p = i >> 5, d = i & 31;
        int t = t0 + ((p >> 3) << 8) + (p & 7);
        ksh[i] = g_ka[(size_t)t*256 + hb + d];
        vsh[i] = g_v [(size_t)t*256 + hb + d];
    }
    for (int i = tid; i < 225; i += 64) rp[i] = rel_pos[h*225 + i];
    __syncthreads();
    int myt = t0 + ((tid >> 3) << 8) + (tid & 7);
    ull qp[16];
#pragma unroll
    for (int d = 0; d < 16; d++) {
        float2 qv = *(const float2*)&g_qa[(size_t)myt*256 + hb + 2*d];
        qp[d] = pack2(qv.x, qv.y);
    }
    int ph = tid >> 3, pw = tid & 7;
    bool lr = wy == 31, lc = wx == 31;
    ull zz = pack2(0.f, 0.f);
    float s[64];
#pragma unroll
    for (int qi = 0; qi < 64; qi++) {
        const ull* kp = (const ull*)&ksh[qi*32];
        ull dp = zz;
#pragma unroll
        for (int d = 0; d < 16; d++) ffma2(dp, qp[d], kp[d]);
        float dl, dh;
        unpack2(dp, dl, dh);
        int qh = qi >> 3, qw = qi & 7;
        float val = (dl + dh)*SCALE + rp[(ph - qh + 7)*15 + (pw - qw + 7)];
        if ((lr && ((ph < 4) != (qh < 4))) || (lc && ((pw < 4) != (qw < 4)))) val = -1e30f;
        s[qi] = val;
    }
    float mx = -1e30f;
#pragma unroll
    for (int qi = 0; qi < 64; qi++) mx = fmaxf(mx, s[qi]);
    float sum = 0.f;
#pragma unroll
    for (int qi = 0; qi < 64; qi++) { s[qi] = expf(s[qi] - mx); sum += s[qi]; }
    float inv = 1.0f / sum;
    ull accp[16];
#pragma unroll
    for (int d = 0; d < 16; d++) accp[d] = zz;
#pragma unroll
    for (int qi = 0; qi < 64; qi++) {
        ull wd = pack2(s[qi]*inv, s[qi]*inv);
        const ull* vp = (const ull*)&vsh[qi*32];
#pragma unroll
        for (int d = 0; d < 16; d++) ffma2(accp[d], wd, vp[d]);
    }
    float af[32];
#pragma unroll
    for (int d = 0; d < 16; d++) unpack2(accp[d], af[2*d], af[2*d+1]);
    __nv_bfloat16* dst = &g_atts[(size_t)myt*768];
#pragma unroll
    for (int d0 = 0; d0 < 32; d0 += 8) {
        __nv_bfloat16 hv[8], lv[8];
#pragma unroll
        for (int e = 0; e < 8; e++) {
            hv[e] = __float2bfloat16(af[d0 + e]);
            lv[e] = __float2bfloat16(af[d0 + e] - bf2f(hv[e]));
        }
        *(uint4*)&dst[hb + d0]       = *(uint4*)hv;
        *(uint4*)&dst[256 + hb + d0] = *(uint4*)lv;
        *(uint4*)&dst[512 + hb + d0] = *(uint4*)hv;
    }
}

// ---------------- final un-roll scatter to NCHW ----------------
__global__ __launch_bounds__(256) void unscatter(float* __restrict__ out) {
    __shared__ float s2[32][261];
    int bid = blockIdx.x;
    int b = bid >> 11, rem = bid & 2047;
    int hr = rem >> 3, w0 = (rem & 7) << 5;
    int tid = threadIdx.x;
    size_t tbase = (size_t)(b << 16) + (hr << 8) + w0;
    for (int i = 0; i < 8; i++) {
        int idx = (i << 8) + tid;
        int tw = idx >> 6, c4 = idx & 63;
        float4 v = *(const float4*)&g_qa[(tbase + tw)*256 + (c4 << 2)];
        s2[tw][(c4 << 2)]     = v.x;
        s2[tw][(c4 << 2) + 1] = v.y;
        s2[tw][(c4 << 2) + 2] = v.z;
        s2[tw][(c4 << 2) + 3] = v.w;
    }
    __syncthreads();
    int hs = ((hr + 4) & 255) << 8;
    for (int i = 0; i < 32; i++) {
        int idx = (i << 8) + tid;
        int c = idx >> 5, wp = idx & 31;
        out[(size_t)((b << 8) + c)*65536 + hs + ((w0 + wp + 4) & 255)] = s2[wp][c];
    }
}

// ---------------- launch ----------------
extern "C" void kernel_launch(void* const* d_in, const int* in_sizes, int n_in,
                              void* d_out, int out_size) {
    const float* x      = (const float*)d_in[0];
    const float* w_qkv  = (const float*)d_in[1];
    const float* b_qkv  = (const float*)d_in[2];
    const float* rel_pos= (const float*)d_in[3];
    const float* gn_w   = (const float*)d_in[4];
    const float* gn_b   = (const float*)d_in[5];
    const float* sq1    = (const float*)d_in[6];
    const float* sq2    = (const float*)d_in[7];
    const float* gwc    = (const float*)d_in[8];
    const float* gwc_b  = (const float*)d_in[9];
    const float* pwc1   = (const float*)d_in[10];
    const float* pwc2   = (const float*)d_in[11];
    const float* w_out  = (const float*)d_in[12];
    const float* b_out  = (const float*)d_in[13];
    float* out = (float*)d_out;

    __nv_bfloat16 *p_bq, *p_bout, *p_bsq, *p_bconv2, *p_bpwc2n, *p_xs, *p_ks, *p_atts, *p_uls2;
    cudaGetSymbolAddress((void**)&p_bq,     g_bq);
    cudaGetSymbolAddress((void**)&p_bout,   g_bout);
    cudaGetSymbolAddress((void**)&p_bsq,    g_bsq);
    cudaGetSymbolAddress((void**)&p_bconv2, g_bconv2);
    cudaGetSymbolAddress((void**)&p_bpwc2n, g_bpwc2n);
    cudaGetSymbolAddress((void**)&p_xs,     g_xs);
    cudaGetSymbolAddress((void**)&p_ks,     g_ks);
    cudaGetSymbolAddress((void**)&p_atts,   g_atts);
    cudaGetSymbolAddress((void**)&p_uls2,   g_uls2);

    const int DSM = 98304;   // 4 stages x 24KB
    cudaFuncSetAttribute(hgemmA<EQKVt>, cudaFuncAttributeMaxDynamicSharedMemorySize, DSM);
    cudaFuncSetAttribute(hgemmA<EOutT>, cudaFuncAttributeMaxDynamicSharedMemorySize, DSM);
    cudaFuncSetAttribute(hgemmA<ESQ>,   cudaFuncAttributeMaxDynamicSharedMemorySize, DSM);
    cudaFuncSetAttribute(hgemmA<EY2h>,  cudaFuncAttributeMaxDynamicSharedMemorySize, DSM);

    zero_small<<<4, 256>>>();                                          // 0
    prep_bw<<<(768*768 + 255)/256, 256>>>(w_qkv, p_bq, 768);           // 1
    xsplit<<<4096, 256>>>(x);                                          // 2
    hgemmA<EQKVt><<<dim3(6, 1024), 256, DSM>>>(p_xs, 768, p_bq, 768, 24, EQKVt{b_qkv});  // 3 (profiled)

    gn_stats<<<256, 256>>>();
    sum_gnw<<<1, 256>>>(gn_w);
    sru_elem<<<65536, 256>>>(gn_w, gn_b);

    prep_bsq<<<(128*768 + 255)/256, 256>>>(sq1, sq2);
    hgemmA<ESQ><<<dim3(1, 1024), 256, DSM>>>(p_ks, 768, p_bsq, 768, 24, ESQ{});
    prep_bconv2<<<(2*128*1088 + 255)/256, 256>>>(gwc, pwc1);
    hgemmS<<<dim3(1, 1024, 2), 256>>>(AConv2{}, p_bconv2, gwc_b);
    prep_bpwc2n<<<(256*192 + 255)/256, 256>>>(pwc2);
    hgemmA<EY2h><<<dim3(2, 1024), 256, DSM>>>(p_uls2, 192, p_bpwc2n, 192, 6, EY2h{});

    pool_kernel<<<512, 256>>>();
    softmax512<<<2, 512>>>();
    cru_combine<<<131072, 256>>>();

    attn<<<dim3(1024, 8, 2), 64>>>(rel_pos);
    prep_bw<<<(256*768 + 255)/256, 256>>>(w_out, p_bout, 256);
    hgemmA<EOutT><<<dim3(2, 1024), 256, DSM>>>(p_atts, 768, p_bout, 768, 24, EOutT{b_out});
    unscatter<<<4096, 256>>>(out);
}

// round 11
// speedup vs baseline: 1.1148x; 1.1148x over previous
#include <cuda_runtime.h>
#include <cuda_bf16.h>
#include <math.h>
#include <cstdint>

#define TTOT 131072
#define SCALE 0.17677669529663687f
#define GN_N 1048576.0f

typedef unsigned long long ull;

__device__ __forceinline__ ull pack2(float a, float b) {
    ull r; asm("mov.b64 %0, {%1, %2};" : "=l"(r) : "f"(a), "f"(b)); return r;
}
__device__ __forceinline__ void unpack2(ull p, float& a, float& b) {
    asm("mov.b64 {%0, %1}, %2;" : "=f"(a), "=f"(b) : "l"(p));
}
__device__ __forceinline__ void ffma2(ull& d, ull a, ull b) {
    asm("fma.rn.f32x2 %0, %1, %2, %0;" : "+l"(d) : "l"(a), "l"(b));
}
__device__ __forceinline__ void mma16816(float* d, const uint32_t* a, const uint32_t* b) {
    asm volatile("mma.sync.aligned.m16n8k16.row.col.f32.bf16.bf16.f32 "
        "{%0,%1,%2,%3}, {%4,%5,%6,%7}, {%8,%9}, {%0,%1,%2,%3};"
        : "+f"(d[0]), "+f"(d[1]), "+f"(d[2]), "+f"(d[3])
        : "r"(a[0]), "r"(a[1]), "r"(a[2]), "r"(a[3]), "r"(b[0]), "r"(b[1]));
}
__device__ __forceinline__ void ldsm4(uint32_t& r0, uint32_t& r1, uint32_t& r2, uint32_t& r3,
                                      uint32_t addr) {
    asm volatile("ldmatrix.sync.aligned.m8n8.x4.shared.b16 {%0,%1,%2,%3}, [%4];"
                 : "=r"(r0), "=r"(r1), "=r"(r2), "=r"(r3) : "r"(addr));
}
__device__ __forceinline__ uint32_t smem_u32(const void* p) {
    uint32_t a;
    asm("{ .reg .u64 t; cvta.to.shared.u64 t, %1; cvt.u32.u64 %0, t; }" : "=r"(a) : "l"(p));
    return a;
}
__device__ __forceinline__ float bf2f(__nv_bfloat16 h) { return __bfloat162float(h); }

#define CP_A16(d, s) asm volatile("cp.async.cg.shared.global [%0], [%1], 16;" :: "r"(d), "l"(s) : "memory")
#define CP_COMMIT()  asm volatile("cp.async.commit_group;" ::: "memory")
#define CP_WAIT1()   asm volatile("cp.async.wait_group 1;" ::: "memory")

// ---------------- scratch ----------------
__device__ __nv_bfloat16 g_xh [(size_t)TTOT*256];
__device__ __nv_bfloat16 g_xl [(size_t)TTOT*256];
__device__ __nv_bfloat16 g_kh [(size_t)TTOT*256];
__device__ __nv_bfloat16 g_kl [(size_t)TTOT*256];
__device__ __nv_bfloat16 g_atth[(size_t)TTOT*256];
__device__ __nv_bfloat16 g_attl[(size_t)TTOT*256];
__device__ __nv_bfloat16 g_uphi[(size_t)TTOT*64];
__device__ __nv_bfloat16 g_uplo[(size_t)TTOT*64];
__device__ __nv_bfloat16 g_ulsh[(size_t)TTOT*64];
__device__ __nv_bfloat16 g_ulsl[(size_t)TTOT*64];
__device__ float g_q  [(size_t)TTOT*256];
__device__ float g_v  [(size_t)TTOT*256];
__device__ float g_qa [(size_t)TTOT*256];
__device__ float g_ka [(size_t)TTOT*256];
__device__ float g_y1 [(size_t)TTOT*256];
__device__ float g_y2 [(size_t)TTOT*192];
__device__ __nv_bfloat16 g_bqh  [768*256];
__device__ __nv_bfloat16 g_bql  [768*256];
__device__ __nv_bfloat16 g_bouth[256*256];
__device__ __nv_bfloat16 g_boutl[256*256];
__device__ __nv_bfloat16 g_bsqh [128*256];
__device__ __nv_bfloat16 g_bsql [128*256];
__device__ __nv_bfloat16 g_bp2h [256*64];
__device__ __nv_bfloat16 g_bp2l [256*64];
__device__ __nv_bfloat16 g_bconv2[2*128*1088];
__device__ float g_gnstats[2*16*2];
__device__ float g_pool[2*512];
__device__ float g_misc[4];

// ---------------- small utilities ----------------
__global__ void zero_small() {
    int i = blockIdx.x*256 + threadIdx.x;
    if (i < 1024) g_pool[i] = 0.f;
    if (i < 64)   g_gnstats[i] = 0.f;
}
__global__ void sum_gnw(const float* __restrict__ gn_w) {
    __shared__ float sh[256];
    sh[threadIdx.x] = gn_w[threadIdx.x];
    __syncthreads();
    for (int st = 128; st > 0; st >>= 1) {
        if (threadIdx.x < st) sh[threadIdx.x] += sh[threadIdx.x + st];
        __syncthreads();
    }
    if (threadIdx.x == 0) g_misc[0] = sh[0];
}
// split weights into separate hi/lo tensors, layout [n][k]
__global__ void prep_bw(const float* __restrict__ w,
                        __nv_bfloat16* __restrict__ dh, __nv_bfloat16* __restrict__ dl, int total) {
    int i = blockIdx.x*256 + threadIdx.x;
    if (i >= total) return;
    float v = w[i];
    __nv_bfloat16 h = __float2bfloat16(v);
    dh[i] = h;
    dl[i] = __float2bfloat16(v - bf2f(h));
}
__global__ void prep_bsq(const float* __restrict__ sq1, const float* __restrict__ sq2) {
    int i = blockIdx.x*256 + threadIdx.x;
    if (i >= 128*256) return;
    int n = i >> 8, k = i & 255;
    float w = 0.f;
    if (n < 64)  { if (k < 128)  w = sq1[n*128 + k]; }
    else         { if (k >= 128) w = sq2[(n-64)*128 + (k-128)]; }
    __nv_bfloat16 h = __float2bfloat16(w);
    g_bsqh[i] = h;
    g_bsql[i] = __float2bfloat16(w - bf2f(h));
}
__global__ void prep_bp2(const float* __restrict__ pwc2) {
    int i = blockIdx.x*256 + threadIdx.x;
    if (i >= 256*64) return;
    int n = i >> 6, k = i & 63;
    float w = (n < 192) ? pwc2[n*64 + k] : 0.f;
    __nv_bfloat16 h = __float2bfloat16(w);
    g_bp2h[i] = h;
    g_bp2l[i] = __float2bfloat16(w - bf2f(h));
}
__global__ void prep_bconv2(const float* __restrict__ gwc, const float* __restrict__ pwc1) {
    int i = blockIdx.x*256 + threadIdx.x;
    if (i >= 2*128*1088) return;
    int z = i / (128*1088), r = i % (128*1088);
    int n = r / 1088, kp = r % 1088;
    float w = 0.f; int seg = 0;
    if (kp < 1056) {
        seg = kp / 352;
        int kk = kp - seg*352;
        int c = z*128 + n;
        if (kk < 288) { int tap = kk >> 5, kl = kk & 31; w = gwc[c*288 + kl*9 + tap]; }
        else          w = pwc1[c*64 + kk - 288];
    }
    __nv_bfloat16 h = __float2bfloat16(w);
    g_bconv2[i] = (seg == 2) ? __float2bfloat16(w - bf2f(h)) : h;
}

// ---------------- roll + split x ----------------
__global__ __launch_bounds__(256) void xsplit(const float* __restrict__ x) {
    __shared__ float s[256][33];
    int bid = blockIdx.x;
    int b = bid >> 11, rem = bid & 2047;
    int hr = rem >> 3, w0 = (rem & 7) << 5;
    int tid = threadIdx.x, wid = tid >> 5, lane = tid & 31;
    int hs = ((hr + 4) & 255) << 8;
    for (int i = 0; i < 32; i++) {
        int idx = (i << 8) + tid;
        int c = idx >> 5, wp = idx & 31;
        s[c][wp] = x[(size_t)((b << 8) + c)*65536 + hs + ((w0 + wp + 4) & 255)];
    }
    __syncthreads();
    size_t t = (size_t)(b << 16) + (hr << 8) + w0 + lane;
    int c0 = wid << 5;
    for (int j = 0; j < 32; j += 8) {
        __nv_bfloat16 hv[8], lv[8];
#pragma unroll
        for (int e = 0; e < 8; e++) {
            float a = s[c0 + j + e][lane];
            hv[e] = __float2bfloat16(a);
            lv[e] = __float2bfloat16(a - bf2f(hv[e]));
        }
        *(uint4*)&g_xh[t*256 + c0 + j] = *(uint4*)hv;
        *(uint4*)&g_xl[t*256 + c0 + j] = *(uint4*)lv;
    }
}

// ---------------- epilogues ----------------
struct EQKVt {
    const float* bias;
    __device__ void st2(int m, int n, int z, float v0, float v1) const {
        v0 += bias[n]; v1 += bias[n+1];
        if (n < 256) {
            *(float2*)&g_q[(size_t)m*256 + n] = make_float2(v0, v1);
        } else if (n < 512) {
            int c = n - 256;
            __nv_bfloat16 h0 = __float2bfloat16(v0), h1 = __float2bfloat16(v1);
            *(__nv_bfloat162*)&g_kh[(size_t)m*256 + c] = __halves2bfloat162(h0, h1);
            *(__nv_bfloat162*)&g_kl[(size_t)m*256 + c] = __halves2bfloat162(
                __float2bfloat16(v0 - bf2f(h0)), __float2bfloat16(v1 - bf2f(h1)));
        } else {
            *(float2*)&g_v[(size_t)m*256 + n - 512] = make_float2(v0, v1);
        }
    }
};
struct EOutT {
    const float* bias;
    __device__ void st2(int m, int n, int z, float v0, float v1) const {
        *(float2*)&g_qa[(size_t)m*256 + n] = make_float2(v0 + bias[n], v1 + bias[n+1]);
    }
};
struct ESQ {
    __device__ void st2(int m, int n, int z, float v0, float v1) const {
        __nv_bfloat16 h0 = __float2bfloat16(v0), h1 = __float2bfloat16(v1);
        __nv_bfloat16 l0 = __float2bfloat16(v0 - bf2f(h0)), l1 = __float2bfloat16(v1 - bf2f(h1));
        if (n < 64) {
            *(__nv_bfloat162*)&g_uphi[(size_t)m*64 + n] = __halves2bfloat162(h0, h1);
            *(__nv_bfloat162*)&g_uplo[(size_t)m*64 + n] = __halves2bfloat162(l0, l1);
        } else {
            int nl = n - 64;
            *(__nv_bfloat162*)&g_ulsh[(size_t)m*64 + nl] = __halves2bfloat162(h0, h1);
            *(__nv_bfloat162*)&g_ulsl[(size_t)m*64 + nl] = __halves2bfloat162(l0, l1);
        }
    }
};
struct EY2h {
    __device__ void st2(int m, int n, int z, float v0, float v1) const {
        if (n < 192) *(float2*)&g_y2[(size_t)m*192 + n] = make_float2(v0, v1);
    }
};

// ---------------- dedup split HMMA GEMM ----------------
// per K32 stage loads distinct {Ah, Al, Bh, Bl} chunks once; computes
// Ah*Bh + Al*Bh + Ah*Bl. stage = 4 x 6144 elems = 48KB; 2 stages.
template<class EF>
__global__ __launch_bounds__(256, 2) void hgemmA(const __nv_bfloat16* __restrict__ Ah_,
                                                 const __nv_bfloat16* __restrict__ Al_, int lda,
                                                 const __nv_bfloat16* __restrict__ Bh_,
                                                 const __nv_bfloat16* __restrict__ Bl_, int ldb,
                                                 int nk, EF ef) {
    extern __shared__ __nv_bfloat16 sm[];
    int tid = threadIdx.x, lane = tid & 31, wid = tid >> 5;
    int m0 = blockIdx.y << 7, n0 = blockIdx.x << 7;
    uint32_t sbase = smem_u32(sm);
    int wm = (wid & 3) << 5, wn = (wid >> 2) << 6;
    int gid = lane >> 2, tig = lane & 3;
    int lr = lane & 7, lh = (lane >> 3) & 1, lk = lane >> 4;
    uint32_t offA[2];
#pragma unroll
    for (int mf = 0; mf < 2; mf++)
        offA[mf] = (uint32_t)(((wm + (mf << 4) + lr + lh*8)*24 + lk*8) << 1);
    int lq = lane >> 3;
    uint32_t offB[4];
#pragma unroll
    for (int p = 0; p < 4; p++)
        offB[p] = (uint32_t)(((wn + (p << 4) + lr + (lq >> 1)*8)*24 + (lq & 1)*8) << 1);

    float acc[2][8][4];
#pragma unroll
    for (int mf = 0; mf < 2; mf++)
#pragma unroll
        for (int nf = 0; nf < 8; nf++)
#pragma unroll
            for (int e = 0; e < 4; e++) acc[mf][nf][e] = 0.f;

    auto prefetch = [&](int ch, int s) {
        int k0 = ch << 5;
#pragma unroll
        for (int i = 0; i < 2; i++) {
            int idx = (i << 8) + tid;          // 0..511
            int r = idx >> 2, c4 = idx & 3;
            int g = c4 >> 1, ke = c4 & 1;
            uint32_t da = sbase + (uint32_t)((s*24576 + (g*128 + r)*24 + ke*8) << 1);
            size_t asrc = (size_t)(m0 + r)*lda + k0 + (c4 << 3);
            size_t bsrc = (size_t)(n0 + r)*ldb + k0 + (c4 << 3);
            CP_A16(da,          Ah_ + asrc);
            CP_A16(da + 12288,  Al_ + asrc);
            CP_A16(da + 24576,  Bh_ + bsrc);
            CP_A16(da + 36864,  Bl_ + bsrc);
        }
        CP_COMMIT();
    };
    prefetch(0, 0);
    for (int ch = 0; ch < nk; ch++) {
        if (ch + 1 < nk) prefetch(ch + 1, (ch + 1) & 1);
        else CP_COMMIT();
        CP_WAIT1();
        __syncthreads();
        uint32_t stb = sbase + (uint32_t)((ch & 1)*49152);
#pragma unroll
        for (int g = 0; g < 2; g++) {
            uint32_t gb = stb + (uint32_t)(g*6144);
            uint32_t a[2][4], b[8][2];
            // Bh
            ldsm4(b[0][0], b[0][1], b[1][0], b[1][1], gb + 24576 + offB[0]);
            ldsm4(b[2][0], b[2][1], b[3][0], b[3][1], gb + 24576 + offB[1]);
            ldsm4(b[4][0], b[4][1], b[5][0], b[5][1], gb + 24576 + offB[2]);
            ldsm4(b[6][0], b[6][1], b[7][0], b[7][1], gb + 24576 + offB[3]);
            // Ah
            ldsm4(a[0][0], a[0][1], a[0][2], a[0][3], gb + offA[0]);
            ldsm4(a[1][0], a[1][1], a[1][2], a[1][3], gb + offA[1]);
#pragma unroll
            for (int mf = 0; mf < 2; mf++)
#pragma unroll
                for (int nf = 0; nf < 8; nf++)
                    mma16816(acc[mf][nf], a[mf], b[nf]);
            // Al
            ldsm4(a[0][0], a[0][1], a[0][2], a[0][3], gb + 12288 + offA[0]);
            ldsm4(a[1][0], a[1][1], a[1][2], a[1][3], gb + 12288 + offA[1]);
#pragma unroll
            for (int mf = 0; mf < 2; mf++)
#pragma unroll
                for (int nf = 0; nf < 8; nf++)
                    mma16816(acc[mf][nf], a[mf], b[nf]);
            // Bl + Ah reload
            ldsm4(b[0][0], b[0][1], b[1][0], b[1][1], gb + 36864 + offB[0]);
            ldsm4(b[2][0], b[2][1], b[3][0], b[3][1], gb + 36864 + offB[1]);
            ldsm4(b[4][0], b[4][1], b[5][0], b[5][1], gb + 36864 + offB[2]);
            ldsm4(b[6][0], b[6][1], b[7][0], b[7][1], gb + 36864 + offB[3]);
            ldsm4(a[0][0], a[0][1], a[0][2], a[0][3], gb + offA[0]);
            ldsm4(a[1][0], a[1][1], a[1][2], a[1][3], gb + offA[1]);
#pragma unroll
            for (int mf = 0; mf < 2; mf++)
#pragma unroll
                for (int nf = 0; nf < 8; nf++)
                    mma16816(acc[mf][nf], a[mf], b[nf]);
        }
        __syncthreads();
    }
#pragma unroll
    for (int mf = 0; mf < 2; mf++) {
        int row0 = m0 + wm + (mf << 4) + gid;
#pragma unroll
        for (int nf = 0; nf < 8; nf++) {
            int col = n0 + wn + (nf << 3) + (tig << 1);
            ef.st2(row0,     col, 0, acc[mf][nf][0], acc[mf][nf][1]);
            ef.st2(row0 + 8, col, 0, acc[mf][nf][2], acc[mf][nf][3]);
        }
    }
}

// ---------------- sync gather HMMA GEMM (conv, unchanged) ----------------
struct AConv2 {
    __device__ uint4 ld8(int m, int k8, int z) const {
        uint4 zr = make_uint4(0, 0, 0, 0);
        if (k8 >= 1056) return zr;
        int seg = (k8 >= 704) ? 2 : ((k8 >= 352) ? 1 : 0);
        int kk = k8 - seg*352;
        const __nv_bfloat16* src = (seg == 1) ? g_uplo : g_uphi;
        if (kk >= 288)
            return *(const uint4*)(src + (size_t)m*64 + (kk - 288));
        int tap = kk >> 5, ki = (z << 5) + (kk & 31);
        int dy = tap/3 - 1, dx = tap - (tap/3)*3 - 1;
        int b = m >> 16, pixi = m & 65535;
        int hr = (pixi >> 8) + dy, wr = (pixi & 255) + dx;
        if ((unsigned)hr > 255u || (unsigned)wr > 255u) return zr;
        return *(const uint4*)(src + (size_t)((b << 16) + (hr << 8) + wr)*64 + ki);
    }
};
__global__ __launch_bounds__(256, 2) void hgemmS(AConv2 af, const __nv_bfloat16* __restrict__ B,
                                                 const float* __restrict__ bias) {
    __shared__ __align__(16) __nv_bfloat16 As[4][128][24];
    __shared__ __align__(16) __nv_bfloat16 Bs[4][128][24];
    int tid = threadIdx.x, lane = tid & 31, wid = tid >> 5;
    int z = blockIdx.z;
    int m0 = blockIdx.y << 7;
    const __nv_bfloat16* Bz = B + (size_t)z*128*1088;
    int wm = (wid & 3) << 5, wn = (wid >> 2) << 6;
    int gid = lane >> 2, tig = lane & 3;
    uint32_t sA = smem_u32(&As[0][0][0]), sB = smem_u32(&Bs[0][0][0]);
    int lr = lane & 7, lh = (lane >> 3) & 1, lk = lane >> 4;
    uint32_t offA[2];
#pragma unroll
    for (int mf = 0; mf < 2; mf++)
        offA[mf] = (uint32_t)(((wm + (mf << 4) + lr + lh*8)*24 + lk*8) << 1);
    int lq = lane >> 3;
    uint32_t offB[4];
#pragma unroll
    for (int p = 0; p < 4; p++)
        offB[p] = (uint32_t)(((wn + (p << 4) + lr + (lq >> 1)*8)*24 + (lq & 1)*8) << 1);

    float acc[2][8][4];
#pragma unroll
    for (int mf = 0; mf < 2; mf++)
#pragma unroll
        for (int nf = 0; nf < 8; nf++)
#pragma unroll
            for (int e = 0; e < 4; e++) acc[mf][nf][e] = 0.f;

    for (int ch = 0; ch < 17; ch++) {
        int k0 = ch << 6;
#pragma unroll
        for (int i = 0; i < 4; i++) {
            int idx = (i << 8) + tid;
            int r = idx >> 3, c8 = idx & 7;
            *(uint4*)&As[c8 >> 1][r][(c8 & 1) << 3] = af.ld8(m0 + r, k0 + (c8 << 3), z);
            *(uint4*)&Bs[c8 >> 1][r][(c8 & 1) << 3] = *(const uint4*)(Bz + (size_t)r*1088 + k0 + (c8 << 3));
        }
        __syncthreads();
#pragma unroll
        for (int g = 0; g < 4; g++) {
            uint32_t abase = sA + (uint32_t)(g*6144);
            uint32_t bbase = sB + (uint32_t)(g*6144);
            uint32_t a[2][4], b[8][2];
            ldsm4(a[0][0], a[0][1], a[0][2], a[0][3], abase + offA[0]);
            ldsm4(a[1][0], a[1][1], a[1][2], a[1][3], abase + offA[1]);
            ldsm4(b[0][0], b[0][1], b[1][0], b[1][1], bbase + offB[0]);
            ldsm4(b[2][0], b[2][1], b[3][0], b[3][1], bbase + offB[1]);
            ldsm4(b[4][0], b[4][1], b[5][0], b[5][1], bbase + offB[2]);
            ldsm4(b[6][0], b[6][1], b[7][0], b[7][1], bbase + offB[3]);
#pragma unroll
            for (int mf = 0; mf < 2; mf++)
#pragma unroll
                for (int nf = 0; nf < 8; nf++)
                    mma16816(acc[mf][nf], a[mf], b[nf]);
        }
        __syncthreads();
    }
#pragma unroll
    for (int mf = 0; mf < 2; mf++) {
        int row0 = m0 + wm + (mf << 4) + gid;
#pragma unroll
        for (int nf = 0; nf < 8; nf++) {
            int col = wn + (nf << 3) + (tig << 1);
            int c = (z << 7) + col;
            *(float2*)&g_y1[(size_t)row0*256 + c] =
                make_float2(acc[mf][nf][0] + bias[c], acc[mf][nf][1] + bias[c+1]);
            *(float2*)&g_y1[(size_t)(row0 + 8)*256 + c] =
                make_float2(acc[mf][nf][2] + bias[c], acc[mf][nf][3] + bias[c+1]);
        }
    }
}

// ---------------- GN stats / SRU / CRU glue ----------------
__global__ void gn_stats() {
    int t0 = blockIdx.x * 512;
    int c = threadIdx.x;
    const float* p = g_q + (size_t)t0*256 + c;
    float s = 0.f, s2 = 0.f;
#pragma unroll 4
    for (int i = 0; i < 512; i++) { float v = p[(size_t)i*256]; s += v; s2 += v*v; }
#pragma unroll
    for (int off = 8; off > 0; off >>= 1) {
        s  += __shfl_down_sync(0xffffffff, s,  off, 16);
        s2 += __shfl_down_sync(0xffffffff, s2, off, 16);
    }
    if ((c & 15) == 0) {
        int b = t0 >> 16, g = c >> 4;
        atomicAdd(&g_gnstats[((b << 4) + g)*2],     s);
        atomicAdd(&g_gnstats[((b << 4) + g)*2 + 1], s2);
    }
}
__global__ void sru_elem(const float* __restrict__ gn_w, const float* __restrict__ gn_b) {
    int i = blockIdx.x*256 + threadIdx.x;
    int t = i >> 7, cp = i & 127;
    int b = t >> 16;
    int c1 = cp, c2 = cp + 128;
    float wsum = g_misc[0];
    int g1 = c1 >> 4, g2 = c2 >> 4;
    float m1 = g_gnstats[((b<<4)+g1)*2] / GN_N;
    float v1 = g_gnstats[((b<<4)+g1)*2+1] / GN_N - m1*m1;
    float m2 = g_gnstats[((b<<4)+g2)*2] / GN_N;
    float v2 = g_gnstats[((b<<4)+g2)*2+1] / GN_N - m2*m2;
    float w1c = gn_w[c1], w2c = gn_w[c2];
    float A1 = rsqrtf(v1 + 1e-5f)*w1c, B1 = gn_b[c1] - m1*rsqrtf(v1 + 1e-5f)*w1c;
    float A2 = rsqrtf(v2 + 1e-5f)*w2c, B2 = gn_b[c2] - m2*rsqrtf(v2 + 1e-5f)*w2c;
    float x1 = g_q[(size_t)t*256 + c1], x2 = g_q[(size_t)t*256 + c2];
    float rw1 = 1.0f/(1.0f + expf(-(x1*A1 + B1)*(w1c/wsum)));
    float rw2 = 1.0f/(1.0f + expf(-(x2*A2 + B2)*(w2c/wsum)));
    float w11 = rw1 > 0.5f ? 1.0f : rw1, w21 = rw1 > 0.5f ? 0.0f : rw1;
    float w12 = rw2 > 0.5f ? 1.0f : rw2, w22 = rw2 > 0.5f ? 0.0f : rw2;
    g_qa[(size_t)t*256 + c1] = w11*x1 + w22*x2;
    g_qa[(size_t)t*256 + c2] = w12*x2 + w21*x1;
}
__global__ void pool_kernel() {
    int t0 = blockIdx.x * 256;
    int b = t0 >> 16;
    int tid = threadIdx.x;
    float a1 = 0.f, a2 = 0.f, a3 = 0.f;
    for (int t = t0; t < t0 + 256; t++) {
        a1 += g_y1[(size_t)t*256 + tid];
        if (tid < 192) a2 += g_y2[(size_t)t*192 + tid];
        if (tid < 64)  a3 += bf2f(g_ulsh[(size_t)t*64 + tid]) + bf2f(g_ulsl[(size_t)t*64 + tid]);
    }
    atomicAdd(&g_pool[(b << 9) + tid], a1);
    if (tid < 192) atomicAdd(&g_pool[(b << 9) + 256 + tid], a2);
    if (tid < 64)  atomicAdd(&g_pool[(b << 9) + 448 + tid], a3);
}
__global__ void softmax512() {
    int b = blockIdx.x, t = threadIdx.x;
    __shared__ float sh[512];
    float v = g_pool[(b << 9) + t] * (1.0f/65536.0f);
    sh[t] = v;
    __syncthreads();
    for (int st = 256; st > 0; st >>= 1) { if (t < st) sh[t] = fmaxf(sh[t], sh[t + st]); __syncthreads(); }
    float mx = sh[0];
    __syncthreads();
    float e = expf(v - mx);
    sh[t] = e;
    __syncthreads();
    for (int st = 256; st > 0; st >>= 1) { if (t < st) sh[t] += sh[t + st]; __syncthreads(); }
    float sum = sh[0];
    __syncthreads();
    g_pool[(b << 9) + t] = e / sum;
}
__global__ void cru_combine() {
    int i = blockIdx.x*256 + threadIdx.x;
    int t = i >> 8, c = i & 255;
    int b = t >> 16;
    float y1 = g_y1[i];
    float y2v;
    if (c < 192) y2v = g_y2[(size_t)t*192 + c];
    else {
        int nl = c - 192;
        y2v = bf2f(g_ulsh[(size_t)t*64 + nl]) + bf2f(g_ulsl[(size_t)t*64 + nl]);
    }
    g_ka[(size_t)t*256 + c] = g_pool[(b << 9) + c]*y1 + g_pool[(b << 9) + 256 + c]*y2v;
}

// ---------------- windowed attention ----------------
__global__ __launch_bounds__(64) void attn(const float* __restrict__ rel_pos) {
    int win = blockIdx.x, h = blockIdx.y, b = blockIdx.z;
    __shared__ __align__(16) float ksh[2048];
    __shared__ __align__(16) float vsh[2048];
    __shared__ float rp[225];
    int wy = win >> 5, wx = win & 31;
    int t0 = (b << 16) + (wy << 11) + (wx << 3);
    int tid = threadIdx.x;
    int hb = h << 5;
    for (int i = tid; i < 2048; i += 64) {
        int p = i >> 5, d = i & 31;
        int t = t0 + ((p >> 3) << 8) + (p & 7);
        ksh[i] = g_ka[(size_t)t*256 + hb + d];
        vsh[i] = g_v [(size_t)t*256 + hb + d];
    }
    for (int i = tid; i < 225; i += 64) rp[i] = rel_pos[h*225 + i];
    __syncthreads();
    int myt = t0 + ((tid >> 3) << 8) + (tid & 7);
    ull qp[16];
#pragma unroll
    for (int d = 0; d < 16; d++) {
        float2 qv = *(const float2*)&g_qa[(size_t)myt*256 + hb + 2*d];
        qp[d] = pack2(qv.x, qv.y);
    }
    int ph = tid >> 3, pw = tid & 7;
    bool lr = wy == 31, lc = wx == 31;
    ull zz = pack2(0.f, 0.f);
    float s[64];
#pragma unroll
    for (int qi = 0; qi < 64; qi++) {
        const ull* kp = (const ull*)&ksh[qi*32];
        ull dp = zz;
#pragma unroll
        for (int d = 0; d < 16; d++) ffma2(dp, qp[d], kp[d]);
        float dl, dh;
        unpack2(dp, dl, dh);
        int qh = qi >> 3, qw = qi & 7;
        float val = (dl + dh)*SCALE + rp[(ph - qh + 7)*15 + (pw - qw + 7)];
        if ((lr && ((ph < 4) != (qh < 4))) || (lc && ((pw < 4) != (qw < 4)))) val = -1e30f;
        s[qi] = val;
    }
    float mx = -1e30f;
#pragma unroll
    for (int qi = 0; qi < 64; qi++) mx = fmaxf(mx, s[qi]);
    float sum = 0.f;
#pragma unroll
    for (int qi = 0; qi < 64; qi++) { s[qi] = expf(s[qi] - mx); sum += s[qi]; }
    float inv = 1.0f / sum;
    ull accp[16];
#pragma unroll
    for (int d = 0; d < 16; d++) accp[d] = zz;
#pragma unroll
    for (int qi = 0; qi < 64; qi++) {
        ull wd = pack2(s[qi]*inv, s[qi]*inv);
        const ull* vp = (const ull*)&vsh[qi*32];
#pragma unroll
        for (int d = 0; d < 16; d++) ffma2(accp[d], wd, vp[d]);
    }
    float af[32];
#pragma unroll
    for (int d = 0; d < 16; d++) unpack2(accp[d], af[2*d], af[2*d+1]);
#pragma unroll
    for (int d0 = 0; d0 < 32; d0 += 8) {
        __nv_bfloat16 hv[8], lv[8];
#pragma unroll
        for (int e = 0; e < 8; e++) {
            hv[e] = __float2bfloat16(af[d0 + e]);
            lv[e] = __float2bfloat16(af[d0 + e] - bf2f(hv[e]));
        }
        *(uint4*)&g_atth[(size_t)myt*256 + hb + d0] = *(uint4*)hv;
        *(uint4*)&g_attl[(size_t)myt*256 + hb + d0] = *(uint4*)lv;
    }
}

// ---------------- final un-roll scatter to NCHW ----------------
__global__ __launch_bounds__(256) void unscatter(float* __restrict__ out) {
    __shared__ float s2[32][261];
    int bid = blockIdx.x;
    int b = bid >> 11, rem = bid & 2047;
    int hr = rem >> 3, w0 = (rem & 7) << 5;
    int tid = threadIdx.x;
    size_t tbase = (size_t)(b << 16) + (hr << 8) + w0;
    for (int i = 0; i < 8; i++) {
        int idx = (i << 8) + tid;
        int tw = idx >> 6, c4 = idx & 63;
        float4 v = *(const float4*)&g_qa[(tbase + tw)*256 + (c4 << 2)];
        s2[tw][(c4 << 2)]     = v.x;
        s2[tw][(c4 << 2) + 1] = v.y;
        s2[tw][(c4 << 2) + 2] = v.z;
        s2[tw][(c4 << 2) + 3] = v.w;
    }
    __syncthreads();
    int hs = ((hr + 4) & 255) << 8;
    for (int i = 0; i < 32; i++) {
        int idx = (i << 8) + tid;
        int c = idx >> 5, wp = idx & 31;
        out[(size_t)((b << 8) + c)*65536 + hs + ((w0 + wp + 4) & 255)] = s2[wp][c];
    }
}

// ---------------- launch ----------------
extern "C" void kernel_launch(void* const* d_in, const int* in_sizes, int n_in,
                              void* d_out, int out_size) {
    const float* x      = (const float*)d_in[0];
    const float* w_qkv  = (const float*)d_in[1];
    const float* b_qkv  = (const float*)d_in[2];
    const float* rel_pos= (const float*)d_in[3];
    const float* gn_w   = (const float*)d_in[4];
    const float* gn_b   = (const float*)d_in[5];
    const float* sq1    = (const float*)d_in[6];
    const float* sq2    = (const float*)d_in[7];
    const float* gwc    = (const float*)d_in[8];
    const float* gwc_b  = (const float*)d_in[9];
    const float* pwc1   = (const float*)d_in[10];
    const float* pwc2   = (const float*)d_in[11];
    const float* w_out  = (const float*)d_in[12];
    const float* b_out  = (const float*)d_in[13];
    float* out = (float*)d_out;

    __nv_bfloat16 *p_bqh, *p_bql, *p_bouth, *p_boutl, *p_bsqh, *p_bsql, *p_bp2h, *p_bp2l;
    __nv_bfloat16 *p_xh, *p_xl, *p_kh, *p_kl, *p_atth, *p_attl, *p_ulsh, *p_ulsl, *p_bconv2;
    cudaGetSymbolAddress((void**)&p_bqh,   g_bqh);
    cudaGetSymbolAddress((void**)&p_bql,   g_bql);
    cudaGetSymbolAddress((void**)&p_bouth, g_bouth);
    cudaGetSymbolAddress((void**)&p_boutl, g_boutl);
    cudaGetSymbolAddress((void**)&p_bsqh,  g_bsqh);
    cudaGetSymbolAddress((void**)&p_bsql,  g_bsql);
    cudaGetSymbolAddress((void**)&p_bp2h,  g_bp2h);
    cudaGetSymbolAddress((void**)&p_bp2l,  g_bp2l);
    cudaGetSymbolAddress((void**)&p_xh,    g_xh);
    cudaGetSymbolAddress((void**)&p_xl,    g_xl);
    cudaGetSymbolAddress((void**)&p_kh,    g_kh);
    cudaGetSymbolAddress((void**)&p_kl,    g_kl);
    cudaGetSymbolAddress((void**)&p_atth,  g_atth);
    cudaGetSymbolAddress((void**)&p_attl,  g_attl);
    cudaGetSymbolAddress((void**)&p_ulsh,  g_ulsh);
    cudaGetSymbolAddress((void**)&p_ulsl,  g_ulsl);
    cudaGetSymbolAddress((void**)&p_bconv2,g_bconv2);

    const int DSM = 98304;   // 2 stages x 48KB
    cudaFuncSetAttribute(hgemmA<EQKVt>, cudaFuncAttributeMaxDynamicSharedMemorySize, DSM);
    cudaFuncSetAttribute(hgemmA<EOutT>, cudaFuncAttributeMaxDynamicSharedMemorySize, DSM);
    cudaFuncSetAttribute(hgemmA<ESQ>,   cudaFuncAttributeMaxDynamicSharedMemorySize, DSM);
    cudaFuncSetAttribute(hgemmA<EY2h>,  cudaFuncAttributeMaxDynamicSharedMemorySize, DSM);

    zero_small<<<4, 256>>>();                                              // 0
    prep_bw<<<768, 256>>>(w_qkv, p_bqh, p_bql, 768*256);                   // 1
    xsplit<<<4096, 256>>>(x);                                              // 2
    hgemmA<EQKVt><<<dim3(6, 1024), 256, DSM>>>(p_xh, p_xl, 256,
                                               p_bqh, p_bql, 256, 8, EQKVt{b_qkv}); // 3 (profiled)

    gn_stats<<<256, 256>>>();
    sum_gnw<<<1, 256>>>(gn_w);
    sru_elem<<<65536, 256>>>(gn_w, gn_b);

    prep_bsq<<<128, 256>>>(sq1, sq2);
    hgemmA<ESQ><<<dim3(1, 1024), 256, DSM>>>(p_kh, p_kl, 256, p_bsqh, p_bsql, 256, 8, ESQ{});
    prep_bconv2<<<(2*128*1088 + 255)/256, 256>>>(gwc, pwc1);
    hgemmS<<<dim3(1, 1024, 2), 256>>>(AConv2{}, p_bconv2, gwc_b);
    prep_bp2<<<64, 256>>>(pwc2);
    hgemmA<EY2h><<<dim3(2, 1024), 256, DSM>>>(p_ulsh, p_ulsl, 64, p_bp2h, p_bp2l, 64, 2, EY2h{});

    pool_kernel<<<512, 256>>>();
    softmax512<<<2, 512>>>();
    cru_combine<<<131072, 256>>>();

    attn<<<dim3(1024, 8, 2), 64>>>(rel_pos);
    prep_bw<<<256, 256>>>(w_out, p_bouth, p_boutl, 256*256);
    hgemmA<EOutT><<<dim3(2, 1024), 256, DSM>>>(p_atth, p_attl, 256,
                                               p_bouth, p_boutl, 256, 8, EOutT{b_out});
    unscatter<<<4096, 256>>>(out);
}

// round 12
// speedup vs baseline: 1.1686x; 1.0482x over previous
#include <cuda_runtime.h>
#include <cuda_bf16.h>
#include <math.h>
#include <cstdint>

#define TTOT 131072
#define SCALE 0.17677669529663687f
#define GN_N 1048576.0f

__device__ __forceinline__ void mma16816(float* d, const uint32_t* a, const uint32_t* b) {
    asm volatile("mma.sync.aligned.m16n8k16.row.col.f32.bf16.bf16.f32 "
        "{%0,%1,%2,%3}, {%4,%5,%6,%7}, {%8,%9}, {%0,%1,%2,%3};"
        : "+f"(d[0]), "+f"(d[1]), "+f"(d[2]), "+f"(d[3])
        : "r"(a[0]), "r"(a[1]), "r"(a[2]), "r"(a[3]), "r"(b[0]), "r"(b[1]));
}
__device__ __forceinline__ void ldsm4(uint32_t& r0, uint32_t& r1, uint32_t& r2, uint32_t& r3,
                                      uint32_t addr) {
    asm volatile("ldmatrix.sync.aligned.m8n8.x4.shared.b16 {%0,%1,%2,%3}, [%4];"
                 : "=r"(r0), "=r"(r1), "=r"(r2), "=r"(r3) : "r"(addr));
}
__device__ __forceinline__ uint32_t smem_u32(const void* p) {
    uint32_t a;
    asm("{ .reg .u64 t; cvta.to.shared.u64 t, %1; cvt.u32.u64 %0, t; }" : "=r"(a) : "l"(p));
    return a;
}
__device__ __forceinline__ float bf2f(__nv_bfloat16 h) { return __bfloat162float(h); }

#define CP_A16(d, s) asm volatile("cp.async.cg.shared.global [%0], [%1], 16;" :: "r"(d), "l"(s) : "memory")
#define CP_COMMIT()  asm volatile("cp.async.commit_group;" ::: "memory")
#define CP_WAIT1()   asm volatile("cp.async.wait_group 1;" ::: "memory")

// ---------------- scratch ----------------
__device__ __nv_bfloat16 g_xh [(size_t)TTOT*256];
__device__ __nv_bfloat16 g_xl [(size_t)TTOT*256];
__device__ __nv_bfloat16 g_kh [(size_t)TTOT*256];   // squeeze input (k path)
__device__ __nv_bfloat16 g_kl [(size_t)TTOT*256];
__device__ __nv_bfloat16 g_qah[(size_t)TTOT*256];   // attention q (split)
__device__ __nv_bfloat16 g_qal[(size_t)TTOT*256];
__device__ __nv_bfloat16 g_kah[(size_t)TTOT*256];   // attention k (split)
__device__ __nv_bfloat16 g_kal[(size_t)TTOT*256];
__device__ __nv_bfloat16 g_vh [(size_t)TTOT*256];   // attention v (split)
__device__ __nv_bfloat16 g_vl [(size_t)TTOT*256];
__device__ __nv_bfloat16 g_atth[(size_t)TTOT*256];
__device__ __nv_bfloat16 g_attl[(size_t)TTOT*256];
__device__ __nv_bfloat16 g_uphi[(size_t)TTOT*64];
__device__ __nv_bfloat16 g_uplo[(size_t)TTOT*64];
__device__ __nv_bfloat16 g_ulsh[(size_t)TTOT*64];
__device__ __nv_bfloat16 g_ulsl[(size_t)TTOT*64];
__device__ float g_q  [(size_t)TTOT*256];
__device__ float g_qa [(size_t)TTOT*256];
__device__ float g_y1 [(size_t)TTOT*256];
__device__ float g_y2 [(size_t)TTOT*192];
__device__ __nv_bfloat16 g_bqh  [768*256];
__device__ __nv_bfloat16 g_bql  [768*256];
__device__ __nv_bfloat16 g_bouth[256*256];
__device__ __nv_bfloat16 g_boutl[256*256];
__device__ __nv_bfloat16 g_bsqh [128*256];
__device__ __nv_bfloat16 g_bsql [128*256];
__device__ __nv_bfloat16 g_bp2h [256*64];
__device__ __nv_bfloat16 g_bp2l [256*64];
__device__ __nv_bfloat16 g_bconv2[2*128*1088];
__device__ float g_gnstats[2*16*2];
__device__ float g_pool[2*512];
__device__ float g_misc[4];

// ---------------- small utilities ----------------
__global__ void zero_small() {
    int i = blockIdx.x*256 + threadIdx.x;
    if (i < 1024) g_pool[i] = 0.f;
    if (i < 64)   g_gnstats[i] = 0.f;
}
__global__ void sum_gnw(const float* __restrict__ gn_w) {
    __shared__ float sh[256];
    sh[threadIdx.x] = gn_w[threadIdx.x];
    __syncthreads();
    for (int st = 128; st > 0; st >>= 1) {
        if (threadIdx.x < st) sh[threadIdx.x] += sh[threadIdx.x + st];
        __syncthreads();
    }
    if (threadIdx.x == 0) g_misc[0] = sh[0];
}
__global__ void prep_bw(const float* __restrict__ w,
                        __nv_bfloat16* __restrict__ dh, __nv_bfloat16* __restrict__ dl, int total) {
    int i = blockIdx.x*256 + threadIdx.x;
    if (i >= total) return;
    float v = w[i];
    __nv_bfloat16 h = __float2bfloat16(v);
    dh[i] = h;
    dl[i] = __float2bfloat16(v - bf2f(h));
}
__global__ void prep_bsq(const float* __restrict__ sq1, const float* __restrict__ sq2) {
    int i = blockIdx.x*256 + threadIdx.x;
    if (i >= 128*256) return;
    int n = i >> 8, k = i & 255;
    float w = 0.f;
    if (n < 64)  { if (k < 128)  w = sq1[n*128 + k]; }
    else         { if (k >= 128) w = sq2[(n-64)*128 + (k-128)]; }
    __nv_bfloat16 h = __float2bfloat16(w);
    g_bsqh[i] = h;
    g_bsql[i] = __float2bfloat16(w - bf2f(h));
}
__global__ void prep_bp2(const float* __restrict__ pwc2) {
    int i = blockIdx.x*256 + threadIdx.x;
    if (i >= 256*64) return;
    int n = i >> 6, k = i & 63;
    float w = (n < 192) ? pwc2[n*64 + k] : 0.f;
    __nv_bfloat16 h = __float2bfloat16(w);
    g_bp2h[i] = h;
    g_bp2l[i] = __float2bfloat16(w - bf2f(h));
}
__global__ void prep_bconv2(const float* __restrict__ gwc, const float* __restrict__ pwc1) {
    int i = blockIdx.x*256 + threadIdx.x;
    if (i >= 2*128*1088) return;
    int z = i / (128*1088), r = i % (128*1088);
    int n = r / 1088, kp = r % 1088;
    float w = 0.f; int seg = 0;
    if (kp < 1056) {
        seg = kp / 352;
        int kk = kp - seg*352;
        int c = z*128 + n;
        if (kk < 288) { int tap = kk >> 5, kl = kk & 31; w = gwc[c*288 + kl*9 + tap]; }
        else          w = pwc1[c*64 + kk - 288];
    }
    __nv_bfloat16 h = __float2bfloat16(w);
    g_bconv2[i] = (seg == 2) ? __float2bfloat16(w - bf2f(h)) : h;
}

// ---------------- roll + split x ----------------
__global__ __launch_bounds__(256) void xsplit(const float* __restrict__ x) {
    __shared__ float s[256][33];
    int bid = blockIdx.x;
    int b = bid >> 11, rem = bid & 2047;
    int hr = rem >> 3, w0 = (rem & 7) << 5;
    int tid = threadIdx.x, wid = tid >> 5, lane = tid & 31;
    int hs = ((hr + 4) & 255) << 8;
    for (int i = 0; i < 32; i++) {
        int idx = (i << 8) + tid;
        int c = idx >> 5, wp = idx & 31;
        s[c][wp] = x[(size_t)((b << 8) + c)*65536 + hs + ((w0 + wp + 4) & 255)];
    }
    __syncthreads();
    size_t t = (size_t)(b << 16) + (hr << 8) + w0 + lane;
    int c0 = wid << 5;
    for (int j = 0; j < 32; j += 8) {
        __nv_bfloat16 hv[8], lv[8];
#pragma unroll
        for (int e = 0; e < 8; e++) {
            float a = s[c0 + j + e][lane];
            hv[e] = __float2bfloat16(a);
            lv[e] = __float2bfloat16(a - bf2f(hv[e]));
        }
        *(uint4*)&g_xh[t*256 + c0 + j] = *(uint4*)hv;
        *(uint4*)&g_xl[t*256 + c0 + j] = *(uint4*)lv;
    }
}

// ---------------- epilogues ----------------
struct EQKVt {
    const float* bias;
    __device__ void st2(int m, int n, int z, float v0, float v1) const {
        v0 += bias[n]; v1 += bias[n+1];
        if (n < 256) {
            *(float2*)&g_q[(size_t)m*256 + n] = make_float2(v0, v1);
        } else if (n < 512) {
            int c = n - 256;
            __nv_bfloat16 h0 = __float2bfloat16(v0), h1 = __float2bfloat16(v1);
            *(__nv_bfloat162*)&g_kh[(size_t)m*256 + c] = __halves2bfloat162(h0, h1);
            *(__nv_bfloat162*)&g_kl[(size_t)m*256 + c] = __halves2bfloat162(
                __float2bfloat16(v0 - bf2f(h0)), __float2bfloat16(v1 - bf2f(h1)));
        } else {
            int c = n - 512;
            __nv_bfloat16 h0 = __float2bfloat16(v0), h1 = __float2bfloat16(v1);
            *(__nv_bfloat162*)&g_vh[(size_t)m*256 + c] = __halves2bfloat162(h0, h1);
            *(__nv_bfloat162*)&g_vl[(size_t)m*256 + c] = __halves2bfloat162(
                __float2bfloat16(v0 - bf2f(h0)), __float2bfloat16(v1 - bf2f(h1)));
        }
    }
};
struct EOutT {
    const float* bias;
    __device__ void st2(int m, int n, int z, float v0, float v1) const {
        *(float2*)&g_qa[(size_t)m*256 + n] = make_float2(v0 + bias[n], v1 + bias[n+1]);
    }
};
struct ESQ {
    __device__ void st2(int m, int n, int z, float v0, float v1) const {
        __nv_bfloat16 h0 = __float2bfloat16(v0), h1 = __float2bfloat16(v1);
        __nv_bfloat16 l0 = __float2bfloat16(v0 - bf2f(h0)), l1 = __float2bfloat16(v1 - bf2f(h1));
        if (n < 64) {
            *(__nv_bfloat162*)&g_uphi[(size_t)m*64 + n] = __halves2bfloat162(h0, h1);
            *(__nv_bfloat162*)&g_uplo[(size_t)m*64 + n] = __halves2bfloat162(l0, l1);
        } else {
            int nl = n - 64;
            *(__nv_bfloat162*)&g_ulsh[(size_t)m*64 + nl] = __halves2bfloat162(h0, h1);
            *(__nv_bfloat162*)&g_ulsl[(size_t)m*64 + nl] = __halves2bfloat162(l0, l1);
        }
    }
};
struct EY2h {
    __device__ void st2(int m, int n, int z, float v0, float v1) const {
        if (n < 192) *(float2*)&g_y2[(size_t)m*192 + n] = make_float2(v0, v1);
    }
};

// ---------------- dedup split HMMA GEMM (round-11, unchanged) ----------------
template<class EF>
__global__ __launch_bounds__(256, 2) void hgemmA(const __nv_bfloat16* __restrict__ Ah_,
                                                 const __nv_bfloat16* __restrict__ Al_, int lda,
                                                 const __nv_bfloat16* __restrict__ Bh_,
                                                 const __nv_bfloat16* __restrict__ Bl_, int ldb,
                                                 int nk, EF ef) {
    extern __shared__ __nv_bfloat16 sm[];
    int tid = threadIdx.x, lane = tid & 31, wid = tid >> 5;
    int m0 = blockIdx.y << 7, n0 = blockIdx.x << 7;
    uint32_t sbase = smem_u32(sm);
    int wm = (wid & 3) << 5, wn = (wid >> 2) << 6;
    int gid = lane >> 2, tig = lane & 3;
    int lr = lane & 7, lh = (lane >> 3) & 1, lk = lane >> 4;
    uint32_t offA[2];
#pragma unroll
    for (int mf = 0; mf < 2; mf++)
        offA[mf] = (uint32_t)(((wm + (mf << 4) + lr + lh*8)*24 + lk*8) << 1);
    int lq = lane >> 3;
    uint32_t offB[4];
#pragma unroll
    for (int p = 0; p < 4; p++)
        offB[p] = (uint32_t)(((wn + (p << 4) + lr + (lq >> 1)*8)*24 + (lq & 1)*8) << 1);

    float acc[2][8][4];
#pragma unroll
    for (int mf = 0; mf < 2; mf++)
#pragma unroll
        for (int nf = 0; nf < 8; nf++)
#pragma unroll
            for (int e = 0; e < 4; e++) acc[mf][nf][e] = 0.f;

    auto prefetch = [&](int ch, int s) {
        int k0 = ch << 5;
#pragma unroll
        for (int i = 0; i < 2; i++) {
            int idx = (i << 8) + tid;
            int r = idx >> 2, c4 = idx & 3;
            int g = c4 >> 1, ke = c4 & 1;
            uint32_t da = sbase + (uint32_t)((s*24576 + (g*128 + r)*24 + ke*8) << 1);
            size_t asrc = (size_t)(m0 + r)*lda + k0 + (c4 << 3);
            size_t bsrc = (size_t)(n0 + r)*ldb + k0 + (c4 << 3);
            CP_A16(da,          Ah_ + asrc);
            CP_A16(da + 12288,  Al_ + asrc);
            CP_A16(da + 24576,  Bh_ + bsrc);
            CP_A16(da + 36864,  Bl_ + bsrc);
        }
        CP_COMMIT();
    };
    prefetch(0, 0);
    for (int ch = 0; ch < nk; ch++) {
        if (ch + 1 < nk) prefetch(ch + 1, (ch + 1) & 1);
        else CP_COMMIT();
        CP_WAIT1();
        __syncthreads();
        uint32_t stb = sbase + (uint32_t)((ch & 1)*49152);
#pragma unroll
        for (int g = 0; g < 2; g++) {
            uint32_t gb = stb + (uint32_t)(g*6144);
            uint32_t a[2][4], b[8][2];
            ldsm4(b[0][0], b[0][1], b[1][0], b[1][1], gb + 24576 + offB[0]);
            ldsm4(b[2][0], b[2][1], b[3][0], b[3][1], gb + 24576 + offB[1]);
            ldsm4(b[4][0], b[4][1], b[5][0], b[5][1], gb + 24576 + offB[2]);
            ldsm4(b[6][0], b[6][1], b[7][0], b[7][1], gb + 24576 + offB[3]);
            ldsm4(a[0][0], a[0][1], a[0][2], a[0][3], gb + offA[0]);
            ldsm4(a[1][0], a[1][1], a[1][2], a[1][3], gb + offA[1]);
#pragma unroll
            for (int mf = 0; mf < 2; mf++)
#pragma unroll
                for (int nf = 0; nf < 8; nf++)
                    mma16816(acc[mf][nf], a[mf], b[nf]);
            ldsm4(a[0][0], a[0][1], a[0][2], a[0][3], gb + 12288 + offA[0]);
            ldsm4(a[1][0], a[1][1], a[1][2], a[1][3], gb + 12288 + offA[1]);
#pragma unroll
            for (int mf = 0; mf < 2; mf++)
#pragma unroll
                for (int nf = 0; nf < 8; nf++)
                    mma16816(acc[mf][nf], a[mf], b[nf]);
            ldsm4(b[0][0], b[0][1], b[1][0], b[1][1], gb + 36864 + offB[0]);
            ldsm4(b[2][0], b[2][1], b[3][0], b[3][1], gb + 36864 + offB[1]);
            ldsm4(b[4][0], b[4][1], b[5][0], b[5][1], gb + 36864 + offB[2]);
            ldsm4(b[6][0], b[6][1], b[7][0], b[7][1], gb + 36864 + offB[3]);
            ldsm4(a[0][0], a[0][1], a[0][2], a[0][3], gb + offA[0]);
            ldsm4(a[1][0], a[1][1], a[1][2], a[1][3], gb + offA[1]);
#pragma unroll
            for (int mf = 0; mf < 2; mf++)
#pragma unroll
                for (int nf = 0; nf < 8; nf++)
                    mma16816(acc[mf][nf], a[mf], b[nf]);
        }
        __syncthreads();
    }
#pragma unroll
    for (int mf = 0; mf < 2; mf++) {
        int row0 = m0 + wm + (mf << 4) + gid;
#pragma unroll
        for (int nf = 0; nf < 8; nf++) {
            int col = n0 + wn + (nf << 3) + (tig << 1);
            ef.st2(row0,     col, 0, acc[mf][nf][0], acc[mf][nf][1]);
            ef.st2(row0 + 8, col, 0, acc[mf][nf][2], acc[mf][nf][3]);
        }
    }
}

// ---------------- sync gather HMMA GEMM (conv, unchanged) ----------------
struct AConv2 {
    __device__ uint4 ld8(int m, int k8, int z) const {
        uint4 zr = make_uint4(0, 0, 0, 0);
        if (k8 >= 1056) return zr;
        int seg = (k8 >= 704) ? 2 : ((k8 >= 352) ? 1 : 0);
        int kk = k8 - seg*352;
        const __nv_bfloat16* src = (seg == 1) ? g_uplo : g_uphi;
        if (kk >= 288)
            return *(const uint4*)(src + (size_t)m*64 + (kk - 288));
        int tap = kk >> 5, ki = (z << 5) + (kk & 31);
        int dy = tap/3 - 1, dx = tap - (tap/3)*3 - 1;
        int b = m >> 16, pixi = m & 65535;
        int hr = (pixi >> 8) + dy, wr = (pixi & 255) + dx;
        if ((unsigned)hr > 255u || (unsigned)wr > 255u) return zr;
        return *(const uint4*)(src + (size_t)((b << 16) + (hr << 8) + wr)*64 + ki);
    }
};
__global__ __launch_bounds__(256, 2) void hgemmS(AConv2 af, const __nv_bfloat16* __restrict__ B,
                                                 const float* __restrict__ bias) {
    __shared__ __align__(16) __nv_bfloat16 As[4][128][24];
    __shared__ __align__(16) __nv_bfloat16 Bs[4][128][24];
    int tid = threadIdx.x, lane = tid & 31, wid = tid >> 5;
    int z = blockIdx.z;
    int m0 = blockIdx.y << 7;
    const __nv_bfloat16* Bz = B + (size_t)z*128*1088;
    int wm = (wid & 3) << 5, wn = (wid >> 2) << 6;
    int gid = lane >> 2, tig = lane & 3;
    uint32_t sA = smem_u32(&As[0][0][0]), sB = smem_u32(&Bs[0][0][0]);
    int lr = lane & 7, lh = (lane >> 3) & 1, lk = lane >> 4;
    uint32_t offA[2];
#pragma unroll
    for (int mf = 0; mf < 2; mf++)
        offA[mf] = (uint32_t)(((wm + (mf << 4) + lr + lh*8)*24 + lk*8) << 1);
    int lq = lane >> 3;
    uint32_t offB[4];
#pragma unroll
    for (int p = 0; p < 4; p++)
        offB[p] = (uint32_t)(((wn + (p << 4) + lr + (lq >> 1)*8)*24 + (lq & 1)*8) << 1);

    float acc[2][8][4];
#pragma unroll
    for (int mf = 0; mf < 2; mf++)
#pragma unroll
        for (int nf = 0; nf < 8; nf++)
#pragma unroll
            for (int e = 0; e < 4; e++) acc[mf][nf][e] = 0.f;

    for (int ch = 0; ch < 17; ch++) {
        int k0 = ch << 6;
#pragma unroll
        for (int i = 0; i < 4; i++) {
            int idx = (i << 8) + tid;
            int r = idx >> 3, c8 = idx & 7;
            *(uint4*)&As[c8 >> 1][r][(c8 & 1) << 3] = af.ld8(m0 + r, k0 + (c8 << 3), z);
            *(uint4*)&Bs[c8 >> 1][r][(c8 & 1) << 3] = *(const uint4*)(Bz + (size_t)r*1088 + k0 + (c8 << 3));
        }
        __syncthreads();
#pragma unroll
        for (int g = 0; g < 4; g++) {
            uint32_t abase = sA + (uint32_t)(g*6144);
            uint32_t bbase = sB + (uint32_t)(g*6144);
            uint32_t a[2][4], b[8][2];
            ldsm4(a[0][0], a[0][1], a[0][2], a[0][3], abase + offA[0]);
            ldsm4(a[1][0], a[1][1], a[1][2], a[1][3], abase + offA[1]);
            ldsm4(b[0][0], b[0][1], b[1][0], b[1][1], bbase + offB[0]);
            ldsm4(b[2][0], b[2][1], b[3][0], b[3][1], bbase + offB[1]);
            ldsm4(b[4][0], b[4][1], b[5][0], b[5][1], bbase + offB[2]);
            ldsm4(b[6][0], b[6][1], b[7][0], b[7][1], bbase + offB[3]);
#pragma unroll
            for (int mf = 0; mf < 2; mf++)
#pragma unroll
                for (int nf = 0; nf < 8; nf++)
                    mma16816(acc[mf][nf], a[mf], b[nf]);
        }
        __syncthreads();
    }
#pragma unroll
    for (int mf = 0; mf < 2; mf++) {
        int row0 = m0 + wm + (mf << 4) + gid;
#pragma unroll
        for (int nf = 0; nf < 8; nf++) {
            int col = wn + (nf << 3) + (tig << 1);
            int c = (z << 7) + col;
            *(float2*)&g_y1[(size_t)row0*256 + c] =
                make_float2(acc[mf][nf][0] + bias[c], acc[mf][nf][1] + bias[c+1]);
            *(float2*)&g_y1[(size_t)(row0 + 8)*256 + c] =
                make_float2(acc[mf][nf][2] + bias[c], acc[mf][nf][3] + bias[c+1]);
        }
    }
}

// ---------------- GN stats / SRU / CRU glue ----------------
__global__ void gn_stats() {
    int t0 = blockIdx.x * 512;
    int c = threadIdx.x;
    const float* p = g_q + (size_t)t0*256 + c;
    float s = 0.f, s2 = 0.f;
#pragma unroll 4
    for (int i = 0; i < 512; i++) { float v = p[(size_t)i*256]; s += v; s2 += v*v; }
#pragma unroll
    for (int off = 8; off > 0; off >>= 1) {
        s  += __shfl_down_sync(0xffffffff, s,  off, 16);
        s2 += __shfl_down_sync(0xffffffff, s2, off, 16);
    }
    if ((c & 15) == 0) {
        int b = t0 >> 16, g = c >> 4;
        atomicAdd(&g_gnstats[((b << 4) + g)*2],     s);
        atomicAdd(&g_gnstats[((b << 4) + g)*2 + 1], s2);
    }
}
__global__ void sru_elem(const float* __restrict__ gn_w, const float* __restrict__ gn_b) {
    int i = blockIdx.x*256 + threadIdx.x;
    int t = i >> 7, cp = i & 127;
    int b = t >> 16;
    int c1 = cp, c2 = cp + 128;
    float wsum = g_misc[0];
    int g1 = c1 >> 4, g2 = c2 >> 4;
    float m1 = g_gnstats[((b<<4)+g1)*2] / GN_N;
    float v1 = g_gnstats[((b<<4)+g1)*2+1] / GN_N - m1*m1;
    float m2 = g_gnstats[((b<<4)+g2)*2] / GN_N;
    float v2 = g_gnstats[((b<<4)+g2)*2+1] / GN_N - m2*m2;
    float w1c = gn_w[c1], w2c = gn_w[c2];
    float A1 = rsqrtf(v1 + 1e-5f)*w1c, B1 = gn_b[c1] - m1*rsqrtf(v1 + 1e-5f)*w1c;
    float A2 = rsqrtf(v2 + 1e-5f)*w2c, B2 = gn_b[c2] - m2*rsqrtf(v2 + 1e-5f)*w2c;
    float x1 = g_q[(size_t)t*256 + c1], x2 = g_q[(size_t)t*256 + c2];
    float rw1 = 1.0f/(1.0f + expf(-(x1*A1 + B1)*(w1c/wsum)));
    float rw2 = 1.0f/(1.0f + expf(-(x2*A2 + B2)*(w2c/wsum)));
    float w11 = rw1 > 0.5f ? 1.0f : rw1, w21 = rw1 > 0.5f ? 0.0f : rw1;
    float w12 = rw2 > 0.5f ? 1.0f : rw2, w22 = rw2 > 0.5f ? 0.0f : rw2;
    float o1 = w11*x1 + w22*x2;
    float o2 = w12*x2 + w21*x1;
    __nv_bfloat16 h1 = __float2bfloat16(o1), h2 = __float2bfloat16(o2);
    g_qah[(size_t)t*256 + c1] = h1;
    g_qal[(size_t)t*256 + c1] = __float2bfloat16(o1 - bf2f(h1));
    g_qah[(size_t)t*256 + c2] = h2;
    g_qal[(size_t)t*256 + c2] = __float2bfloat16(o2 - bf2f(h2));
}
__global__ void pool_kernel() {
    int t0 = blockIdx.x * 256;
    int b = t0 >> 16;
    int tid = threadIdx.x;
    float a1 = 0.f, a2 = 0.f, a3 = 0.f;
    for (int t = t0; t < t0 + 256; t++) {
        a1 += g_y1[(size_t)t*256 + tid];
        if (tid < 192) a2 += g_y2[(size_t)t*192 + tid];
        if (tid < 64)  a3 += bf2f(g_ulsh[(size_t)t*64 + tid]) + bf2f(g_ulsl[(size_t)t*64 + tid]);
    }
    atomicAdd(&g_pool[(b << 9) + tid], a1);
    if (tid < 192) atomicAdd(&g_pool[(b << 9) + 256 + tid], a2);
    if (tid < 64)  atomicAdd(&g_pool[(b << 9) + 448 + tid], a3);
}
__global__ void softmax512() {
    int b = blockIdx.x, t = threadIdx.x;
    __shared__ float sh[512];
    float v = g_pool[(b << 9) + t] * (1.0f/65536.0f);
    sh[t] = v;
    __syncthreads();
    for (int st = 256; st > 0; st >>= 1) { if (t < st) sh[t] = fmaxf(sh[t], sh[t + st]); __syncthreads(); }
    float mx = sh[0];
    __syncthreads();
    float e = expf(v - mx);
    sh[t] = e;
    __syncthreads();
    for (int st = 256; st > 0; st >>= 1) { if (t < st) sh[t] += sh[t + st]; __syncthreads(); }
    float sum = sh[0];
    __syncthreads();
    g_pool[(b << 9) + t] = e / sum;
}
__global__ void cru_combine() {
    int i = blockIdx.x*256 + threadIdx.x;
    int t = i >> 8, c = i & 255;
    int b = t >> 16;
    float y1 = g_y1[i];
    float y2v;
    if (c < 192) y2v = g_y2[(size_t)t*192 + c];
    else {
        int nl = c - 192;
        y2v = bf2f(g_ulsh[(size_t)t*64 + nl]) + bf2f(g_ulsl[(size_t)t*64 + nl]);
    }
    float o = g_pool[(b << 9) + c]*y1 + g_pool[(b << 9) + 256 + c]*y2v;
    __nv_bfloat16 h = __float2bfloat16(o);
    g_kah[(size_t)t*256 + c] = h;
    g_kal[(size_t)t*256 + c] = __float2bfloat16(o - bf2f(h));
}

// ---------------- HMMA windowed attention ----------------
// CTA = 128 thr (4 warps = 4 heads) per (win, headgroup, batch).
// smem: per head tile = [Kh | Kl | Vth | Vtl], each 3072 elems (24-stride layout);
//       4 heads = 49152 elems (96KB); then rel_pos 4*225 floats.
__global__ __launch_bounds__(128) void attn_mma(const float* __restrict__ rel_pos) {
    extern __shared__ __nv_bfloat16 smb[];
    float* rps = (float*)(smb + 49152);
    int tid = threadIdx.x, lane = tid & 31, wid = tid >> 5;
    int win = blockIdx.x, hg = blockIdx.y, b = blockIdx.z;
    int wy = win >> 5, wx = win & 31;
    int t0 = (b << 16) + (wy << 11) + (wx << 3);
    // stage K hi/lo
    for (int i = 0; i < 8; i++) {
        int idx = (i << 7) + tid;            // 0..1023 (uint4 units)
        int hh = idx >> 8, r = idx & 255;
        int tok = r >> 2, c8 = (r & 3) << 3;
        int token = t0 + ((tok >> 3) << 8) + (tok & 7);
        size_t src = (size_t)token*256 + (((hg << 2) + hh) << 5) + c8;
        int dst = hh*12288 + ((c8 >> 4)*64 + tok)*24 + (c8 & 15);
        *(uint4*)&smb[dst]        = *(const uint4*)&g_kah[src];
        *(uint4*)&smb[dst + 3072] = *(const uint4*)&g_kal[src];
    }
    // stage V transposed (rows=channels, k=tokens)
    for (int i = 0; i < 32; i++) {
        int idx = (i << 7) + tid;            // 0..4095 (bf16x2 units)
        int hh = idx >> 10, r = idx & 1023;
        int tok = r >> 4, dp = (r & 15) << 1;
        int token = t0 + ((tok >> 3) << 8) + (tok & 7);
        size_t src = (size_t)token*256 + (((hg << 2) + hh) << 5) + dp;
        __nv_bfloat162 vh = *(const __nv_bfloat162*)&g_vh[src];
        __nv_bfloat162 vl = *(const __nv_bfloat162*)&g_vl[src];
        int base = hh*12288 + 6144 + (tok >> 4)*768 + (tok & 15);
        smb[base + dp*24]            = vh.x;
        smb[base + (dp+1)*24]        = vh.y;
        smb[base + 3072 + dp*24]     = vl.x;
        smb[base + 3072 + (dp+1)*24] = vl.y;
    }
    for (int i = tid; i < 900; i += 128) {
        int hh = i / 225, r = i - hh*225;
        rps[i] = rel_pos[(((hg << 2) + hh))*225 + r];
    }
    __syncthreads();

    int hh = wid;
    uint32_t tb = smem_u32(smb) + (uint32_t)(hh*24576);
    uint32_t khb = tb, klb = tb + 6144, vhb = tb + 12288, vlb = tb + 18432;
    const float* rp = rps + hh*225;
    int gid = lane >> 2, tig = lane & 3;
    int lr = lane & 7, lq = lane >> 3;
    uint32_t offK[4], offV[2];
#pragma unroll
    for (int p = 0; p < 4; p++)
        offK[p] = (uint32_t)((((p << 4) + lr + (lq >> 1)*8)*24 + (lq & 1)*8) << 1);
#pragma unroll
    for (int p = 0; p < 2; p++)
        offV[p] = (uint32_t)((((p << 4) + lr + (lq >> 1)*8)*24 + (lq & 1)*8) << 1);
    bool lrm = wy == 31, lcm = wx == 31;
    int hbc = ((hg << 2) + hh) << 5;

    for (int half = 0; half < 2; half++) {
        int rbase = half << 5;
        uint32_t qh[2][2][4], ql[2][2][4];
#pragma unroll
        for (int mt = 0; mt < 2; mt++) {
            int r0 = rbase + (mt << 4) + gid;
            int tok0 = t0 + ((r0 >> 3) << 8) + (r0 & 7);
            int r1 = r0 + 8;
            int tok1 = t0 + ((r1 >> 3) << 8) + (r1 & 7);
#pragma unroll
            for (int kf = 0; kf < 2; kf++) {
                int kc = hbc + (kf << 4) + (tig << 1);
                qh[mt][kf][0] = *(const uint32_t*)&g_qah[(size_t)tok0*256 + kc];
                qh[mt][kf][1] = *(const uint32_t*)&g_qah[(size_t)tok1*256 + kc];
                qh[mt][kf][2] = *(const uint32_t*)&g_qah[(size_t)tok0*256 + kc + 8];
                qh[mt][kf][3] = *(const uint32_t*)&g_qah[(size_t)tok1*256 + kc + 8];
                ql[mt][kf][0] = *(const uint32_t*)&g_qal[(size_t)tok0*256 + kc];
                ql[mt][kf][1] = *(const uint32_t*)&g_qal[(size_t)tok1*256 + kc];
                ql[mt][kf][2] = *(const uint32_t*)&g_qal[(size_t)tok0*256 + kc + 8];
                ql[mt][kf][3] = *(const uint32_t*)&g_qal[(size_t)tok1*256 + kc + 8];
            }
        }
        float sacc[2][8][4];
#pragma unroll
        for (int mt = 0; mt < 2; mt++)
#pragma unroll
            for (int nt = 0; nt < 8; nt++)
#pragma unroll
                for (int e = 0; e < 4; e++) sacc[mt][nt][e] = 0.f;
#pragma unroll
        for (int kg = 0; kg < 2; kg++) {
            uint32_t bk[8][2];
            uint32_t kgb = khb + (uint32_t)(kg*3072);
            ldsm4(bk[0][0], bk[0][1], bk[1][0], bk[1][1], kgb + offK[0]);
            ldsm4(bk[2][0], bk[2][1], bk[3][0], bk[3][1], kgb + offK[1]);
            ldsm4(bk[4][0], bk[4][1], bk[5][0], bk[5][1], kgb + offK[2]);
            ldsm4(bk[6][0], bk[6][1], bk[7][0], bk[7][1], kgb + offK[3]);
#pragma unroll
            for (int mt = 0; mt < 2; mt++)
#pragma unroll
                for (int nt = 0; nt < 8; nt++) {
                    mma16816(sacc[mt][nt], qh[mt][kg], bk[nt]);
                    mma16816(sacc[mt][nt], ql[mt][kg], bk[nt]);
                }
            uint32_t lgb = klb + (uint32_t)(kg*3072);
            ldsm4(bk[0][0], bk[0][1], bk[1][0], bk[1][1], lgb + offK[0]);
            ldsm4(bk[2][0], bk[2][1], bk[3][0], bk[3][1], lgb + offK[1]);
            ldsm4(bk[4][0], bk[4][1], bk[5][0], bk[5][1], lgb + offK[2]);
            ldsm4(bk[6][0], bk[6][1], bk[7][0], bk[7][1], lgb + offK[3]);
#pragma unroll
            for (int mt = 0; mt < 2; mt++)
#pragma unroll
                for (int nt = 0; nt < 8; nt++)
                    mma16816(sacc[mt][nt], qh[mt][kg], bk[nt]);
        }
        // rel_pos + mask + softmax (rows: (mt, rr))
#pragma unroll
        for (int mt = 0; mt < 2; mt++)
#pragma unroll
            for (int rr = 0; rr < 2; rr++) {
                int row = rbase + (mt << 4) + gid + (rr << 3);
                int ph = row >> 3, pw = row & 7;
                float vv[16];
                float mx = -1e30f;
#pragma unroll
                for (int nt = 0; nt < 8; nt++)
#pragma unroll
                    for (int j = 0; j < 2; j++) {
                        int col = (nt << 3) + (tig << 1) + j;
                        int qy = col >> 3, qw = col & 7;
                        float v = sacc[mt][nt][rr*2 + j]*SCALE + rp[(ph - qy + 7)*15 + (pw - qw + 7)];
                        if ((lrm && ((ph < 4) != (qy < 4))) || (lcm && ((pw < 4) != (qw < 4)))) v = -1e30f;
                        vv[nt*2 + j] = v;
                        mx = fmaxf(mx, v);
                    }
                mx = fmaxf(mx, __shfl_xor_sync(0xffffffff, mx, 1));
                mx = fmaxf(mx, __shfl_xor_sync(0xffffffff, mx, 2));
                float s = 0.f;
#pragma unroll
                for (int e = 0; e < 16; e++) { vv[e] = expf(vv[e] - mx); s += vv[e]; }
                s += __shfl_xor_sync(0xffffffff, s, 1);
                s += __shfl_xor_sync(0xffffffff, s, 2);
                float inv = 1.0f / s;
#pragma unroll
                for (int nt = 0; nt < 8; nt++)
#pragma unroll
                    for (int j = 0; j < 2; j++)
                        sacc[mt][nt][rr*2 + j] = vv[nt*2 + j]*inv;
            }
        // PV: 3-term split, register P->A reuse
        float oacc[2][4][4];
#pragma unroll
        for (int mt = 0; mt < 2; mt++)
#pragma unroll
            for (int nt = 0; nt < 4; nt++)
#pragma unroll
                for (int e = 0; e < 4; e++) oacc[mt][nt][e] = 0.f;
#pragma unroll
        for (int kf = 0; kf < 4; kf++) {
            uint32_t pfh[2][4], pfl[2][4];
#pragma unroll
            for (int mt = 0; mt < 2; mt++) {
#pragma unroll
                for (int e = 0; e < 4; e++) {
                    int nt = 2*kf + (e >> 1);
                    float p0 = sacc[mt][nt][(e & 1)*2];
                    float p1 = sacc[mt][nt][(e & 1)*2 + 1];
                    __nv_bfloat162 h2 = __floats2bfloat162_rn(p0, p1);
                    pfh[mt][e] = *(uint32_t*)&h2;
                    __nv_bfloat162 l2 = __floats2bfloat162_rn(p0 - bf2f(h2.x), p1 - bf2f(h2.y));
                    pfl[mt][e] = *(uint32_t*)&l2;
                }
            }
            uint32_t bv[4][2];
            uint32_t vgb = vhb + (uint32_t)(kf*1536);
            ldsm4(bv[0][0], bv[0][1], bv[1][0], bv[1][1], vgb + offV[0]);
            ldsm4(bv[2][0], bv[2][1], bv[3][0], bv[3][1], vgb + offV[1]);
#pragma unroll
            for (int mt = 0; mt < 2; mt++)
#pragma unroll
                for (int nt = 0; nt < 4; nt++) {
                    mma16816(oacc[mt][nt], pfh[mt], bv[nt]);
                    mma16816(oacc[mt][nt], pfl[mt], bv[nt]);
                }
            uint32_t lgb = vlb + (uint32_t)(kf*1536);
            ldsm4(bv[0][0], bv[0][1], bv[1][0], bv[1][1], lgb + offV[0]);
            ldsm4(bv[2][0], bv[2][1], bv[3][0], bv[3][1], lgb + offV[1]);
#pragma unroll
            for (int mt = 0; mt < 2; mt++)
#pragma unroll
                for (int nt = 0; nt < 4; nt++)
                    mma16816(oacc[mt][nt], pfh[mt], bv[nt]);
        }
        // store O split
#pragma unroll
        for (int mt = 0; mt < 2; mt++) {
            int r0 = rbase + (mt << 4) + gid;
            int tok0 = t0 + ((r0 >> 3) << 8) + (r0 & 7);
            int r1 = r0 + 8;
            int tok1 = t0 + ((r1 >> 3) << 8) + (r1 & 7);
#pragma unroll
            for (int nt = 0; nt < 4; nt++) {
                int c = hbc + (nt << 3) + (tig << 1);
                float a0 = oacc[mt][nt][0], a1 = oacc[mt][nt][1];
                float a2 = oacc[mt][nt][2], a3 = oacc[mt][nt][3];
                __nv_bfloat162 h0 = __floats2bfloat162_rn(a0, a1);
                __nv_bfloat162 h1 = __floats2bfloat162_rn(a2, a3);
                *(__nv_bfloat162*)&g_atth[(size_t)tok0*256 + c] = h0;
                *(__nv_bfloat162*)&g_atth[(size_t)tok1*256 + c] = h1;
                *(__nv_bfloat162*)&g_attl[(size_t)tok0*256 + c] =
                    __floats2bfloat162_rn(a0 - bf2f(h0.x), a1 - bf2f(h0.y));
                *(__nv_bfloat162*)&g_attl[(size_t)tok1*256 + c] =
                    __floats2bfloat162_rn(a2 - bf2f(h1.x), a3 - bf2f(h1.y));
            }
        }
    }
}

// ---------------- final un-roll scatter to NCHW ----------------
__global__ __launch_bounds__(256) void unscatter(float* __restrict__ out) {
    __shared__ float s2[32][261];
    int bid = blockIdx.x;
    int b = bid >> 11, rem = bid & 2047;
    int hr = rem >> 3, w0 = (rem & 7) << 5;
    int tid = threadIdx.x;
    size_t tbase = (size_t)(b << 16) + (hr << 8) + w0;
    for (int i = 0; i < 8; i++) {
        int idx = (i << 8) + tid;
        int tw = idx >> 6, c4 = idx & 63;
        float4 v = *(const float4*)&g_qa[(tbase + tw)*256 + (c4 << 2)];
        s2[tw][(c4 << 2)]     = v.x;
        s2[tw][(c4 << 2) + 1] = v.y;
        s2[tw][(c4 << 2) + 2] = v.z;
        s2[tw][(c4 << 2) + 3] = v.w;
    }
    __syncthreads();
    int hs = ((hr + 4) & 255) << 8;
    for (int i = 0; i < 32; i++) {
        int idx = (i << 8) + tid;
        int c = idx >> 5, wp = idx & 31;
        out[(size_t)((b << 8) + c)*65536 + hs + ((w0 + wp + 4) & 255)] = s2[wp][c];
    }
}

// ---------------- launch ----------------
extern "C" void kernel_launch(void* const* d_in, const int* in_sizes, int n_in,
                              void* d_out, int out_size) {
    const float* x      = (const float*)d_in[0];
    const float* w_qkv  = (const float*)d_in[1];
    const float* b_qkv  = (const float*)d_in[2];
    const float* rel_pos= (const float*)d_in[3];
    const float* gn_w   = (const float*)d_in[4];
    const float* gn_b   = (const float*)d_in[5];
    const float* sq1    = (const float*)d_in[6];
    const float* sq2    = (const float*)d_in[7];
    const float* gwc    = (const float*)d_in[8];
    const float* gwc_b  = (const float*)d_in[9];
    const float* pwc1   = (const float*)d_in[10];
    const float* pwc2   = (const float*)d_in[11];
    const float* w_out  = (const float*)d_in[12];
    const float* b_out  = (const float*)d_in[13];
    float* out = (float*)d_out;

    __nv_bfloat16 *p_bqh, *p_bql, *p_bouth, *p_boutl, *p_bsqh, *p_bsql, *p_bp2h, *p_bp2l;
    __nv_bfloat16 *p_xh, *p_xl, *p_kh, *p_kl, *p_atth, *p_attl, *p_ulsh, *p_ulsl, *p_bconv2;
    cudaGetSymbolAddress((void**)&p_bqh,   g_bqh);
    cudaGetSymbolAddress((void**)&p_bql,   g_bql);
    cudaGetSymbolAddress((void**)&p_bouth, g_bouth);
    cudaGetSymbolAddress((void**)&p_boutl, g_boutl);
    cudaGetSymbolAddress((void**)&p_bsqh,  g_bsqh);
    cudaGetSymbolAddress((void**)&p_bsql,  g_bsql);
    cudaGetSymbolAddress((void**)&p_bp2h,  g_bp2h);
    cudaGetSymbolAddress((void**)&p_bp2l,  g_bp2l);
    cudaGetSymbolAddress((void**)&p_xh,    g_xh);
    cudaGetSymbolAddress((void**)&p_xl,    g_xl);
    cudaGetSymbolAddress((void**)&p_kh,    g_kh);
    cudaGetSymbolAddress((void**)&p_kl,    g_kl);
    cudaGetSymbolAddress((void**)&p_atth,  g_atth);
    cudaGetSymbolAddress((void**)&p_attl,  g_attl);
    cudaGetSymbolAddress((void**)&p_ulsh,  g_ulsh);
    cudaGetSymbolAddress((void**)&p_ulsl,  g_ulsl);
    cudaGetSymbolAddress((void**)&p_bconv2,g_bconv2);

    const int DSM = 98304;                    // hgemmA: 2 stages x 48KB
    const int ASM = 49152*2 + 900*4;          // attn: 96KB tiles + rel_pos
    cudaFuncSetAttribute(hgemmA<EQKVt>, cudaFuncAttributeMaxDynamicSharedMemorySize, DSM);
    cudaFuncSetAttribute(hgemmA<EOutT>, cudaFuncAttributeMaxDynamicSharedMemorySize, DSM);
    cudaFuncSetAttribute(hgemmA<ESQ>,   cudaFuncAttributeMaxDynamicSharedMemorySize, DSM);
    cudaFuncSetAttribute(hgemmA<EY2h>,  cudaFuncAttributeMaxDynamicSharedMemorySize, DSM);
    cudaFuncSetAttribute(attn_mma,      cudaFuncAttributeMaxDynamicSharedMemorySize, ASM);

    zero_small<<<4, 256>>>();                                              // 0
    prep_bw<<<768, 256>>>(w_qkv, p_bqh, p_bql, 768*256);                   // 1
    xsplit<<<4096, 256>>>(x);                                              // 2
    hgemmA<EQKVt><<<dim3(6, 1024), 256, DSM>>>(p_xh, p_xl, 256,
                                               p_bqh, p_bql, 256, 8, EQKVt{b_qkv}); // 3 (profiled)

    gn_stats<<<256, 256>>>();
    sum_gnw<<<1, 256>>>(gn_w);
    sru_elem<<<65536, 256>>>(gn_w, gn_b);

    prep_bsq<<<128, 256>>>(sq1, sq2);
    hgemmA<ESQ><<<dim3(1, 1024), 256, DSM>>>(p_kh, p_kl, 256, p_bsqh, p_bsql, 256, 8, ESQ{});
    prep_bconv2<<<(2*128*1088 + 255)/256, 256>>>(gwc, pwc1);
    hgemmS<<<dim3(1, 1024, 2), 256>>>(AConv2{}, p_bconv2, gwc_b);
    prep_bp2<<<64, 256>>>(pwc2);
    hgemmA<EY2h><<<dim3(2, 1024), 256, DSM>>>(p_ulsh, p_ulsl, 64, p_bp2h, p_bp2l, 64, 2, EY2h{});

    pool_kernel<<<512, 256>>>();
    softmax512<<<2, 512>>>();
    cru_combine<<<131072, 256>>>();

    attn_mma<<<dim3(1024, 2, 2), 128, ASM>>>(rel_pos);
    prep_bw<<<256, 256>>>(w_out, p_bouth, p_boutl, 256*256);
    hgemmA<EOutT><<<dim3(2, 1024), 256, DSM>>>(p_atth, p_attl, 256,
                                               p_bouth, p_boutl, 256, 8, EOutT{b_out});
    unscatter<<<4096, 256>>>(out);
}

// round 13
// speedup vs baseline: 1.2240x; 1.0474x over previous
#include <cuda_runtime.h>
#include <cuda_bf16.h>
#include <math.h>
#include <cstdint>

#define TTOT 131072
#define SCALE 0.17677669529663687f
#define GN_N 1048576.0f

__device__ __forceinline__ void mma16816(float* d, const uint32_t* a, const uint32_t* b) {
    asm volatile("mma.sync.aligned.m16n8k16.row.col.f32.bf16.bf16.f32 "
        "{%0,%1,%2,%3}, {%4,%5,%6,%7}, {%8,%9}, {%0,%1,%2,%3};"
        : "+f"(d[0]), "+f"(d[1]), "+f"(d[2]), "+f"(d[3])
        : "r"(a[0]), "r"(a[1]), "r"(a[2]), "r"(a[3]), "r"(b[0]), "r"(b[1]));
}
__device__ __forceinline__ void ldsm4(uint32_t& r0, uint32_t& r1, uint32_t& r2, uint32_t& r3,
                                      uint32_t addr) {
    asm volatile("ldmatrix.sync.aligned.m8n8.x4.shared.b16 {%0,%1,%2,%3}, [%4];"
                 : "=r"(r0), "=r"(r1), "=r"(r2), "=r"(r3) : "r"(addr));
}
__device__ __forceinline__ uint32_t smem_u32(const void* p) {
    uint32_t a;
    asm("{ .reg .u64 t; cvta.to.shared.u64 t, %1; cvt.u32.u64 %0, t; }" : "=r"(a) : "l"(p));
    return a;
}
__device__ __forceinline__ float bf2f(__nv_bfloat16 h) { return __bfloat162float(h); }

#define CP_A16(d, s) asm volatile("cp.async.cg.shared.global [%0], [%1], 16;" :: "r"(d), "l"(s) : "memory")
#define CP_A16Z(d, s, sz) asm volatile("cp.async.cg.shared.global [%0], [%1], 16, %2;" :: "r"(d), "l"(s), "r"(sz) : "memory")
#define CP_COMMIT()  asm volatile("cp.async.commit_group;" ::: "memory")
#define CP_WAIT1()   asm volatile("cp.async.wait_group 1;" ::: "memory")

// ---------------- scratch ----------------
__device__ __nv_bfloat16 g_xh [(size_t)TTOT*256];
__device__ __nv_bfloat16 g_xl [(size_t)TTOT*256];
__device__ __nv_bfloat16 g_kh [(size_t)TTOT*256];
__device__ __nv_bfloat16 g_kl [(size_t)TTOT*256];
__device__ __nv_bfloat16 g_qah[(size_t)TTOT*256];
__device__ __nv_bfloat16 g_qal[(size_t)TTOT*256];
__device__ __nv_bfloat16 g_kah[(size_t)TTOT*256];
__device__ __nv_bfloat16 g_kal[(size_t)TTOT*256];
__device__ __nv_bfloat16 g_vh [(size_t)TTOT*256];
__device__ __nv_bfloat16 g_vl [(size_t)TTOT*256];
__device__ __nv_bfloat16 g_atth[(size_t)TTOT*256];
__device__ __nv_bfloat16 g_attl[(size_t)TTOT*256];
__device__ __nv_bfloat16 g_uphi[(size_t)TTOT*64];
__device__ __nv_bfloat16 g_uplo[(size_t)TTOT*64];
__device__ __nv_bfloat16 g_ulsh[(size_t)TTOT*64];
__device__ __nv_bfloat16 g_ulsl[(size_t)TTOT*64];
__device__ float g_q  [(size_t)TTOT*256];
__device__ float g_qa [(size_t)TTOT*256];
__device__ float g_y1 [(size_t)TTOT*256];
__device__ float g_y2 [(size_t)TTOT*192];
__device__ __nv_bfloat16 g_bqh  [768*256];
__device__ __nv_bfloat16 g_bql  [768*256];
__device__ __nv_bfloat16 g_bouth[256*256];
__device__ __nv_bfloat16 g_boutl[256*256];
__device__ __nv_bfloat16 g_bsqh [128*256];
__device__ __nv_bfloat16 g_bsql [128*256];
__device__ __nv_bfloat16 g_bp2h [256*64];
__device__ __nv_bfloat16 g_bp2l [256*64];
__device__ __nv_bfloat16 g_bcvh [2*128*352];
__device__ __nv_bfloat16 g_bcvl [2*128*352];
__device__ float g_gnstats[2*16*2];
__device__ float g_pool[2*512];
__device__ float g_misc[4];

// ---------------- small utilities ----------------
__global__ void zero_small() {
    int i = blockIdx.x*256 + threadIdx.x;
    if (i < 1024) g_pool[i] = 0.f;
    if (i < 64)   g_gnstats[i] = 0.f;
}
__global__ void sum_gnw(const float* __restrict__ gn_w) {
    __shared__ float sh[256];
    sh[threadIdx.x] = gn_w[threadIdx.x];
    __syncthreads();
    for (int st = 128; st > 0; st >>= 1) {
        if (threadIdx.x < st) sh[threadIdx.x] += sh[threadIdx.x + st];
        __syncthreads();
    }
    if (threadIdx.x == 0) g_misc[0] = sh[0];
}
__global__ void prep_bw(const float* __restrict__ w,
                        __nv_bfloat16* __restrict__ dh, __nv_bfloat16* __restrict__ dl, int total) {
    int i = blockIdx.x*256 + threadIdx.x;
    if (i >= total) return;
    float v = w[i];
    __nv_bfloat16 h = __float2bfloat16(v);
    dh[i] = h;
    dl[i] = __float2bfloat16(v - bf2f(h));
}
__global__ void prep_bsq(const float* __restrict__ sq1, const float* __restrict__ sq2) {
    int i = blockIdx.x*256 + threadIdx.x;
    if (i >= 128*256) return;
    int n = i >> 8, k = i & 255;
    float w = 0.f;
    if (n < 64)  { if (k < 128)  w = sq1[n*128 + k]; }
    else         { if (k >= 128) w = sq2[(n-64)*128 + (k-128)]; }
    __nv_bfloat16 h = __float2bfloat16(w);
    g_bsqh[i] = h;
    g_bsql[i] = __float2bfloat16(w - bf2f(h));
}
__global__ void prep_bp2(const float* __restrict__ pwc2) {
    int i = blockIdx.x*256 + threadIdx.x;
    if (i >= 256*64) return;
    int n = i >> 6, k = i & 63;
    float w = (n < 192) ? pwc2[n*64 + k] : 0.f;
    __nv_bfloat16 h = __float2bfloat16(w);
    g_bp2h[i] = h;
    g_bp2l[i] = __float2bfloat16(w - bf2f(h));
}
// conv weights, tap-major, K=352 = 288(gwc) + 64(pwc1)
__global__ void prep_bcv(const float* __restrict__ gwc, const float* __restrict__ pwc1) {
    int i = blockIdx.x*256 + threadIdx.x;
    if (i >= 2*128*352) return;
    int z = i / (128*352), r = i % (128*352);
    int n = r / 352, k = r % 352;
    int c = z*128 + n;
    float w = (k < 288) ? gwc[c*288 + (k & 31)*9 + (k >> 5)] : pwc1[c*64 + (k - 288)];
    __nv_bfloat16 h = __float2bfloat16(w);
    g_bcvh[i] = h;
    g_bcvl[i] = __float2bfloat16(w - bf2f(h));
}

// ---------------- roll + split x ----------------
__global__ __launch_bounds__(256) void xsplit(const float* __restrict__ x) {
    __shared__ float s[256][33];
    int bid = blockIdx.x;
    int b = bid >> 11, rem = bid & 2047;
    int hr = rem >> 3, w0 = (rem & 7) << 5;
    int tid = threadIdx.x, wid = tid >> 5, lane = tid & 31;
    int hs = ((hr + 4) & 255) << 8;
    for (int i = 0; i < 32; i++) {
        int idx = (i << 8) + tid;
        int c = idx >> 5, wp = idx & 31;
        s[c][wp] = x[(size_t)((b << 8) + c)*65536 + hs + ((w0 + wp + 4) & 255)];
    }
    __syncthreads();
    size_t t = (size_t)(b << 16) + (hr << 8) + w0 + lane;
    int c0 = wid << 5;
    for (int j = 0; j < 32; j += 8) {
        __nv_bfloat16 hv[8], lv[8];
#pragma unroll
        for (int e = 0; e < 8; e++) {
            float a = s[c0 + j + e][lane];
            hv[e] = __float2bfloat16(a);
            lv[e] = __float2bfloat16(a - bf2f(hv[e]));
        }
        *(uint4*)&g_xh[t*256 + c0 + j] = *(uint4*)hv;
        *(uint4*)&g_xl[t*256 + c0 + j] = *(uint4*)lv;
    }
}

// ---------------- epilogues ----------------
struct EQKVt {
    const float* bias;
    __device__ void st2(int m, int n, int z, float v0, float v1) const {
        v0 += bias[n]; v1 += bias[n+1];
        if (n < 256) {
            *(float2*)&g_q[(size_t)m*256 + n] = make_float2(v0, v1);
        } else if (n < 512) {
            int c = n - 256;
            __nv_bfloat16 h0 = __float2bfloat16(v0), h1 = __float2bfloat16(v1);
            *(__nv_bfloat162*)&g_kh[(size_t)m*256 + c] = __halves2bfloat162(h0, h1);
            *(__nv_bfloat162*)&g_kl[(size_t)m*256 + c] = __halves2bfloat162(
                __float2bfloat16(v0 - bf2f(h0)), __float2bfloat16(v1 - bf2f(h1)));
        } else {
            int c = n - 512;
            __nv_bfloat16 h0 = __float2bfloat16(v0), h1 = __float2bfloat16(v1);
            *(__nv_bfloat162*)&g_vh[(size_t)m*256 + c] = __halves2bfloat162(h0, h1);
            *(__nv_bfloat162*)&g_vl[(size_t)m*256 + c] = __halves2bfloat162(
                __float2bfloat16(v0 - bf2f(h0)), __float2bfloat16(v1 - bf2f(h1)));
        }
    }
};
struct EOutT {
    const float* bias;
    __device__ void st2(int m, int n, int z, float v0, float v1) const {
        *(float2*)&g_qa[(size_t)m*256 + n] = make_float2(v0 + bias[n], v1 + bias[n+1]);
    }
};
struct ESQ {
    __device__ void st2(int m, int n, int z, float v0, float v1) const {
        __nv_bfloat16 h0 = __float2bfloat16(v0), h1 = __float2bfloat16(v1);
        __nv_bfloat16 l0 = __float2bfloat16(v0 - bf2f(h0)), l1 = __float2bfloat16(v1 - bf2f(h1));
        if (n < 64) {
            *(__nv_bfloat162*)&g_uphi[(size_t)m*64 + n] = __halves2bfloat162(h0, h1);
            *(__nv_bfloat162*)&g_uplo[(size_t)m*64 + n] = __halves2bfloat162(l0, l1);
        } else {
            int nl = n - 64;
            *(__nv_bfloat162*)&g_ulsh[(size_t)m*64 + nl] = __halves2bfloat162(h0, h1);
            *(__nv_bfloat162*)&g_ulsl[(size_t)m*64 + nl] = __halves2bfloat162(l0, l1);
        }
    }
};
struct EY2h {
    __device__ void st2(int m, int n, int z, float v0, float v1) const {
        if (n < 192) *(float2*)&g_y2[(size_t)m*192 + n] = make_float2(v0, v1);
    }
};

// ---------------- dedup split HMMA GEMM ----------------
template<class EF>
__global__ __launch_bounds__(256, 2) void hgemmA(const __nv_bfloat16* __restrict__ Ah_,
                                                 const __nv_bfloat16* __restrict__ Al_, int lda,
                                                 const __nv_bfloat16* __restrict__ Bh_,
                                                 const __nv_bfloat16* __restrict__ Bl_, int ldb,
                                                 int nk, EF ef) {
    extern __shared__ __nv_bfloat16 sm[];
    int tid = threadIdx.x, lane = tid & 31, wid = tid >> 5;
    int m0 = blockIdx.y << 7, n0 = blockIdx.x << 7;
    uint32_t sbase = smem_u32(sm);
    int wm = (wid & 3) << 5, wn = (wid >> 2) << 6;
    int gid = lane >> 2, tig = lane & 3;
    int lr = lane & 7, lh = (lane >> 3) & 1, lk = lane >> 4;
    uint32_t offA[2];
#pragma unroll
    for (int mf = 0; mf < 2; mf++)
        offA[mf] = (uint32_t)(((wm + (mf << 4) + lr + lh*8)*24 + lk*8) << 1);
    int lq = lane >> 3;
    uint32_t offB[4];
#pragma unroll
    for (int p = 0; p < 4; p++)
        offB[p] = (uint32_t)(((wn + (p << 4) + lr + (lq >> 1)*8)*24 + (lq & 1)*8) << 1);

    float acc[2][8][4];
#pragma unroll
    for (int mf = 0; mf < 2; mf++)
#pragma unroll
        for (int nf = 0; nf < 8; nf++)
#pragma unroll
            for (int e = 0; e < 4; e++) acc[mf][nf][e] = 0.f;

    auto prefetch = [&](int ch, int s) {
        int k0 = ch << 5;
#pragma unroll
        for (int i = 0; i < 2; i++) {
            int idx = (i << 8) + tid;
            int r = idx >> 2, c4 = idx & 3;
            int g = c4 >> 1, ke = c4 & 1;
            uint32_t da = sbase + (uint32_t)((s*24576 + (g*128 + r)*24 + ke*8) << 1);
            size_t asrc = (size_t)(m0 + r)*lda + k0 + (c4 << 3);
            size_t bsrc = (size_t)(n0 + r)*ldb + k0 + (c4 << 3);
            CP_A16(da,          Ah_ + asrc);
            CP_A16(da + 12288,  Al_ + asrc);
            CP_A16(da + 24576,  Bh_ + bsrc);
            CP_A16(da + 36864,  Bl_ + bsrc);
        }
        CP_COMMIT();
    };
    prefetch(0, 0);
    for (int ch = 0; ch < nk; ch++) {
        if (ch + 1 < nk) prefetch(ch + 1, (ch + 1) & 1);
        else CP_COMMIT();
        CP_WAIT1();
        __syncthreads();
        uint32_t stb = sbase + (uint32_t)((ch & 1)*49152);
#pragma unroll
        for (int g = 0; g < 2; g++) {
            uint32_t gb = stb + (uint32_t)(g*6144);
            uint32_t a[2][4], b[8][2];
            ldsm4(b[0][0], b[0][1], b[1][0], b[1][1], gb + 24576 + offB[0]);
            ldsm4(b[2][0], b[2][1], b[3][0], b[3][1], gb + 24576 + offB[1]);
            ldsm4(b[4][0], b[4][1], b[5][0], b[5][1], gb + 24576 + offB[2]);
            ldsm4(b[6][0], b[6][1], b[7][0], b[7][1], gb + 24576 + offB[3]);
            ldsm4(a[0][0], a[0][1], a[0][2], a[0][3], gb + offA[0]);
            ldsm4(a[1][0], a[1][1], a[1][2], a[1][3], gb + offA[1]);
#pragma unroll
            for (int mf = 0; mf < 2; mf++)
#pragma unroll
                for (int nf = 0; nf < 8; nf++)
                    mma16816(acc[mf][nf], a[mf], b[nf]);
            ldsm4(a[0][0], a[0][1], a[0][2], a[0][3], gb + 12288 + offA[0]);
            ldsm4(a[1][0], a[1][1], a[1][2], a[1][3], gb + 12288 + offA[1]);
#pragma unroll
            for (int mf = 0; mf < 2; mf++)
#pragma unroll
                for (int nf = 0; nf < 8; nf++)
                    mma16816(acc[mf][nf], a[mf], b[nf]);
            ldsm4(b[0][0], b[0][1], b[1][0], b[1][1], gb + 36864 + offB[0]);
            ldsm4(b[2][0], b[2][1], b[3][0], b[3][1], gb + 36864 + offB[1]);
            ldsm4(b[4][0], b[4][1], b[5][0], b[5][1], gb + 36864 + offB[2]);
            ldsm4(b[6][0], b[6][1], b[7][0], b[7][1], gb + 36864 + offB[3]);
            ldsm4(a[0][0], a[0][1], a[0][2], a[0][3], gb + offA[0]);
            ldsm4(a[1][0], a[1][1], a[1][2], a[1][3], gb + offA[1]);
#pragma unroll
            for (int mf = 0; mf < 2; mf++)
#pragma unroll
                for (int nf = 0; nf < 8; nf++)
                    mma16816(acc[mf][nf], a[mf], b[nf]);
        }
        __syncthreads();
    }
#pragma unroll
    for (int mf = 0; mf < 2; mf++) {
        int row0 = m0 + wm + (mf << 4) + gid;
#pragma unroll
        for (int nf = 0; nf < 8; nf++) {
            int col = n0 + wn + (nf << 3) + (tig << 1);
            ef.st2(row0,     col, 0, acc[mf][nf][0], acc[mf][nf][1]);
            ef.st2(row0 + 8, col, 0, acc[mf][nf][2], acc[mf][nf][3]);
        }
    }
}

// ---------------- conv GEMM: dedup split + async gather prefetch ----------------
// A = im2col(up) K=352 (tap-major 288 + pwc1 64), B = g_bcv[h|l][z], N=128, out -> y1.
__global__ __launch_bounds__(256, 2) void hgemmC(const __nv_bfloat16* __restrict__ Bh_,
                                                 const __nv_bfloat16* __restrict__ Bl_,
                                                 const float* __restrict__ bias) {
    extern __shared__ __nv_bfloat16 sm[];
    int tid = threadIdx.x, lane = tid & 31, wid = tid >> 5;
    int m0 = blockIdx.y << 7, z = blockIdx.z;
    uint32_t sbase = smem_u32(sm);
    int wm = (wid & 3) << 5, wn = (wid >> 2) << 6;
    int gid = lane >> 2, tig = lane & 3;
    int lr = lane & 7, lh = (lane >> 3) & 1, lk = lane >> 4;
    uint32_t offA[2];
#pragma unroll
    for (int mf = 0; mf < 2; mf++)
        offA[mf] = (uint32_t)(((wm + (mf << 4) + lr + lh*8)*24 + lk*8) << 1);
    int lq = lane >> 3;
    uint32_t offB[4];
#pragma unroll
    for (int p = 0; p < 4; p++)
        offB[p] = (uint32_t)(((wn + (p << 4) + lr + (lq >> 1)*8)*24 + (lq & 1)*8) << 1);

    float acc[2][8][4];
#pragma unroll
    for (int mf = 0; mf < 2; mf++)
#pragma unroll
        for (int nf = 0; nf < 8; nf++)
#pragma unroll
            for (int e = 0; e < 4; e++) acc[mf][nf][e] = 0.f;

    const __nv_bfloat16* Bzh = Bh_ + (size_t)z*128*352;
    const __nv_bfloat16* Bzl = Bl_ + (size_t)z*128*352;

    auto prefetch = [&](int ch, int s) {
        int k0 = ch << 5;
#pragma unroll
        for (int i = 0; i < 2; i++) {
            int idx = (i << 8) + tid;
            int r = idx >> 2, c4 = idx & 3;
            int g = c4 >> 1, ke = c4 & 1;
            uint32_t da = sbase + (uint32_t)((s*24576 + (g*128 + r)*24 + ke*8) << 1);
            int k = k0 + (c4 << 3);
            int m = m0 + r;
            size_t aoff; int sz = 16;
            if (k < 288) {
                int tap = k >> 5, kl0 = k & 31;
                int dy = tap/3 - 1, dx = tap - (tap/3)*3 - 1;
                int b = m >> 16;
                int hr = ((m >> 8) & 255) + dy, wr = (m & 255) + dx;
                if ((unsigned)hr > 255u || (unsigned)wr > 255u) sz = 0;
                aoff = (size_t)((b << 16) + ((hr & 255) << 8) + (wr & 255))*64 + (z << 5) + kl0;
            } else {
                aoff = (size_t)m*64 + (k - 288);
            }
            CP_A16Z(da,         g_uphi + aoff, sz);
            CP_A16Z(da + 12288, g_uplo + aoff, sz);
            size_t boff = (size_t)r*352 + k;
            CP_A16(da + 24576, Bzh + boff);
            CP_A16(da + 36864, Bzl + boff);
        }
        CP_COMMIT();
    };
    prefetch(0, 0);
    for (int ch = 0; ch < 11; ch++) {
        if (ch + 1 < 11) prefetch(ch + 1, (ch + 1) & 1);
        else CP_COMMIT();
        CP_WAIT1();
        __syncthreads();
        uint32_t stb = sbase + (uint32_t)((ch & 1)*49152);
#pragma unroll
        for (int g = 0; g < 2; g++) {
            uint32_t gb = stb + (uint32_t)(g*6144);
            uint32_t a[2][4], b[8][2];
            ldsm4(b[0][0], b[0][1], b[1][0], b[1][1], gb + 24576 + offB[0]);
            ldsm4(b[2][0], b[2][1], b[3][0], b[3][1], gb + 24576 + offB[1]);
            ldsm4(b[4][0], b[4][1], b[5][0], b[5][1], gb + 24576 + offB[2]);
            ldsm4(b[6][0], b[6][1], b[7][0], b[7][1], gb + 24576 + offB[3]);
            ldsm4(a[0][0], a[0][1], a[0][2], a[0][3], gb + offA[0]);
            ldsm4(a[1][0], a[1][1], a[1][2], a[1][3], gb + offA[1]);
#pragma unroll
            for (int mf = 0; mf < 2; mf++)
#pragma unroll
                for (int nf = 0; nf < 8; nf++)
                    mma16816(acc[mf][nf], a[mf], b[nf]);
            ldsm4(a[0][0], a[0][1], a[0][2], a[0][3], gb + 12288 + offA[0]);
            ldsm4(a[1][0], a[1][1], a[1][2], a[1][3], gb + 12288 + offA[1]);
#pragma unroll
            for (int mf = 0; mf < 2; mf++)
#pragma unroll
                for (int nf = 0; nf < 8; nf++)
                    mma16816(acc[mf][nf], a[mf], b[nf]);
            ldsm4(b[0][0], b[0][1], b[1][0], b[1][1], gb + 36864 + offB[0]);
            ldsm4(b[2][0], b[2][1], b[3][0], b[3][1], gb + 36864 + offB[1]);
            ldsm4(b[4][0], b[4][1], b[5][0], b[5][1], gb + 36864 + offB[2]);
            ldsm4(b[6][0], b[6][1], b[7][0], b[7][1], gb + 36864 + offB[3]);
            ldsm4(a[0][0], a[0][1], a[0][2], a[0][3], gb + offA[0]);
            ldsm4(a[1][0], a[1][1], a[1][2], a[1][3], gb + offA[1]);
#pragma unroll
            for (int mf = 0; mf < 2; mf++)
#pragma unroll
                for (int nf = 0; nf < 8; nf++)
                    mma16816(acc[mf][nf], a[mf], b[nf]);
        }
        __syncthreads();
    }
#pragma unroll
    for (int mf = 0; mf < 2; mf++) {
        int row0 = m0 + wm + (mf << 4) + gid;
#pragma unroll
        for (int nf = 0; nf < 8; nf++) {
            int col = wn + (nf << 3) + (tig << 1);
            int c = (z << 7) + col;
            *(float2*)&g_y1[(size_t)row0*256 + c] =
                make_float2(acc[mf][nf][0] + bias[c], acc[mf][nf][1] + bias[c+1]);
            *(float2*)&g_y1[(size_t)(row0 + 8)*256 + c] =
                make_float2(acc[mf][nf][2] + bias[c], acc[mf][nf][3] + bias[c+1]);
        }
    }
}

// ---------------- GN stats / SRU / CRU glue ----------------
__global__ void gn_stats() {
    int t0 = blockIdx.x * 512;
    int c = threadIdx.x;
    const float* p = g_q + (size_t)t0*256 + c;
    float s = 0.f, s2 = 0.f;
#pragma unroll 4
    for (int i = 0; i < 512; i++) { float v = p[(size_t)i*256]; s += v; s2 += v*v; }
#pragma unroll
    for (int off = 8; off > 0; off >>= 1) {
        s  += __shfl_down_sync(0xffffffff, s,  off, 16);
        s2 += __shfl_down_sync(0xffffffff, s2, off, 16);
    }
    if ((c & 15) == 0) {
        int b = t0 >> 16, g = c >> 4;
        atomicAdd(&g_gnstats[((b << 4) + g)*2],     s);
        atomicAdd(&g_gnstats[((b << 4) + g)*2 + 1], s2);
    }
}
__global__ void sru_elem(const float* __restrict__ gn_w, const float* __restrict__ gn_b) {
    int i = blockIdx.x*256 + threadIdx.x;
    int t = i >> 7, cp = i & 127;
    int b = t >> 16;
    int c1 = cp, c2 = cp + 128;
    float wsum = g_misc[0];
    int g1 = c1 >> 4, g2 = c2 >> 4;
    float m1 = g_gnstats[((b<<4)+g1)*2] / GN_N;
    float v1 = g_gnstats[((b<<4)+g1)*2+1] / GN_N - m1*m1;
    float m2 = g_gnstats[((b<<4)+g2)*2] / GN_N;
    float v2 = g_gnstats[((b<<4)+g2)*2+1] / GN_N - m2*m2;
    float w1c = gn_w[c1], w2c = gn_w[c2];
    float A1 = rsqrtf(v1 + 1e-5f)*w1c, B1 = gn_b[c1] - m1*rsqrtf(v1 + 1e-5f)*w1c;
    float A2 = rsqrtf(v2 + 1e-5f)*w2c, B2 = gn_b[c2] - m2*rsqrtf(v2 + 1e-5f)*w2c;
    float x1 = g_q[(size_t)t*256 + c1], x2 = g_q[(size_t)t*256 + c2];
    float rw1 = 1.0f/(1.0f + expf(-(x1*A1 + B1)*(w1c/wsum)));
    float rw2 = 1.0f/(1.0f + expf(-(x2*A2 + B2)*(w2c/wsum)));
    float w11 = rw1 > 0.5f ? 1.0f : rw1, w21 = rw1 > 0.5f ? 0.0f : rw1;
    float w12 = rw2 > 0.5f ? 1.0f : rw2, w22 = rw2 > 0.5f ? 0.0f : rw2;
    float o1 = w11*x1 + w22*x2;
    float o2 = w12*x2 + w21*x1;
    __nv_bfloat16 h1 = __float2bfloat16(o1), h2 = __float2bfloat16(o2);
    g_qah[(size_t)t*256 + c1] = h1;
    g_qal[(size_t)t*256 + c1] = __float2bfloat16(o1 - bf2f(h1));
    g_qah[(size_t)t*256 + c2] = h2;
    g_qal[(size_t)t*256 + c2] = __float2bfloat16(o2 - bf2f(h2));
}
__global__ void pool_kernel() {
    int t0 = blockIdx.x * 256;
    int b = t0 >> 16;
    int tid = threadIdx.x;
    float a1 = 0.f, a2 = 0.f, a3 = 0.f;
    for (int t = t0; t < t0 + 256; t++) {
        a1 += g_y1[(size_t)t*256 + tid];
        if (tid < 192) a2 += g_y2[(size_t)t*192 + tid];
        if (tid < 64)  a3 += bf2f(g_ulsh[(size_t)t*64 + tid]) + bf2f(g_ulsl[(size_t)t*64 + tid]);
    }
    atomicAdd(&g_pool[(b << 9) + tid], a1);
    if (tid < 192) atomicAdd(&g_pool[(b << 9) + 256 + tid], a2);
    if (tid < 64)  atomicAdd(&g_pool[(b << 9) + 448 + tid], a3);
}
__global__ void softmax512() {
    int b = blockIdx.x, t = threadIdx.x;
    __shared__ float sh[512];
    float v = g_pool[(b << 9) + t] * (1.0f/65536.0f);
    sh[t] = v;
    __syncthreads();
    for (int st = 256; st > 0; st >>= 1) { if (t < st) sh[t] = fmaxf(sh[t], sh[t + st]); __syncthreads(); }
    float mx = sh[0];
    __syncthreads();
    float e = expf(v - mx);
    sh[t] = e;
    __syncthreads();
    for (int st = 256; st > 0; st >>= 1) { if (t < st) sh[t] += sh[t + st]; __syncthreads(); }
    float sum = sh[0];
    __syncthreads();
    g_pool[(b << 9) + t] = e / sum;
}
__global__ void cru_combine() {
    int i = blockIdx.x*256 + threadIdx.x;
    int t = i >> 8, c = i & 255;
    int b = t >> 16;
    float y1 = g_y1[i];
    float y2v;
    if (c < 192) y2v = g_y2[(size_t)t*192 + c];
    else {
        int nl = c - 192;
        y2v = bf2f(g_ulsh[(size_t)t*64 + nl]) + bf2f(g_ulsl[(size_t)t*64 + nl]);
    }
    float o = g_pool[(b << 9) + c]*y1 + g_pool[(b << 9) + 256 + c]*y2v;
    __nv_bfloat16 h = __float2bfloat16(o);
    g_kah[(size_t)t*256 + c] = h;
    g_kal[(size_t)t*256 + c] = __float2bfloat16(o - bf2f(h));
}

// ---------------- HMMA windowed attention (round-12, unchanged) ----------------
__global__ __launch_bounds__(128) void attn_mma(const float* __restrict__ rel_pos) {
    extern __shared__ __nv_bfloat16 smb[];
    float* rps = (float*)(smb + 49152);
    int tid = threadIdx.x, lane = tid & 31, wid = tid >> 5;
    int win = blockIdx.x, hg = blockIdx.y, b = blockIdx.z;
    int wy = win >> 5, wx = win & 31;
    int t0 = (b << 16) + (wy << 11) + (wx << 3);
    for (int i = 0; i < 8; i++) {
        int idx = (i << 7) + tid;
        int hh = idx >> 8, r = idx & 255;
        int tok = r >> 2, c8 = (r & 3) << 3;
        int token = t0 + ((tok >> 3) << 8) + (tok & 7);
        size_t src = (size_t)token*256 + (((hg << 2) + hh) << 5) + c8;
        int dst = hh*12288 + ((c8 >> 4)*64 + tok)*24 + (c8 & 15);
        *(uint4*)&smb[dst]        = *(const uint4*)&g_kah[src];
        *(uint4*)&smb[dst + 3072] = *(const uint4*)&g_kal[src];
    }
    for (int i = 0; i < 32; i++) {
        int idx = (i << 7) + tid;
        int hh = idx >> 10, r = idx & 1023;
        int tok = r >> 4, dp = (r & 15) << 1;
        int token = t0 + ((tok >> 3) << 8) + (tok & 7);
        size_t src = (size_t)token*256 + (((hg << 2) + hh) << 5) + dp;
        __nv_bfloat162 vh = *(const __nv_bfloat162*)&g_vh[src];
        __nv_bfloat162 vl = *(const __nv_bfloat162*)&g_vl[src];
        int base = hh*12288 + 6144 + (tok >> 4)*768 + (tok & 15);
        smb[base + dp*24]            = vh.x;
        smb[base + (dp+1)*24]        = vh.y;
        smb[base + 3072 + dp*24]     = vl.x;
        smb[base + 3072 + (dp+1)*24] = vl.y;
    }
    for (int i = tid; i < 900; i += 128) {
        int hh = i / 225, r = i - hh*225;
        rps[i] = rel_pos[(((hg << 2) + hh))*225 + r];
    }
    __syncthreads();

    int hh = wid;
    uint32_t tb = smem_u32(smb) + (uint32_t)(hh*24576);
    uint32_t khb = tb, klb = tb + 6144, vhb = tb + 12288, vlb = tb + 18432;
    const float* rp = rps + hh*225;
    int gid = lane >> 2, tig = lane & 3;
    int lr = lane & 7, lq = lane >> 3;
    uint32_t offK[4], offV[2];
#pragma unroll
    for (int p = 0; p < 4; p++)
        offK[p] = (uint32_t)((((p << 4) + lr + (lq >> 1)*8)*24 + (lq & 1)*8) << 1);
#pragma unroll
    for (int p = 0; p < 2; p++)
        offV[p] = (uint32_t)((((p << 4) + lr + (lq >> 1)*8)*24 + (lq & 1)*8) << 1);
    bool lrm = wy == 31, lcm = wx == 31;
    int hbc = ((hg << 2) + hh) << 5;

    for (int half = 0; half < 2; half++) {
        int rbase = half << 5;
        uint32_t qh[2][2][4], ql[2][2][4];
#pragma unroll
        for (int mt = 0; mt < 2; mt++) {
            int r0 = rbase + (mt << 4) + gid;
            int tok0 = t0 + ((r0 >> 3) << 8) + (r0 & 7);
            int r1 = r0 + 8;
            int tok1 = t0 + ((r1 >> 3) << 8) + (r1 & 7);
#pragma unroll
            for (int kf = 0; kf < 2; kf++) {
                int kc = hbc + (kf << 4) + (tig << 1);
                qh[mt][kf][0] = *(const uint32_t*)&g_qah[(size_t)tok0*256 + kc];
                qh[mt][kf][1] = *(const uint32_t*)&g_qah[(size_t)tok1*256 + kc];
                qh[mt][kf][2] = *(const uint32_t*)&g_qah[(size_t)tok0*256 + kc + 8];
                qh[mt][kf][3] = *(const uint32_t*)&g_qah[(size_t)tok1*256 + kc + 8];
                ql[mt][kf][0] = *(const uint32_t*)&g_qal[(size_t)tok0*256 + kc];
                ql[mt][kf][1] = *(const uint32_t*)&g_qal[(size_t)tok1*256 + kc];
                ql[mt][kf][2] = *(const uint32_t*)&g_qal[(size_t)tok0*256 + kc + 8];
                ql[mt][kf][3] = *(const uint32_t*)&g_qal[(size_t)tok1*256 + kc + 8];
            }
        }
        float sacc[2][8][4];
#pragma unroll
        for (int mt = 0; mt < 2; mt++)
#pragma unroll
            for (int nt = 0; nt < 8; nt++)
#pragma unroll
                for (int e = 0; e < 4; e++) sacc[mt][nt][e] = 0.f;
#pragma unroll
        for (int kg = 0; kg < 2; kg++) {
            uint32_t bk[8][2];
            uint32_t kgb = khb + (uint32_t)(kg*3072);
            ldsm4(bk[0][0], bk[0][1], bk[1][0], bk[1][1], kgb + offK[0]);
            ldsm4(bk[2][0], bk[2][1], bk[3][0], bk[3][1], kgb + offK[1]);
            ldsm4(bk[4][0], bk[4][1], bk[5][0], bk[5][1], kgb + offK[2]);
            ldsm4(bk[6][0], bk[6][1], bk[7][0], bk[7][1], kgb + offK[3]);
#pragma unroll
            for (int mt = 0; mt < 2; mt++)
#pragma unroll
                for (int nt = 0; nt < 8; nt++) {
                    mma16816(sacc[mt][nt], qh[mt][kg], bk[nt]);
                    mma16816(sacc[mt][nt], ql[mt][kg], bk[nt]);
                }
            uint32_t lgb = klb + (uint32_t)(kg*3072);
            ldsm4(bk[0][0], bk[0][1], bk[1][0], bk[1][1], lgb + offK[0]);
            ldsm4(bk[2][0], bk[2][1], bk[3][0], bk[3][1], lgb + offK[1]);
            ldsm4(bk[4][0], bk[4][1], bk[5][0], bk[5][1], lgb + offK[2]);
            ldsm4(bk[6][0], bk[6][1], bk[7][0], bk[7][1], lgb + offK[3]);
#pragma unroll
            for (int mt = 0; mt < 2; mt++)
#pragma unroll
                for (int nt = 0; nt < 8; nt++)
                    mma16816(sacc[mt][nt], qh[mt][kg], bk[nt]);
        }
#pragma unroll
        for (int mt = 0; mt < 2; mt++)
#pragma unroll
            for (int rr = 0; rr < 2; rr++) {
                int row = rbase + (mt << 4) + gid + (rr << 3);
                int ph = row >> 3, pw = row & 7;
                float vv[16];
                float mx = -1e30f;
#pragma unroll
                for (int nt = 0; nt < 8; nt++)
#pragma unroll
                    for (int j = 0; j < 2; j++) {
                        int col = (nt << 3) + (tig << 1) + j;
                        int qy = col >> 3, qw = col & 7;
                        float v = sacc[mt][nt][rr*2 + j]*SCALE + rp[(ph - qy + 7)*15 + (pw - qw + 7)];
                        if ((lrm && ((ph < 4) != (qy < 4))) || (lcm && ((pw < 4) != (qw < 4)))) v = -1e30f;
                        vv[nt*2 + j] = v;
                        mx = fmaxf(mx, v);
                    }
                mx = fmaxf(mx, __shfl_xor_sync(0xffffffff, mx, 1));
                mx = fmaxf(mx, __shfl_xor_sync(0xffffffff, mx, 2));
                float s = 0.f;
#pragma unroll
                for (int e = 0; e < 16; e++) { vv[e] = expf(vv[e] - mx); s += vv[e]; }
                s += __shfl_xor_sync(0xffffffff, s, 1);
                s += __shfl_xor_sync(0xffffffff, s, 2);
                float inv = 1.0f / s;
#pragma unroll
                for (int nt = 0; nt < 8; nt++)
#pragma unroll
                    for (int j = 0; j < 2; j++)
                        sacc[mt][nt][rr*2 + j] = vv[nt*2 + j]*inv;
            }
        float oacc[2][4][4];
#pragma unroll
        for (int mt = 0; mt < 2; mt++)
#pragma unroll
            for (int nt = 0; nt < 4; nt++)
#pragma unroll
                for (int e = 0; e < 4; e++) oacc[mt][nt][e] = 0.f;
#pragma unroll
        for (int kf = 0; kf < 4; kf++) {
            uint32_t pfh[2][4], pfl[2][4];
#pragma unroll
            for (int mt = 0; mt < 2; mt++) {
#pragma unroll
                for (int e = 0; e < 4; e++) {
                    int nt = 2*kf + (e >> 1);
                    float p0 = sacc[mt][nt][(e & 1)*2];
                    float p1 = sacc[mt][nt][(e & 1)*2 + 1];
                    __nv_bfloat162 h2 = __floats2bfloat162_rn(p0, p1);
                    pfh[mt][e] = *(uint32_t*)&h2;
                    __nv_bfloat162 l2 = __floats2bfloat162_rn(p0 - bf2f(h2.x), p1 - bf2f(h2.y));
                    pfl[mt][e] = *(uint32_t*)&l2;
                }
            }
            uint32_t bv[4][2];
            uint32_t vgb = vhb + (uint32_t)(kf*1536);
            ldsm4(bv[0][0], bv[0][1], bv[1][0], bv[1][1], vgb + offV[0]);
            ldsm4(bv[2][0], bv[2][1], bv[3][0], bv[3][1], vgb + offV[1]);
#pragma unroll
            for (int mt = 0; mt < 2; mt++)
#pragma unroll
                for (int nt = 0; nt < 4; nt++) {
                    mma16816(oacc[mt][nt], pfh[mt], bv[nt]);
                    mma16816(oacc[mt][nt], pfl[mt], bv[nt]);
                }
            uint32_t lgb = vlb + (uint32_t)(kf*1536);
            ldsm4(bv[0][0], bv[0][1], bv[1][0], bv[1][1], lgb + offV[0]);
            ldsm4(bv[2][0], bv[2][1], bv[3][0], bv[3][1], lgb + offV[1]);
#pragma unroll
            for (int mt = 0; mt < 2; mt++)
#pragma unroll
                for (int nt = 0; nt < 4; nt++)
                    mma16816(oacc[mt][nt], pfh[mt], bv[nt]);
        }
#pragma unroll
        for (int mt = 0; mt < 2; mt++) {
            int r0 = rbase + (mt << 4) + gid;
            int tok0 = t0 + ((r0 >> 3) << 8) + (r0 & 7);
            int r1 = r0 + 8;
            int tok1 = t0 + ((r1 >> 3) << 8) + (r1 & 7);
#pragma unroll
            for (int nt = 0; nt < 4; nt++) {
                int c = hbc + (nt << 3) + (tig << 1);
                float a0 = oacc[mt][nt][0], a1 = oacc[mt][nt][1];
                float a2 = oacc[mt][nt][2], a3 = oacc[mt][nt][3];
                __nv_bfloat162 h0 = __floats2bfloat162_rn(a0, a1);
                __nv_bfloat162 h1 = __floats2bfloat162_rn(a2, a3);
                *(__nv_bfloat162*)&g_atth[(size_t)tok0*256 + c] = h0;
                *(__nv_bfloat162*)&g_atth[(size_t)tok1*256 + c] = h1;
                *(__nv_bfloat162*)&g_attl[(size_t)tok0*256 + c] =
                    __floats2bfloat162_rn(a0 - bf2f(h0.x), a1 - bf2f(h0.y));
                *(__nv_bfloat162*)&g_attl[(size_t)tok1*256 + c] =
                    __floats2bfloat162_rn(a2 - bf2f(h1.x), a3 - bf2f(h1.y));
            }
        }
    }
}

// ---------------- final un-roll scatter to NCHW ----------------
__global__ __launch_bounds__(256) void unscatter(float* __restrict__ out) {
    __shared__ float s2[32][261];
    int bid = blockIdx.x;
    int b = bid >> 11, rem = bid & 2047;
    int hr = rem >> 3, w0 = (rem & 7) << 5;
    int tid = threadIdx.x;
    size_t tbase = (size_t)(b << 16) + (hr << 8) + w0;
    for (int i = 0; i < 8; i++) {
        int idx = (i << 8) + tid;
        int tw = idx >> 6, c4 = idx & 63;
        float4 v = *(const float4*)&g_qa[(tbase + tw)*256 + (c4 << 2)];
        s2[tw][(c4 << 2)]     = v.x;
        s2[tw][(c4 << 2) + 1] = v.y;
        s2[tw][(c4 << 2) + 2] = v.z;
        s2[tw][(c4 << 2) + 3] = v.w;
    }
    __syncthreads();
    int hs = ((hr + 4) & 255) << 8;
    for (int i = 0; i < 32; i++) {
        int idx = (i << 8) + tid;
        int c = idx >> 5, wp = idx & 31;
        out[(size_t)((b << 8) + c)*65536 + hs + ((w0 + wp + 4) & 255)] = s2[wp][c];
    }
}

// ---------------- launch ----------------
extern "C" void kernel_launch(void* const* d_in, const int* in_sizes, int n_in,
                              void* d_out, int out_size) {
    const float* x      = (const float*)d_in[0];
    const float* w_qkv  = (const float*)d_in[1];
    const float* b_qkv  = (const float*)d_in[2];
    const float* rel_pos= (const float*)d_in[3];
    const float* gn_w   = (const float*)d_in[4];
    const float* gn_b   = (const float*)d_in[5];
    const float* sq1    = (const float*)d_in[6];
    const float* sq2    = (const float*)d_in[7];
    const float* gwc    = (const float*)d_in[8];
    const float* gwc_b  = (const float*)d_in[9];
    const float* pwc1   = (const float*)d_in[10];
    const float* pwc2   = (const float*)d_in[11];
    const float* w_out  = (const float*)d_in[12];
    const float* b_out  = (const float*)d_in[13];
    float* out = (float*)d_out;

    __nv_bfloat16 *p_bqh, *p_bql, *p_bouth, *p_boutl, *p_bsqh, *p_bsql, *p_bp2h, *p_bp2l;
    __nv_bfloat16 *p_xh, *p_xl, *p_kh, *p_kl, *p_atth, *p_attl, *p_ulsh, *p_ulsl;
    __nv_bfloat16 *p_bcvh, *p_bcvl;
    cudaGetSymbolAddress((void**)&p_bqh,   g_bqh);
    cudaGetSymbolAddress((void**)&p_bql,   g_bql);
    cudaGetSymbolAddress((void**)&p_bouth, g_bouth);
    cudaGetSymbolAddress((void**)&p_boutl, g_boutl);
    cudaGetSymbolAddress((void**)&p_bsqh,  g_bsqh);
    cudaGetSymbolAddress((void**)&p_bsql,  g_bsql);
    cudaGetSymbolAddress((void**)&p_bp2h,  g_bp2h);
    cudaGetSymbolAddress((void**)&p_bp2l,  g_bp2l);
    cudaGetSymbolAddress((void**)&p_xh,    g_xh);
    cudaGetSymbolAddress((void**)&p_xl,    g_xl);
    cudaGetSymbolAddress((void**)&p_kh,    g_kh);
    cudaGetSymbolAddress((void**)&p_kl,    g_kl);
    cudaGetSymbolAddress((void**)&p_atth,  g_atth);
    cudaGetSymbolAddress((void**)&p_attl,  g_attl);
    cudaGetSymbolAddress((void**)&p_ulsh,  g_ulsh);
    cudaGetSymbolAddress((void**)&p_ulsl,  g_ulsl);
    cudaGetSymbolAddress((void**)&p_bcvh,  g_bcvh);
    cudaGetSymbolAddress((void**)&p_bcvl,  g_bcvl);

    const int DSM = 98304;
    const int ASM = 49152*2 + 900*4;
    cudaFuncSetAttribute(hgemmA<EQKVt>, cudaFuncAttributeMaxDynamicSharedMemorySize, DSM);
    cudaFuncSetAttribute(hgemmA<EOutT>, cudaFuncAttributeMaxDynamicSharedMemorySize, DSM);
    cudaFuncSetAttribute(hgemmA<ESQ>,   cudaFuncAttributeMaxDynamicSharedMemorySize, DSM);
    cudaFuncSetAttribute(hgemmA<EY2h>,  cudaFuncAttributeMaxDynamicSharedMemorySize, DSM);
    cudaFuncSetAttribute(hgemmC,        cudaFuncAttributeMaxDynamicSharedMemorySize, DSM);
    cudaFuncSetAttribute(attn_mma,      cudaFuncAttributeMaxDynamicSharedMemorySize, ASM);

    zero_small<<<4, 256>>>();                                              // 0
    prep_bw<<<768, 256>>>(w_qkv, p_bqh, p_bql, 768*256);                   // 1
    xsplit<<<4096, 256>>>(x);                                              // 2
    hgemmA<EQKVt><<<dim3(6, 1024), 256, DSM>>>(p_xh, p_xl, 256,
                                               p_bqh, p_bql, 256, 8, EQKVt{b_qkv}); // 3 (profiled)

    gn_stats<<<256, 256>>>();
    sum_gnw<<<1, 256>>>(gn_w);
    sru_elem<<<65536, 256>>>(gn_w, gn_b);

    prep_bsq<<<128, 256>>>(sq1, sq2);
    hgemmA<ESQ><<<dim3(1, 1024), 256, DSM>>>(p_kh, p_kl, 256, p_bsqh, p_bsql, 256, 8, ESQ{});
    prep_bcv<<<(2*128*352 + 255)/256, 256>>>(gwc, pwc1);
    hgemmC<<<dim3(1, 1024, 2), 256, DSM>>>(p_bcvh, p_bcvl, gwc_b);
    prep_bp2<<<64, 256>>>(pwc2);
    hgemmA<EY2h><<<dim3(2, 1024), 256, DSM>>>(p_ulsh, p_ulsl, 64, p_bp2h, p_bp2l, 64, 2, EY2h{});

    pool_kernel<<<512, 256>>>();
    softmax512<<<2, 512>>>();
    cru_combine<<<131072, 256>>>();

    attn_mma<<<dim3(1024, 2, 2), 128, ASM>>>(rel_pos);
    prep_bw<<<256, 256>>>(w_out, p_bouth, p_boutl, 256*256);
    hgemmA<EOutT><<<dim3(2, 1024), 256, DSM>>>(p_atth, p_attl, 256,
                                               p_bouth, p_boutl, 256, 8, EOutT{b_out});
    unscatter<<<4096, 256>>>(out);
}

// round 14
// speedup vs baseline: 1.3770x; 1.1250x over previous
#include <cuda_runtime.h>
#include <cuda_bf16.h>
#include <math.h>
#include <cstdint>

#define TTOT 131072
#define SCALE 0.17677669529663687f
#define GN_N 1048576.0f

__device__ __forceinline__ void mma16816(float* d, const uint32_t* a, const uint32_t* b) {
    asm volatile("mma.sync.aligned.m16n8k16.row.col.f32.bf16.bf16.f32 "
        "{%0,%1,%2,%3}, {%4,%5,%6,%7}, {%8,%9}, {%0,%1,%2,%3};"
        : "+f"(d[0]), "+f"(d[1]), "+f"(d[2]), "+f"(d[3])
        : "r"(a[0]), "r"(a[1]), "r"(a[2]), "r"(a[3]), "r"(b[0]), "r"(b[1]));
}
__device__ __forceinline__ void ldsm4(uint32_t& r0, uint32_t& r1, uint32_t& r2, uint32_t& r3,
                                      uint32_t addr) {
    asm volatile("ldmatrix.sync.aligned.m8n8.x4.shared.b16 {%0,%1,%2,%3}, [%4];"
                 : "=r"(r0), "=r"(r1), "=r"(r2), "=r"(r3) : "r"(addr));
}
__device__ __forceinline__ uint32_t smem_u32(const void* p) {
    uint32_t a;
    asm("{ .reg .u64 t; cvta.to.shared.u64 t, %1; cvt.u32.u64 %0, t; }" : "=r"(a) : "l"(p));
    return a;
}
__device__ __forceinline__ float bf2f(__nv_bfloat16 h) { return __bfloat162float(h); }

#define CP_A16(d, s) asm volatile("cp.async.cg.shared.global [%0], [%1], 16;" :: "r"(d), "l"(s) : "memory")
#define CP_A16Z(d, s, sz) asm volatile("cp.async.cg.shared.global [%0], [%1], 16, %2;" :: "r"(d), "l"(s), "r"(sz) : "memory")
#define CP_COMMIT()  asm volatile("cp.async.commit_group;" ::: "memory")
#define CP_WAIT1()   asm volatile("cp.async.wait_group 1;" ::: "memory")

// ---------------- scratch ----------------
__device__ __nv_bfloat16 g_xh [(size_t)TTOT*256];
__device__ __nv_bfloat16 g_xl [(size_t)TTOT*256];
__device__ __nv_bfloat16 g_kh [(size_t)TTOT*256];
__device__ __nv_bfloat16 g_kl [(size_t)TTOT*256];
__device__ __nv_bfloat16 g_qah[(size_t)TTOT*256];
__device__ __nv_bfloat16 g_qal[(size_t)TTOT*256];
__device__ __nv_bfloat16 g_kah[(size_t)TTOT*256];
__device__ __nv_bfloat16 g_kal[(size_t)TTOT*256];
__device__ __nv_bfloat16 g_vh [(size_t)TTOT*256];
__device__ __nv_bfloat16 g_vl [(size_t)TTOT*256];
__device__ __nv_bfloat16 g_atth[(size_t)TTOT*256];
__device__ __nv_bfloat16 g_attl[(size_t)TTOT*256];
__device__ __nv_bfloat16 g_uphi[(size_t)TTOT*64];
__device__ __nv_bfloat16 g_uplo[(size_t)TTOT*64];
__device__ __nv_bfloat16 g_ulsh[(size_t)TTOT*64];
__device__ __nv_bfloat16 g_ulsl[(size_t)TTOT*64];
__device__ float g_q  [(size_t)TTOT*256];
__device__ float g_y1 [(size_t)TTOT*256];
__device__ float g_y2 [(size_t)TTOT*192];
__device__ __nv_bfloat16 g_bqh  [768*256];
__device__ __nv_bfloat16 g_bql  [768*256];
__device__ __nv_bfloat16 g_bouth[256*256];
__device__ __nv_bfloat16 g_boutl[256*256];
__device__ __nv_bfloat16 g_bsqh [128*256];
__device__ __nv_bfloat16 g_bsql [128*256];
__device__ __nv_bfloat16 g_bp2h [256*64];
__device__ __nv_bfloat16 g_bp2l [256*64];
__device__ __nv_bfloat16 g_bcvh [2*128*352];
__device__ __nv_bfloat16 g_bcvl [2*128*352];
__device__ float g_gnstats[2*16*2];
__device__ float g_pool[2*512];
__device__ float g_misc[4];

// ---------------- small utilities ----------------
__global__ void zero_small() {
    int i = blockIdx.x*256 + threadIdx.x;
    if (i < 1024) g_pool[i] = 0.f;
    if (i < 64)   g_gnstats[i] = 0.f;
}
__global__ void sum_gnw(const float* __restrict__ gn_w) {
    __shared__ float sh[256];
    sh[threadIdx.x] = gn_w[threadIdx.x];
    __syncthreads();
    for (int st = 128; st > 0; st >>= 1) {
        if (threadIdx.x < st) sh[threadIdx.x] += sh[threadIdx.x + st];
        __syncthreads();
    }
    if (threadIdx.x == 0) g_misc[0] = sh[0];
}
__global__ void prep_bw(const float* __restrict__ w,
                        __nv_bfloat16* __restrict__ dh, __nv_bfloat16* __restrict__ dl, int total) {
    int i = blockIdx.x*256 + threadIdx.x;
    if (i >= total) return;
    float v = w[i];
    __nv_bfloat16 h = __float2bfloat16(v);
    dh[i] = h;
    dl[i] = __float2bfloat16(v - bf2f(h));
}
__global__ void prep_bsq(const float* __restrict__ sq1, const float* __restrict__ sq2) {
    int i = blockIdx.x*256 + threadIdx.x;
    if (i >= 128*256) return;
    int n = i >> 8, k = i & 255;
    float w = 0.f;
    if (n < 64)  { if (k < 128)  w = sq1[n*128 + k]; }
    else         { if (k >= 128) w = sq2[(n-64)*128 + (k-128)]; }
    __nv_bfloat16 h = __float2bfloat16(w);
    g_bsqh[i] = h;
    g_bsql[i] = __float2bfloat16(w - bf2f(h));
}
__global__ void prep_bp2(const float* __restrict__ pwc2) {
    int i = blockIdx.x*256 + threadIdx.x;
    if (i >= 256*64) return;
    int n = i >> 6, k = i & 63;
    float w = (n < 192) ? pwc2[n*64 + k] : 0.f;
    __nv_bfloat16 h = __float2bfloat16(w);
    g_bp2h[i] = h;
    g_bp2l[i] = __float2bfloat16(w - bf2f(h));
}
__global__ void prep_bcv(const float* __restrict__ gwc, const float* __restrict__ pwc1) {
    int i = blockIdx.x*256 + threadIdx.x;
    if (i >= 2*128*352) return;
    int z = i / (128*352), r = i % (128*352);
    int n = r / 352, k = r % 352;
    int c = z*128 + n;
    float w = (k < 288) ? gwc[c*288 + (k & 31)*9 + (k >> 5)] : pwc1[c*64 + (k - 288)];
    __nv_bfloat16 h = __float2bfloat16(w);
    g_bcvh[i] = h;
    g_bcvl[i] = __float2bfloat16(w - bf2f(h));
}

// ---------------- roll + split x ----------------
__global__ __launch_bounds__(256) void xsplit(const float* __restrict__ x) {
    __shared__ float s[256][33];
    int bid = blockIdx.x;
    int b = bid >> 11, rem = bid & 2047;
    int hr = rem >> 3, w0 = (rem & 7) << 5;
    int tid = threadIdx.x, wid = tid >> 5, lane = tid & 31;
    int hs = ((hr + 4) & 255) << 8;
    for (int i = 0; i < 32; i++) {
        int idx = (i << 8) + tid;
        int c = idx >> 5, wp = idx & 31;
        s[c][wp] = x[(size_t)((b << 8) + c)*65536 + hs + ((w0 + wp + 4) & 255)];
    }
    __syncthreads();
    size_t t = (size_t)(b << 16) + (hr << 8) + w0 + lane;
    int c0 = wid << 5;
    for (int j = 0; j < 32; j += 8) {
        __nv_bfloat16 hv[8], lv[8];
#pragma unroll
        for (int e = 0; e < 8; e++) {
            float a = s[c0 + j + e][lane];
            hv[e] = __float2bfloat16(a);
            lv[e] = __float2bfloat16(a - bf2f(hv[e]));
        }
        *(uint4*)&g_xh[t*256 + c0 + j] = *(uint4*)hv;
        *(uint4*)&g_xl[t*256 + c0 + j] = *(uint4*)lv;
    }
}

// ---------------- epilogues ----------------
struct EQKVt {
    static constexpr bool HAS_POOL = false;
    const float* bias;
    __device__ void st2(int m, int n, int z, float v0, float v1) const {
        v0 += bias[n]; v1 += bias[n+1];
        if (n < 256) {
            *(float2*)&g_q[(size_t)m*256 + n] = make_float2(v0, v1);
        } else if (n < 512) {
            int c = n - 256;
            __nv_bfloat16 h0 = __float2bfloat16(v0), h1 = __float2bfloat16(v1);
            *(__nv_bfloat162*)&g_kh[(size_t)m*256 + c] = __halves2bfloat162(h0, h1);
            *(__nv_bfloat162*)&g_kl[(size_t)m*256 + c] = __halves2bfloat162(
                __float2bfloat16(v0 - bf2f(h0)), __float2bfloat16(v1 - bf2f(h1)));
        } else {
            int c = n - 512;
            __nv_bfloat16 h0 = __float2bfloat16(v0), h1 = __float2bfloat16(v1);
            *(__nv_bfloat162*)&g_vh[(size_t)m*256 + c] = __halves2bfloat162(h0, h1);
            *(__nv_bfloat162*)&g_vl[(size_t)m*256 + c] = __halves2bfloat162(
                __float2bfloat16(v0 - bf2f(h0)), __float2bfloat16(v1 - bf2f(h1)));
        }
    }
    __device__ int pslot(int n, int b) const { return -1; }
};
struct ESQ {
    static constexpr bool HAS_POOL = true;
    __device__ void st2(int m, int n, int z, float v0, float v1) const {
        __nv_bfloat16 h0 = __float2bfloat16(v0), h1 = __float2bfloat16(v1);
        __nv_bfloat16 l0 = __float2bfloat16(v0 - bf2f(h0)), l1 = __float2bfloat16(v1 - bf2f(h1));
        if (n < 64) {
            *(__nv_bfloat162*)&g_uphi[(size_t)m*64 + n] = __halves2bfloat162(h0, h1);
            *(__nv_bfloat162*)&g_uplo[(size_t)m*64 + n] = __halves2bfloat162(l0, l1);
        } else {
            int nl = n - 64;
            *(__nv_bfloat162*)&g_ulsh[(size_t)m*64 + nl] = __halves2bfloat162(h0, h1);
            *(__nv_bfloat162*)&g_ulsl[(size_t)m*64 + nl] = __halves2bfloat162(l0, l1);
        }
    }
    __device__ int pslot(int n, int b) const { return n >= 64 ? (b << 9) + 448 + (n - 64) : -1; }
};
struct EY2h {
    static constexpr bool HAS_POOL = true;
    __device__ void st2(int m, int n, int z, float v0, float v1) const {
        if (n < 192) *(float2*)&g_y2[(size_t)m*192 + n] = make_float2(v0, v1);
    }
    __device__ int pslot(int n, int b) const { return n < 192 ? (b << 9) + 256 + n : -1; }
};

// ---------------- dedup split HMMA GEMM (+ optional fused pool) ----------------
template<class EF>
__global__ __launch_bounds__(256, 2) void hgemmA(const __nv_bfloat16* __restrict__ Ah_,
                                                 const __nv_bfloat16* __restrict__ Al_, int lda,
                                                 const __nv_bfloat16* __restrict__ Bh_,
                                                 const __nv_bfloat16* __restrict__ Bl_, int ldb,
                                                 int nk, EF ef) {
    extern __shared__ __nv_bfloat16 sm[];
    int tid = threadIdx.x, lane = tid & 31, wid = tid >> 5;
    int m0 = blockIdx.y << 7, n0 = blockIdx.x << 7;
    uint32_t sbase = smem_u32(sm);
    int wm = (wid & 3) << 5, wn = (wid >> 2) << 6;
    int gid = lane >> 2, tig = lane & 3;
    int lr = lane & 7, lh = (lane >> 3) & 1, lk = lane >> 4;
    uint32_t offA[2];
#pragma unroll
    for (int mf = 0; mf < 2; mf++)
        offA[mf] = (uint32_t)(((wm + (mf << 4) + lr + lh*8)*24 + lk*8) << 1);
    int lq = lane >> 3;
    uint32_t offB[4];
#pragma unroll
    for (int p = 0; p < 4; p++)
        offB[p] = (uint32_t)(((wn + (p << 4) + lr + (lq >> 1)*8)*24 + (lq & 1)*8) << 1);

    float acc[2][8][4];
#pragma unroll
    for (int mf = 0; mf < 2; mf++)
#pragma unroll
        for (int nf = 0; nf < 8; nf++)
#pragma unroll
            for (int e = 0; e < 4; e++) acc[mf][nf][e] = 0.f;

    auto prefetch = [&](int ch, int s) {
        int k0 = ch << 5;
#pragma unroll
        for (int i = 0; i < 2; i++) {
            int idx = (i << 8) + tid;
            int r = idx >> 2, c4 = idx & 3;
            int g = c4 >> 1, ke = c4 & 1;
            uint32_t da = sbase + (uint32_t)((s*24576 + (g*128 + r)*24 + ke*8) << 1);
            size_t asrc = (size_t)(m0 + r)*lda + k0 + (c4 << 3);
            size_t bsrc = (size_t)(n0 + r)*ldb + k0 + (c4 << 3);
            CP_A16(da,          Ah_ + asrc);
            CP_A16(da + 12288,  Al_ + asrc);
            CP_A16(da + 24576,  Bh_ + bsrc);
            CP_A16(da + 36864,  Bl_ + bsrc);
        }
        CP_COMMIT();
    };
    prefetch(0, 0);
    for (int ch = 0; ch < nk; ch++) {
        if (ch + 1 < nk) prefetch(ch + 1, (ch + 1) & 1);
        else CP_COMMIT();
        CP_WAIT1();
        __syncthreads();
        uint32_t stb = sbase + (uint32_t)((ch & 1)*49152);
#pragma unroll
        for (int g = 0; g < 2; g++) {
            uint32_t gb = stb + (uint32_t)(g*6144);
            uint32_t a[2][4], b[8][2];
            ldsm4(b[0][0], b[0][1], b[1][0], b[1][1], gb + 24576 + offB[0]);
            ldsm4(b[2][0], b[2][1], b[3][0], b[3][1], gb + 24576 + offB[1]);
            ldsm4(b[4][0], b[4][1], b[5][0], b[5][1], gb + 24576 + offB[2]);
            ldsm4(b[6][0], b[6][1], b[7][0], b[7][1], gb + 24576 + offB[3]);
            ldsm4(a[0][0], a[0][1], a[0][2], a[0][3], gb + offA[0]);
            ldsm4(a[1][0], a[1][1], a[1][2], a[1][3], gb + offA[1]);
#pragma unroll
            for (int mf = 0; mf < 2; mf++)
#pragma unroll
                for (int nf = 0; nf < 8; nf++)
                    mma16816(acc[mf][nf], a[mf], b[nf]);
            ldsm4(a[0][0], a[0][1], a[0][2], a[0][3], gb + 12288 + offA[0]);
            ldsm4(a[1][0], a[1][1], a[1][2], a[1][3], gb + 12288 + offA[1]);
#pragma unroll
            for (int mf = 0; mf < 2; mf++)
#pragma unroll
                for (int nf = 0; nf < 8; nf++)
                    mma16816(acc[mf][nf], a[mf], b[nf]);
            ldsm4(b[0][0], b[0][1], b[1][0], b[1][1], gb + 36864 + offB[0]);
            ldsm4(b[2][0], b[2][1], b[3][0], b[3][1], gb + 36864 + offB[1]);
            ldsm4(b[4][0], b[4][1], b[5][0], b[5][1], gb + 36864 + offB[2]);
            ldsm4(b[6][0], b[6][1], b[7][0], b[7][1], gb + 36864 + offB[3]);
            ldsm4(a[0][0], a[0][1], a[0][2], a[0][3], gb + offA[0]);
            ldsm4(a[1][0], a[1][1], a[1][2], a[1][3], gb + offA[1]);
#pragma unroll
            for (int mf = 0; mf < 2; mf++)
#pragma unroll
                for (int nf = 0; nf < 8; nf++)
                    mma16816(acc[mf][nf], a[mf], b[nf]);
        }
        __syncthreads();
    }
#pragma unroll
    for (int mf = 0; mf < 2; mf++) {
        int row0 = m0 + wm + (mf << 4) + gid;
#pragma unroll
        for (int nf = 0; nf < 8; nf++) {
            int col = n0 + wn + (nf << 3) + (tig << 1);
            ef.st2(row0,     col, 0, acc[mf][nf][0], acc[mf][nf][1]);
            ef.st2(row0 + 8, col, 0, acc[mf][nf][2], acc[mf][nf][3]);
        }
    }
    if (EF::HAS_POOL) {
        float* red = (float*)sm;
        int contrib = ((wid & 3) << 3) + gid;
#pragma unroll
        for (int nf = 0; nf < 8; nf++)
#pragma unroll
            for (int j = 0; j < 2; j++) {
                float p = acc[0][nf][j] + acc[0][nf][j+2] + acc[1][nf][j] + acc[1][nf][j+2];
                red[(wn + (nf << 3) + (tig << 1) + j)*32 + contrib] = p;
            }
        __syncthreads();
        if (tid < 128) {
            float s = 0.f;
#pragma unroll
            for (int c2 = 0; c2 < 32; c2++) s += red[tid*32 + c2];
            int slot = ef.pslot(n0 + tid, m0 >> 16);
            if (slot >= 0) atomicAdd(&g_pool[slot], s);
        }
    }
}

// ---------------- out-projection GEMM with fused NCHW roll-scatter ----------------
__global__ __launch_bounds__(256, 2) void hgemmO(const __nv_bfloat16* __restrict__ Ah_,
                                                 const __nv_bfloat16* __restrict__ Al_,
                                                 const __nv_bfloat16* __restrict__ Bh_,
                                                 const __nv_bfloat16* __restrict__ Bl_,
                                                 const float* __restrict__ bias,
                                                 float* __restrict__ out) {
    extern __shared__ __nv_bfloat16 sm[];
    int tid = threadIdx.x, lane = tid & 31, wid = tid >> 5;
    int m0 = blockIdx.y << 7, n0 = blockIdx.x << 7;
    uint32_t sbase = smem_u32(sm);
    int wm = (wid & 3) << 5, wn = (wid >> 2) << 6;
    int gid = lane >> 2, tig = lane & 3;
    int lr = lane & 7, lh = (lane >> 3) & 1, lk = lane >> 4;
    uint32_t offA[2];
#pragma unroll
    for (int mf = 0; mf < 2; mf++)
        offA[mf] = (uint32_t)(((wm + (mf << 4) + lr + lh*8)*24 + lk*8) << 1);
    int lq = lane >> 3;
    uint32_t offB[4];
#pragma unroll
    for (int p = 0; p < 4; p++)
        offB[p] = (uint32_t)(((wn + (p << 4) + lr + (lq >> 1)*8)*24 + (lq & 1)*8) << 1);

    float acc[2][8][4];
#pragma unroll
    for (int mf = 0; mf < 2; mf++)
#pragma unroll
        for (int nf = 0; nf < 8; nf++)
#pragma unroll
            for (int e = 0; e < 4; e++) acc[mf][nf][e] = 0.f;

    auto prefetch = [&](int ch, int s) {
        int k0 = ch << 5;
#pragma unroll
        for (int i = 0; i < 2; i++) {
            int idx = (i << 8) + tid;
            int r = idx >> 2, c4 = idx & 3;
            int g = c4 >> 1, ke = c4 & 1;
            uint32_t da = sbase + (uint32_t)((s*24576 + (g*128 + r)*24 + ke*8) << 1);
            size_t asrc = (size_t)(m0 + r)*256 + k0 + (c4 << 3);
            size_t bsrc = (size_t)(n0 + r)*256 + k0 + (c4 << 3);
            CP_A16(da,          Ah_ + asrc);
            CP_A16(da + 12288,  Al_ + asrc);
            CP_A16(da + 24576,  Bh_ + bsrc);
            CP_A16(da + 36864,  Bl_ + bsrc);
        }
        CP_COMMIT();
    };
    prefetch(0, 0);
    for (int ch = 0; ch < 8; ch++) {
        if (ch + 1 < 8) prefetch(ch + 1, (ch + 1) & 1);
        else CP_COMMIT();
        CP_WAIT1();
        __syncthreads();
        uint32_t stb = sbase + (uint32_t)((ch & 1)*49152);
#pragma unroll
        for (int g = 0; g < 2; g++) {
            uint32_t gb = stb + (uint32_t)(g*6144);
            uint32_t a[2][4], b[8][2];
            ldsm4(b[0][0], b[0][1], b[1][0], b[1][1], gb + 24576 + offB[0]);
            ldsm4(b[2][0], b[2][1], b[3][0], b[3][1], gb + 24576 + offB[1]);
            ldsm4(b[4][0], b[4][1], b[5][0], b[5][1], gb + 24576 + offB[2]);
            ldsm4(b[6][0], b[6][1], b[7][0], b[7][1], gb + 24576 + offB[3]);
            ldsm4(a[0][0], a[0][1], a[0][2], a[0][3], gb + offA[0]);
            ldsm4(a[1][0], a[1][1], a[1][2], a[1][3], gb + offA[1]);
#pragma unroll
            for (int mf = 0; mf < 2; mf++)
#pragma unroll
                for (int nf = 0; nf < 8; nf++)
                    mma16816(acc[mf][nf], a[mf], b[nf]);
            ldsm4(a[0][0], a[0][1], a[0][2], a[0][3], gb + 12288 + offA[0]);
            ldsm4(a[1][0], a[1][1], a[1][2], a[1][3], gb + 12288 + offA[1]);
#pragma unroll
            for (int mf = 0; mf < 2; mf++)
#pragma unroll
                for (int nf = 0; nf < 8; nf++)
                    mma16816(acc[mf][nf], a[mf], b[nf]);
            ldsm4(b[0][0], b[0][1], b[1][0], b[1][1], gb + 36864 + offB[0]);
            ldsm4(b[2][0], b[2][1], b[3][0], b[3][1], gb + 36864 + offB[1]);
            ldsm4(b[4][0], b[4][1], b[5][0], b[5][1], gb + 36864 + offB[2]);
            ldsm4(b[6][0], b[6][1], b[7][0], b[7][1], gb + 36864 + offB[3]);
            ldsm4(a[0][0], a[0][1], a[0][2], a[0][3], gb + offA[0]);
            ldsm4(a[1][0], a[1][1], a[1][2], a[1][3], gb + offA[1]);
#pragma unroll
            for (int mf = 0; mf < 2; mf++)
#pragma unroll
                for (int nf = 0; nf < 8; nf++)
                    mma16816(acc[mf][nf], a[mf], b[nf]);
        }
        __syncthreads();
    }
    // staged NCHW roll-scatter: 4 chunks of 32 rows
    const int SP = 132;
    float* stage = (float*)sm;
#pragma unroll
    for (int chunk = 0; chunk < 4; chunk++) {
#pragma unroll
        for (int mf = 0; mf < 2; mf++) {
            int r0 = wm + (mf << 4) + gid;
#pragma unroll
            for (int rr = 0; rr < 2; rr++) {
                int r = r0 + (rr << 3);
                if ((r >> 5) == chunk) {
                    int rl = r & 31;
#pragma unroll
                    for (int nf = 0; nf < 8; nf++) {
                        int cl = wn + (nf << 3) + (tig << 1);
                        stage[rl*SP + cl]     = acc[mf][nf][rr*2]     + bias[n0 + cl];
                        stage[rl*SP + cl + 1] = acc[mf][nf][rr*2 + 1] + bias[n0 + cl + 1];
                    }
                }
            }
        }
        __syncthreads();
        int m = m0 + (chunk << 5) + lane;
        int b = m >> 16, pixi = m & 65535;
        int hr = pixi >> 8, wr = pixi & 255;
        size_t pbase = (size_t)(((hr + 4) & 255) << 8) + ((wr + 4) & 255);
        for (int nl = wid; nl < 128; nl += 8)
            out[(size_t)((b << 8) + n0 + nl)*65536 + pbase] = stage[lane*SP + nl];
        __syncthreads();
    }
}

// ---------------- conv GEMM: dedup split + async gather prefetch + fused pool ----------------
__global__ __launch_bounds__(256, 2) void hgemmC(const __nv_bfloat16* __restrict__ Bh_,
                                                 const __nv_bfloat16* __restrict__ Bl_,
                                                 const float* __restrict__ bias) {
    extern __shared__ __nv_bfloat16 sm[];
    int tid = threadIdx.x, lane = tid & 31, wid = tid >> 5;
    int m0 = blockIdx.y << 7, z = blockIdx.z;
    uint32_t sbase = smem_u32(sm);
    int wm = (wid & 3) << 5, wn = (wid >> 2) << 6;
    int gid = lane >> 2, tig = lane & 3;
    int lr = lane & 7, lh = (lane >> 3) & 1, lk = lane >> 4;
    uint32_t offA[2];
#pragma unroll
    for (int mf = 0; mf < 2; mf++)
        offA[mf] = (uint32_t)(((wm + (mf << 4) + lr + lh*8)*24 + lk*8) << 1);
    int lq = lane >> 3;
    uint32_t offB[4];
#pragma unroll
    for (int p = 0; p < 4; p++)
        offB[p] = (uint32_t)(((wn + (p << 4) + lr + (lq >> 1)*8)*24 + (lq & 1)*8) << 1);

    float acc[2][8][4];
#pragma unroll
    for (int mf = 0; mf < 2; mf++)
#pragma unroll
        for (int nf = 0; nf < 8; nf++)
#pragma unroll
            for (int e = 0; e < 4; e++) acc[mf][nf][e] = 0.f;

    const __nv_bfloat16* Bzh = Bh_ + (size_t)z*128*352;
    const __nv_bfloat16* Bzl = Bl_ + (size_t)z*128*352;

    auto prefetch = [&](int ch, int s) {
        int k0 = ch << 5;
#pragma unroll
        for (int i = 0; i < 2; i++) {
            int idx = (i << 8) + tid;
            int r = idx >> 2, c4 = idx & 3;
            int g = c4 >> 1, ke = c4 & 1;
            uint32_t da = sbase + (uint32_t)((s*24576 + (g*128 + r)*24 + ke*8) << 1);
            int k = k0 + (c4 << 3);
            int m = m0 + r;
            size_t aoff; int sz = 16;
            if (k < 288) {
                int tap = k >> 5, kl0 = k & 31;
                int dy = tap/3 - 1, dx = tap - (tap/3)*3 - 1;
                int b = m >> 16;
                int hr = ((m >> 8) & 255) + dy, wr = (m & 255) + dx;
                if ((unsigned)hr > 255u || (unsigned)wr > 255u) sz = 0;
                aoff = (size_t)((b << 16) + ((hr & 255) << 8) + (wr & 255))*64 + (z << 5) + kl0;
            } else {
                aoff = (size_t)m*64 + (k - 288);
            }
            CP_A16Z(da,         g_uphi + aoff, sz);
            CP_A16Z(da + 12288, g_uplo + aoff, sz);
            size_t boff = (size_t)r*352 + k;
            CP_A16(da + 24576, Bzh + boff);
            CP_A16(da + 36864, Bzl + boff);
        }
        CP_COMMIT();
    };
    prefetch(0, 0);
    for (int ch = 0; ch < 11; ch++) {
        if (ch + 1 < 11) prefetch(ch + 1, (ch + 1) & 1);
        else CP_COMMIT();
        CP_WAIT1();
        __syncthreads();
        uint32_t stb = sbase + (uint32_t)((ch & 1)*49152);
#pragma unroll
        for (int g = 0; g < 2; g++) {
            uint32_t gb = stb + (uint32_t)(g*6144);
            uint32_t a[2][4], b[8][2];
            ldsm4(b[0][0], b[0][1], b[1][0], b[1][1], gb + 24576 + offB[0]);
            ldsm4(b[2][0], b[2][1], b[3][0], b[3][1], gb + 24576 + offB[1]);
            ldsm4(b[4][0], b[4][1], b[5][0], b[5][1], gb + 24576 + offB[2]);
            ldsm4(b[6][0], b[6][1], b[7][0], b[7][1], gb + 24576 + offB[3]);
            ldsm4(a[0][0], a[0][1], a[0][2], a[0][3], gb + offA[0]);
            ldsm4(a[1][0], a[1][1], a[1][2], a[1][3], gb + offA[1]);
#pragma unroll
            for (int mf = 0; mf < 2; mf++)
#pragma unroll
                for (int nf = 0; nf < 8; nf++)
                    mma16816(acc[mf][nf], a[mf], b[nf]);
            ldsm4(a[0][0], a[0][1], a[0][2], a[0][3], gb + 12288 + offA[0]);
            ldsm4(a[1][0], a[1][1], a[1][2], a[1][3], gb + 12288 + offA[1]);
#pragma unroll
            for (int mf = 0; mf < 2; mf++)
#pragma unroll
                for (int nf = 0; nf < 8; nf++)
                    mma16816(acc[mf][nf], a[mf], b[nf]);
            ldsm4(b[0][0], b[0][1], b[1][0], b[1][1], gb + 36864 + offB[0]);
            ldsm4(b[2][0], b[2][1], b[3][0], b[3][1], gb + 36864 + offB[1]);
            ldsm4(b[4][0], b[4][1], b[5][0], b[5][1], gb + 36864 + offB[2]);
            ldsm4(b[6][0], b[6][1], b[7][0], b[7][1], gb + 36864 + offB[3]);
            ldsm4(a[0][0], a[0][1], a[0][2], a[0][3], gb + offA[0]);
            ldsm4(a[1][0], a[1][1], a[1][2], a[1][3], gb + offA[1]);
#pragma unroll
            for (int mf = 0; mf < 2; mf++)
#pragma unroll
                for (int nf = 0; nf < 8; nf++)
                    mma16816(acc[mf][nf], a[mf], b[nf]);
        }
        __syncthreads();
    }
#pragma unroll
    for (int mf = 0; mf < 2; mf++) {
        int row0 = m0 + wm + (mf << 4) + gid;
#pragma unroll
        for (int nf = 0; nf < 8; nf++) {
            int col = wn + (nf << 3) + (tig << 1);
            int c = (z << 7) + col;
            *(float2*)&g_y1[(size_t)row0*256 + c] =
                make_float2(acc[mf][nf][0] + bias[c], acc[mf][nf][1] + bias[c+1]);
            *(float2*)&g_y1[(size_t)(row0 + 8)*256 + c] =
                make_float2(acc[mf][nf][2] + bias[c], acc[mf][nf][3] + bias[c+1]);
        }
    }
    // fused pool: sum of stored y1 values (bias included per element)
    {
        float* red = (float*)sm;
        int contrib = ((wid & 3) << 3) + gid;
#pragma unroll
        for (int nf = 0; nf < 8; nf++)
#pragma unroll
            for (int j = 0; j < 2; j++) {
                int col = wn + (nf << 3) + (tig << 1) + j;
                float bb = bias[(z << 7) + col];
                float p = acc[0][nf][j] + acc[0][nf][j+2] + acc[1][nf][j] + acc[1][nf][j+2] + 4.f*bb;
                red[col*32 + contrib] = p;
            }
        __syncthreads();
        if (tid < 128) {
            float s = 0.f;
#pragma unroll
            for (int c2 = 0; c2 < 32; c2++) s += red[tid*32 + c2];
            atomicAdd(&g_pool[((m0 >> 16) << 9) + (z << 7) + tid], s);
        }
    }
}

// ---------------- GN stats / SRU / CRU glue ----------------
__global__ void gn_stats() {
    int t0 = blockIdx.x * 512;
    int c = threadIdx.x;
    const float* p = g_q + (size_t)t0*256 + c;
    float s = 0.f, s2 = 0.f;
#pragma unroll 4
    for (int i = 0; i < 512; i++) { float v = p[(size_t)i*256]; s += v; s2 += v*v; }
#pragma unroll
    for (int off = 8; off > 0; off >>= 1) {
        s  += __shfl_down_sync(0xffffffff, s,  off, 16);
        s2 += __shfl_down_sync(0xffffffff, s2, off, 16);
    }
    if ((c & 15) == 0) {
        int b = t0 >> 16, g = c >> 4;
        atomicAdd(&g_gnstats[((b << 4) + g)*2],     s);
        atomicAdd(&g_gnstats[((b << 4) + g)*2 + 1], s2);
    }
}
__global__ void sru_elem(const float* __restrict__ gn_w, const float* __restrict__ gn_b) {
    int i = blockIdx.x*256 + threadIdx.x;
    int t = i >> 7, cp = i & 127;
    int b = t >> 16;
    int c1 = cp, c2 = cp + 128;
    float wsum = g_misc[0];
    int g1 = c1 >> 4, g2 = c2 >> 4;
    float m1 = g_gnstats[((b<<4)+g1)*2] / GN_N;
    float v1 = g_gnstats[((b<<4)+g1)*2+1] / GN_N - m1*m1;
    float m2 = g_gnstats[((b<<4)+g2)*2] / GN_N;
    float v2 = g_gnstats[((b<<4)+g2)*2+1] / GN_N - m2*m2;
    float w1c = gn_w[c1], w2c = gn_w[c2];
    float A1 = rsqrtf(v1 + 1e-5f)*w1c, B1 = gn_b[c1] - m1*rsqrtf(v1 + 1e-5f)*w1c;
    float A2 = rsqrtf(v2 + 1e-5f)*w2c, B2 = gn_b[c2] - m2*rsqrtf(v2 + 1e-5f)*w2c;
    float x1 = g_q[(size_t)t*256 + c1], x2 = g_q[(size_t)t*256 + c2];
    float rw1 = 1.0f/(1.0f + expf(-(x1*A1 + B1)*(w1c/wsum)));
    float rw2 = 1.0f/(1.0f + expf(-(x2*A2 + B2)*(w2c/wsum)));
    float w11 = rw1 > 0.5f ? 1.0f : rw1, w21 = rw1 > 0.5f ? 0.0f : rw1;
    float w12 = rw2 > 0.5f ? 1.0f : rw2, w22 = rw2 > 0.5f ? 0.0f : rw2;
    float o1 = w11*x1 + w22*x2;
    float o2 = w12*x2 + w21*x1;
    __nv_bfloat16 h1 = __float2bfloat16(o1), h2 = __float2bfloat16(o2);
    g_qah[(size_t)t*256 + c1] = h1;
    g_qal[(size_t)t*256 + c1] = __float2bfloat16(o1 - bf2f(h1));
    g_qah[(size_t)t*256 + c2] = h2;
    g_qal[(size_t)t*256 + c2] = __float2bfloat16(o2 - bf2f(h2));
}
__global__ void softmax512() {
    int b = blockIdx.x, t = threadIdx.x;
    __shared__ float sh[512];
    float v = g_pool[(b << 9) + t] * (1.0f/65536.0f);
    sh[t] = v;
    __syncthreads();
    for (int st = 256; st > 0; st >>= 1) { if (t < st) sh[t] = fmaxf(sh[t], sh[t + st]); __syncthreads(); }
    float mx = sh[0];
    __syncthreads();
    float e = expf(v - mx);
    sh[t] = e;
    __syncthreads();
    for (int st = 256; st > 0; st >>= 1) { if (t < st) sh[t] += sh[t + st]; __syncthreads(); }
    float sum = sh[0];
    __syncthreads();
    g_pool[(b << 9) + t] = e / sum;
}
__global__ void cru_combine() {
    int i = blockIdx.x*256 + threadIdx.x;
    int t = i >> 8, c = i & 255;
    int b = t >> 16;
    float y1 = g_y1[i];
    float y2v;
    if (c < 192) y2v = g_y2[(size_t)t*192 + c];
    else {
        int nl = c - 192;
        y2v = bf2f(g_ulsh[(size_t)t*64 + nl]) + bf2f(g_ulsl[(size_t)t*64 + nl]);
    }
    float o = g_pool[(b << 9) + c]*y1 + g_pool[(b << 9) + 256 + c]*y2v;
    __nv_bfloat16 h = __float2bfloat16(o);
    g_kah[(size_t)t*256 + c] = h;
    g_kal[(size_t)t*256 + c] = __float2bfloat16(o - bf2f(h));
}

// ---------------- HMMA windowed attention (round-12, unchanged) ----------------
__global__ __launch_bounds__(128) void attn_mma(const float* __restrict__ rel_pos) {
    extern __shared__ __nv_bfloat16 smb[];
    float* rps = (float*)(smb + 49152);
    int tid = threadIdx.x, lane = tid & 31, wid = tid >> 5;
    int win = blockIdx.x, hg = blockIdx.y, b = blockIdx.z;
    int wy = win >> 5, wx = win & 31;
    int t0 = (b << 16) + (wy << 11) + (wx << 3);
    for (int i = 0; i < 8; i++) {
        int idx = (i << 7) + tid;
        int hh = idx >> 8, r = idx & 255;
        int tok = r >> 2, c8 = (r & 3) << 3;
        int token = t0 + ((tok >> 3) << 8) + (tok & 7);
        size_t src = (size_t)token*256 + (((hg << 2) + hh) << 5) + c8;
        int dst = hh*12288 + ((c8 >> 4)*64 + tok)*24 + (c8 & 15);
        *(uint4*)&smb[dst]        = *(const uint4*)&g_kah[src];
        *(uint4*)&smb[dst + 3072] = *(const uint4*)&g_kal[src];
    }
    for (int i = 0; i < 32; i++) {
        int idx = (i << 7) + tid;
        int hh = idx >> 10, r = idx & 1023;
        int tok = r >> 4, dp = (r & 15) << 1;
        int token = t0 + ((tok >> 3) << 8) + (tok & 7);
        size_t src = (size_t)token*256 + (((hg << 2) + hh) << 5) + dp;
        __nv_bfloat162 vh = *(const __nv_bfloat162*)&g_vh[src];
        __nv_bfloat162 vl = *(const __nv_bfloat162*)&g_vl[src];
        int base = hh*12288 + 6144 + (tok >> 4)*768 + (tok & 15);
        smb[base + dp*24]            = vh.x;
        smb[base + (dp+1)*24]        = vh.y;
        smb[base + 3072 + dp*24]     = vl.x;
        smb[base + 3072 + (dp+1)*24] = vl.y;
    }
    for (int i = tid; i < 900; i += 128) {
        int hh = i / 225, r = i - hh*225;
        rps[i] = rel_pos[(((hg << 2) + hh))*225 + r];
    }
    __syncthreads();

    int hh = wid;
    uint32_t tb = smem_u32(smb) + (uint32_t)(hh*24576);
    uint32_t khb = tb, klb = tb + 6144, vhb = tb + 12288, vlb = tb + 18432;
    const float* rp = rps + hh*225;
    int gid = lane >> 2, tig = lane & 3;
    int lr = lane & 7, lq = lane >> 3;
    uint32_t offK[4], offV[2];
#pragma unroll
    for (int p = 0; p < 4; p++)
        offK[p] = (uint32_t)((((p << 4) + lr + (lq >> 1)*8)*24 + (lq & 1)*8) << 1);
#pragma unroll
    for (int p = 0; p < 2; p++)
        offV[p] = (uint32_t)((((p << 4) + lr + (lq >> 1)*8)*24 + (lq & 1)*8) << 1);
    bool lrm = wy == 31, lcm = wx == 31;
    int hbc = ((hg << 2) + hh) << 5;

    for (int half = 0; half < 2; half++) {
        int rbase = half << 5;
        uint32_t qh[2][2][4], ql[2][2][4];
#pragma unroll
        for (int mt = 0; mt < 2; mt++) {
            int r0 = rbase + (mt << 4) + gid;
            int tok0 = t0 + ((r0 >> 3) << 8) + (r0 & 7);
            int r1 = r0 + 8;
            int tok1 = t0 + ((r1 >> 3) << 8) + (r1 & 7);
#pragma unroll
            for (int kf = 0; kf < 2; kf++) {
                int kc = hbc + (kf << 4) + (tig << 1);
                qh[mt][kf][0] = *(const uint32_t*)&g_qah[(size_t)tok0*256 + kc];
                qh[mt][kf][1] = *(const uint32_t*)&g_qah[(size_t)tok1*256 + kc];
                qh[mt][kf][2] = *(const uint32_t*)&g_qah[(size_t)tok0*256 + kc + 8];
                qh[mt][kf][3] = *(const uint32_t*)&g_qah[(size_t)tok1*256 + kc + 8];
                ql[mt][kf][0] = *(const uint32_t*)&g_qal[(size_t)tok0*256 + kc];
                ql[mt][kf][1] = *(const uint32_t*)&g_qal[(size_t)tok1*256 + kc];
                ql[mt][kf][2] = *(const uint32_t*)&g_qal[(size_t)tok0*256 + kc + 8];
                ql[mt][kf][3] = *(const uint32_t*)&g_qal[(size_t)tok1*256 + kc + 8];
            }
        }
        float sacc[2][8][4];
#pragma unroll
        for (int mt = 0; mt < 2; mt++)
#pragma unroll
            for (int nt = 0; nt < 8; nt++)
#pragma unroll
                for (int e = 0; e < 4; e++) sacc[mt][nt][e] = 0.f;
#pragma unroll
        for (int kg = 0; kg < 2; kg++) {
            uint32_t bk[8][2];
            uint32_t kgb = khb + (uint32_t)(kg*3072);
            ldsm4(bk[0][0], bk[0][1], bk[1][0], bk[1][1], kgb + offK[0]);
            ldsm4(bk[2][0], bk[2][1], bk[3][0], bk[3][1], kgb + offK[1]);
            ldsm4(bk[4][0], bk[4][1], bk[5][0], bk[5][1], kgb + offK[2]);
            ldsm4(bk[6][0], bk[6][1], bk[7][0], bk[7][1], kgb + offK[3]);
#pragma unroll
            for (int mt = 0; mt < 2; mt++)
#pragma unroll
                for (int nt = 0; nt < 8; nt++) {
                    mma16816(sacc[mt][nt], qh[mt][kg], bk[nt]);
                    mma16816(sacc[mt][nt], ql[mt][kg], bk[nt]);
                }
            uint32_t lgb = klb + (uint32_t)(kg*3072);
            ldsm4(bk[0][0], bk[0][1], bk[1][0], bk[1][1], lgb + offK[0]);
            ldsm4(bk[2][0], bk[2][1], bk[3][0], bk[3][1], lgb + offK[1]);
            ldsm4(bk[4][0], bk[4][1], bk[5][0], bk[5][1], lgb + offK[2]);
            ldsm4(bk[6][0], bk[6][1], bk[7][0], bk[7][1], lgb + offK[3]);
#pragma unroll
            for (int mt = 0; mt < 2; mt++)
#pragma unroll
                for (int nt = 0; nt < 8; nt++)
                    mma16816(sacc[mt][nt], qh[mt][kg], bk[nt]);
        }
#pragma unroll
        for (int mt = 0; mt < 2; mt++)
#pragma unroll
            for (int rr = 0; rr < 2; rr++) {
                int row = rbase + (mt << 4) + gid + (rr << 3);
                int ph = row >> 3, pw = row & 7;
                float vv[16];
                float mx = -1e30f;
#pragma unroll
                for (int nt = 0; nt < 8; nt++)
#pragma unroll
                    for (int j = 0; j < 2; j++) {
                        int col = (nt << 3) + (tig << 1) + j;
                        int qy = col >> 3, qw = col & 7;
                        float v = sacc[mt][nt][rr*2 + j]*SCALE + rp[(ph - qy + 7)*15 + (pw - qw + 7)];
                        if ((lrm && ((ph < 4) != (qy < 4))) || (lcm && ((pw < 4) != (qw < 4)))) v = -1e30f;
                        vv[nt*2 + j] = v;
                        mx = fmaxf(mx, v);
                    }
                mx = fmaxf(mx, __shfl_xor_sync(0xffffffff, mx, 1));
                mx = fmaxf(mx, __shfl_xor_sync(0xffffffff, mx, 2));
                float s = 0.f;
#pragma unroll
                for (int e = 0; e < 16; e++) { vv[e] = expf(vv[e] - mx); s += vv[e]; }
                s += __shfl_xor_sync(0xffffffff, s, 1);
                s += __shfl_xor_sync(0xffffffff, s, 2);
                float inv = 1.0f / s;
#pragma unroll
                for (int nt = 0; nt < 8; nt++)
#pragma unroll
                    for (int j = 0; j < 2; j++)
                        sacc[mt][nt][rr*2 + j] = vv[nt*2 + j]*inv;
            }
        float oacc[2][4][4];
#pragma unroll
        for (int mt = 0; mt < 2; mt++)
#pragma unroll
            for (int nt = 0; nt < 4; nt++)
#pragma unroll
                for (int e = 0; e < 4; e++) oacc[mt][nt][e] = 0.f;
#pragma unroll
        for (int kf = 0; kf < 4; kf++) {
            uint32_t pfh[2][4], pfl[2][4];
#pragma unroll
            for (int mt = 0; mt < 2; mt++) {
#pragma unroll
                for (int e = 0; e < 4; e++) {
                    int nt = 2*kf + (e >> 1);
                    float p0 = sacc[mt][nt][(e & 1)*2];
                    float p1 = sacc[mt][nt][(e & 1)*2 + 1];
                    __nv_bfloat162 h2 = __floats2bfloat162_rn(p0, p1);
                    pfh[mt][e] = *(uint32_t*)&h2;
                    __nv_bfloat162 l2 = __floats2bfloat162_rn(p0 - bf2f(h2.x), p1 - bf2f(h2.y));
                    pfl[mt][e] = *(uint32_t*)&l2;
                }
            }
            uint32_t bv[4][2];
            uint32_t vgb = vhb + (uint32_t)(kf*1536);
            ldsm4(bv[0][0], bv[0][1], bv[1][0], bv[1][1], vgb + offV[0]);
            ldsm4(bv[2][0], bv[2][1], bv[3][0], bv[3][1], vgb + offV[1]);
#pragma unroll
            for (int mt = 0; mt < 2; mt++)
#pragma unroll
                for (int nt = 0; nt < 4; nt++) {
                    mma16816(oacc[mt][nt], pfh[mt], bv[nt]);
                    mma16816(oacc[mt][nt], pfl[mt], bv[nt]);
                }
            uint32_t lgb = vlb + (uint32_t)(kf*1536);
            ldsm4(bv[0][0], bv[0][1], bv[1][0], bv[1][1], lgb + offV[0]);
            ldsm4(bv[2][0], bv[2][1], bv[3][0], bv[3][1], lgb + offV[1]);
#pragma unroll
            for (int mt = 0; mt < 2; mt++)
#pragma unroll
                for (int nt = 0; nt < 4; nt++)
                    mma16816(oacc[mt][nt], pfh[mt], bv[nt]);
        }
#pragma unroll
        for (int mt = 0; mt < 2; mt++) {
            int r0 = rbase + (mt << 4) + gid;
            int tok0 = t0 + ((r0 >> 3) << 8) + (r0 & 7);
            int r1 = r0 + 8;
            int tok1 = t0 + ((r1 >> 3) << 8) + (r1 & 7);
#pragma unroll
            for (int nt = 0; nt < 4; nt++) {
                int c = hbc + (nt << 3) + (tig << 1);
                float a0 = oacc[mt][nt][0], a1 = oacc[mt][nt][1];
                float a2 = oacc[mt][nt][2], a3 = oacc[mt][nt][3];
                __nv_bfloat162 h0 = __floats2bfloat162_rn(a0, a1);
                __nv_bfloat162 h1 = __floats2bfloat162_rn(a2, a3);
                *(__nv_bfloat162*)&g_atth[(size_t)tok0*256 + c] = h0;
                *(__nv_bfloat162*)&g_atth[(size_t)tok1*256 + c] = h1;
                *(__nv_bfloat162*)&g_attl[(size_t)tok0*256 + c] =
                    __floats2bfloat162_rn(a0 - bf2f(h0.x), a1 - bf2f(h0.y));
                *(__nv_bfloat162*)&g_attl[(size_t)tok1*256 + c] =
                    __floats2bfloat162_rn(a2 - bf2f(h1.x), a3 - bf2f(h1.y));
            }
        }
    }
}

// ---------------- launch ----------------
extern "C" void kernel_launch(void* const* d_in, const int* in_sizes, int n_in,
                              void* d_out, int out_size) {
    const float* x      = (const float*)d_in[0];
    const float* w_qkv  = (const float*)d_in[1];
    const float* b_qkv  = (const float*)d_in[2];
    const float* rel_pos= (const float*)d_in[3];
    const float* gn_w   = (const float*)d_in[4];
    const float* gn_b   = (const float*)d_in[5];
    const float* sq1    = (const float*)d_in[6];
    const float* sq2    = (const float*)d_in[7];
    const float* gwc    = (const float*)d_in[8];
    const float* gwc_b  = (const float*)d_in[9];
    const float* pwc1   = (const float*)d_in[10];
    const float* pwc2   = (const float*)d_in[11];
    const float* w_out  = (const float*)d_in[12];
    const float* b_out  = (const float*)d_in[13];
    float* out = (float*)d_out;

    __nv_bfloat16 *p_bqh, *p_bql, *p_bouth, *p_boutl, *p_bsqh, *p_bsql, *p_bp2h, *p_bp2l;
    __nv_bfloat16 *p_xh, *p_xl, *p_kh, *p_kl, *p_atth, *p_attl, *p_ulsh, *p_ulsl;
    __nv_bfloat16 *p_bcvh, *p_bcvl;
    cudaGetSymbolAddress((void**)&p_bqh,   g_bqh);
    cudaGetSymbolAddress((void**)&p_bql,   g_bql);
    cudaGetSymbolAddress((void**)&p_bouth, g_bouth);
    cudaGetSymbolAddress((void**)&p_boutl, g_boutl);
    cudaGetSymbolAddress((void**)&p_bsqh,  g_bsqh);
    cudaGetSymbolAddress((void**)&p_bsql,  g_bsql);
    cudaGetSymbolAddress((void**)&p_bp2h,  g_bp2h);
    cudaGetSymbolAddress((void**)&p_bp2l,  g_bp2l);
    cudaGetSymbolAddress((void**)&p_xh,    g_xh);
    cudaGetSymbolAddress((void**)&p_xl,    g_xl);
    cudaGetSymbolAddress((void**)&p_kh,    g_kh);
    cudaGetSymbolAddress((void**)&p_kl,    g_kl);
    cudaGetSymbolAddress((void**)&p_atth,  g_atth);
    cudaGetSymbolAddress((void**)&p_attl,  g_attl);
    cudaGetSymbolAddress((void**)&p_ulsh,  g_ulsh);
    cudaGetSymbolAddress((void**)&p_ulsl,  g_ulsl);
    cudaGetSymbolAddress((void**)&p_bcvh,  g_bcvh);
    cudaGetSymbolAddress((void**)&p_bcvl,  g_bcvl);

    const int DSM = 98304;
    const int ASM = 49152*2 + 900*4;
    cudaFuncSetAttribute(hgemmA<EQKVt>, cudaFuncAttributeMaxDynamicSharedMemorySize, DSM);
    cudaFuncSetAttribute(hgemmA<ESQ>,   cudaFuncAttributeMaxDynamicSharedMemorySize, DSM);
    cudaFuncSetAttribute(hgemmA<EY2h>,  cudaFuncAttributeMaxDynamicSharedMemorySize, DSM);
    cudaFuncSetAttribute(hgemmO,        cudaFuncAttributeMaxDynamicSharedMemorySize, DSM);
    cudaFuncSetAttribute(hgemmC,        cudaFuncAttributeMaxDynamicSharedMemorySize, DSM);
    cudaFuncSetAttribute(attn_mma,      cudaFuncAttributeMaxDynamicSharedMemorySize, ASM);

    zero_small<<<4, 256>>>();                                              // 0
    prep_bw<<<768, 256>>>(w_qkv, p_bqh, p_bql, 768*256);                   // 1
    xsplit<<<4096, 256>>>(x);                                              // 2
    hgemmA<EQKVt><<<dim3(6, 1024), 256, DSM>>>(p_xh, p_xl, 256,
                                               p_bqh, p_bql, 256, 8, EQKVt{b_qkv}); // 3 (profiled)

    gn_stats<<<256, 256>>>();
    sum_gnw<<<1, 256>>>(gn_w);
    sru_elem<<<65536, 256>>>(gn_w, gn_b);

    prep_bsq<<<128, 256>>>(sq1, sq2);
    hgemmA<ESQ><<<dim3(1, 1024), 256, DSM>>>(p_kh, p_kl, 256, p_bsqh, p_bsql, 256, 8, ESQ{});
    prep_bcv<<<(2*128*352 + 255)/256, 256>>>(gwc, pwc1);
    hgemmC<<<dim3(1, 1024, 2), 256, DSM>>>(p_bcvh, p_bcvl, gwc_b);
    prep_bp2<<<64, 256>>>(pwc2);
    hgemmA<EY2h><<<dim3(2, 1024), 256, DSM>>>(p_ulsh, p_ulsl, 64, p_bp2h, p_bp2l, 64, 2, EY2h{});

    softmax512<<<2, 512>>>();
    cru_combine<<<131072, 256>>>();

    attn_mma<<<dim3(1024, 2, 2), 128, ASM>>>(rel_pos);
    prep_bw<<<256, 256>>>(w_out, p_bouth, p_boutl, 256*256);
    hgemmO<<<dim3(2, 1024), 256, DSM>>>(p_atth, p_attl, p_bouth, p_boutl, b_out, out);
}

// round 15
// speedup vs baseline: 1.4460x; 1.0501x over previous
#include <cuda_runtime.h>
#include <cuda_bf16.h>
#include <math.h>
#include <cstdint>

#define TTOT 131072
#define SCALE 0.17677669529663687f
#define GN_N 1048576.0f

__device__ __forceinline__ void mma16816(float* d, const uint32_t* a, const uint32_t* b) {
    asm volatile("mma.sync.aligned.m16n8k16.row.col.f32.bf16.bf16.f32 "
        "{%0,%1,%2,%3}, {%4,%5,%6,%7}, {%8,%9}, {%0,%1,%2,%3};"
        : "+f"(d[0]), "+f"(d[1]), "+f"(d[2]), "+f"(d[3])
        : "r"(a[0]), "r"(a[1]), "r"(a[2]), "r"(a[3]), "r"(b[0]), "r"(b[1]));
}
__device__ __forceinline__ void ldsm4(uint32_t& r0, uint32_t& r1, uint32_t& r2, uint32_t& r3,
                                      uint32_t addr) {
    asm volatile("ldmatrix.sync.aligned.m8n8.x4.shared.b16 {%0,%1,%2,%3}, [%4];"
                 : "=r"(r0), "=r"(r1), "=r"(r2), "=r"(r3) : "r"(addr));
}
__device__ __forceinline__ uint32_t smem_u32(const void* p) {
    uint32_t a;
    asm("{ .reg .u64 t; cvta.to.shared.u64 t, %1; cvt.u32.u64 %0, t; }" : "=r"(a) : "l"(p));
    return a;
}
__device__ __forceinline__ float bf2f(__nv_bfloat16 h) { return __bfloat162float(h); }

#define CP_A16(d, s) asm volatile("cp.async.cg.shared.global [%0], [%1], 16;" :: "r"(d), "l"(s) : "memory")
#define CP_A16Z(d, s, sz) asm volatile("cp.async.cg.shared.global [%0], [%1], 16, %2;" :: "r"(d), "l"(s), "r"(sz) : "memory")
#define CP_COMMIT()  asm volatile("cp.async.commit_group;" ::: "memory")
#define CP_WAIT1()   asm volatile("cp.async.wait_group 1;" ::: "memory")

// ---------------- scratch ----------------
__device__ __nv_bfloat16 g_xh [(size_t)TTOT*256];
__device__ __nv_bfloat16 g_xl [(size_t)TTOT*256];
__device__ __nv_bfloat16 g_kh [(size_t)TTOT*256];
__device__ __nv_bfloat16 g_kl [(size_t)TTOT*256];
__device__ __nv_bfloat16 g_qah[(size_t)TTOT*256];
__device__ __nv_bfloat16 g_qal[(size_t)TTOT*256];
__device__ __nv_bfloat16 g_vh [(size_t)TTOT*256];
__device__ __nv_bfloat16 g_vl [(size_t)TTOT*256];
__device__ __nv_bfloat16 g_atth[(size_t)TTOT*256];
__device__ __nv_bfloat16 g_attl[(size_t)TTOT*256];
__device__ __nv_bfloat16 g_uphi[(size_t)TTOT*64];
__device__ __nv_bfloat16 g_uplo[(size_t)TTOT*64];
__device__ __nv_bfloat16 g_ulsh[(size_t)TTOT*64];
__device__ __nv_bfloat16 g_ulsl[(size_t)TTOT*64];
__device__ float g_q  [(size_t)TTOT*256];
__device__ float g_y1 [(size_t)TTOT*256];
__device__ float g_y2 [(size_t)TTOT*192];
__device__ __nv_bfloat16 g_bqh  [768*256];
__device__ __nv_bfloat16 g_bql  [768*256];
__device__ __nv_bfloat16 g_bouth[256*256];
__device__ __nv_bfloat16 g_boutl[256*256];
__device__ __nv_bfloat16 g_bsqh [128*256];
__device__ __nv_bfloat16 g_bsql [128*256];
__device__ __nv_bfloat16 g_bp2h [256*64];
__device__ __nv_bfloat16 g_bp2l [256*64];
__device__ __nv_bfloat16 g_bcvh [2*128*352];
__device__ __nv_bfloat16 g_bcvl [2*128*352];
__device__ float g_gnstats[2*16*2];
__device__ float g_pool[2*512];
__device__ float g_misc[4];

// ---------------- small utilities ----------------
__global__ void zero_small() {
    int i = blockIdx.x*256 + threadIdx.x;
    if (i < 1024) g_pool[i] = 0.f;
    if (i < 64)   g_gnstats[i] = 0.f;
}
__global__ void sum_gnw(const float* __restrict__ gn_w) {
    __shared__ float sh[256];
    sh[threadIdx.x] = gn_w[threadIdx.x];
    __syncthreads();
    for (int st = 128; st > 0; st >>= 1) {
        if (threadIdx.x < st) sh[threadIdx.x] += sh[threadIdx.x + st];
        __syncthreads();
    }
    if (threadIdx.x == 0) g_misc[0] = sh[0];
}
__global__ void prep_bw(const float* __restrict__ w,
                        __nv_bfloat16* __restrict__ dh, __nv_bfloat16* __restrict__ dl, int total) {
    int i = blockIdx.x*256 + threadIdx.x;
    if (i >= total) return;
    float v = w[i];
    __nv_bfloat16 h = __float2bfloat16(v);
    dh[i] = h;
    dl[i] = __float2bfloat16(v - bf2f(h));
}
__global__ void prep_bsq(const float* __restrict__ sq1, const float* __restrict__ sq2) {
    int i = blockIdx.x*256 + threadIdx.x;
    if (i >= 128*256) return;
    int n = i >> 8, k = i & 255;
    float w = 0.f;
    if (n < 64)  { if (k < 128)  w = sq1[n*128 + k]; }
    else         { if (k >= 128) w = sq2[(n-64)*128 + (k-128)]; }
    __nv_bfloat16 h = __float2bfloat16(w);
    g_bsqh[i] = h;
    g_bsql[i] = __float2bfloat16(w - bf2f(h));
}
__global__ void prep_bp2(const float* __restrict__ pwc2) {
    int i = blockIdx.x*256 + threadIdx.x;
    if (i >= 256*64) return;
    int n = i >> 6, k = i & 63;
    float w = (n < 192) ? pwc2[n*64 + k] : 0.f;
    __nv_bfloat16 h = __float2bfloat16(w);
    g_bp2h[i] = h;
    g_bp2l[i] = __float2bfloat16(w - bf2f(h));
}
__global__ void prep_bcv(const float* __restrict__ gwc, const float* __restrict__ pwc1) {
    int i = blockIdx.x*256 + threadIdx.x;
    if (i >= 2*128*352) return;
    int z = i / (128*352), r = i % (128*352);
    int n = r / 352, k = r % 352;
    int c = z*128 + n;
    float w = (k < 288) ? gwc[c*288 + (k & 31)*9 + (k >> 5)] : pwc1[c*64 + (k - 288)];
    __nv_bfloat16 h = __float2bfloat16(w);
    g_bcvh[i] = h;
    g_bcvl[i] = __float2bfloat16(w - bf2f(h));
}

// ---------------- roll + split x ----------------
__global__ __launch_bounds__(256) void xsplit(const float* __restrict__ x) {
    __shared__ float s[256][33];
    int bid = blockIdx.x;
    int b = bid >> 11, rem = bid & 2047;
    int hr = rem >> 3, w0 = (rem & 7) << 5;
    int tid = threadIdx.x, wid = tid >> 5, lane = tid & 31;
    int hs = ((hr + 4) & 255) << 8;
    for (int i = 0; i < 32; i++) {
        int idx = (i << 8) + tid;
        int c = idx >> 5, wp = idx & 31;
        s[c][wp] = x[(size_t)((b << 8) + c)*65536 + hs + ((w0 + wp + 4) & 255)];
    }
    __syncthreads();
    size_t t = (size_t)(b << 16) + (hr << 8) + w0 + lane;
    int c0 = wid << 5;
    for (int j = 0; j < 32; j += 8) {
        __nv_bfloat16 hv[8], lv[8];
#pragma unroll
        for (int e = 0; e < 8; e++) {
            float a = s[c0 + j + e][lane];
            hv[e] = __float2bfloat16(a);
            lv[e] = __float2bfloat16(a - bf2f(hv[e]));
        }
        *(uint4*)&g_xh[t*256 + c0 + j] = *(uint4*)hv;
        *(uint4*)&g_xl[t*256 + c0 + j] = *(uint4*)lv;
    }
}

// ---------------- epilogues ----------------
struct EQKVt {
    static constexpr bool HAS_POOL = false;
    static constexpr bool HAS_GN = true;
    const float* bias;
    __device__ void st2(int m, int n, int z, float v0, float v1) const {
        v0 += bias[n]; v1 += bias[n+1];
        if (n < 256) {
            *(float2*)&g_q[(size_t)m*256 + n] = make_float2(v0, v1);
        } else if (n < 512) {
            int c = n - 256;
            __nv_bfloat16 h0 = __float2bfloat16(v0), h1 = __float2bfloat16(v1);
            *(__nv_bfloat162*)&g_kh[(size_t)m*256 + c] = __halves2bfloat162(h0, h1);
            *(__nv_bfloat162*)&g_kl[(size_t)m*256 + c] = __halves2bfloat162(
                __float2bfloat16(v0 - bf2f(h0)), __float2bfloat16(v1 - bf2f(h1)));
        } else {
            int c = n - 512;
            __nv_bfloat16 h0 = __float2bfloat16(v0), h1 = __float2bfloat16(v1);
            *(__nv_bfloat162*)&g_vh[(size_t)m*256 + c] = __halves2bfloat162(h0, h1);
            *(__nv_bfloat162*)&g_vl[(size_t)m*256 + c] = __halves2bfloat162(
                __float2bfloat16(v0 - bf2f(h0)), __float2bfloat16(v1 - bf2f(h1)));
        }
    }
    __device__ int pslot(int n, int b) const { return -1; }
    __device__ float gnbias(int n) const { return bias[n]; }
};
struct ESQ {
    static constexpr bool HAS_POOL = true;
    static constexpr bool HAS_GN = false;
    __device__ void st2(int m, int n, int z, float v0, float v1) const {
        __nv_bfloat16 h0 = __float2bfloat16(v0), h1 = __float2bfloat16(v1);
        __nv_bfloat16 l0 = __float2bfloat16(v0 - bf2f(h0)), l1 = __float2bfloat16(v1 - bf2f(h1));
        if (n < 64) {
            *(__nv_bfloat162*)&g_uphi[(size_t)m*64 + n] = __halves2bfloat162(h0, h1);
            *(__nv_bfloat162*)&g_uplo[(size_t)m*64 + n] = __halves2bfloat162(l0, l1);
        } else {
            int nl = n - 64;
            *(__nv_bfloat162*)&g_ulsh[(size_t)m*64 + nl] = __halves2bfloat162(h0, h1);
            *(__nv_bfloat162*)&g_ulsl[(size_t)m*64 + nl] = __halves2bfloat162(l0, l1);
        }
    }
    __device__ int pslot(int n, int b) const { return n >= 64 ? (b << 9) + 448 + (n - 64) : -1; }
    __device__ float gnbias(int n) const { return 0.f; }
};
struct EY2h {
    static constexpr bool HAS_POOL = true;
    static constexpr bool HAS_GN = false;
    __device__ void st2(int m, int n, int z, float v0, float v1) const {
        if (n < 192) *(float2*)&g_y2[(size_t)m*192 + n] = make_float2(v0, v1);
    }
    __device__ int pslot(int n, int b) const { return n < 192 ? (b << 9) + 256 + n : -1; }
    __device__ float gnbias(int n) const { return 0.f; }
};

// ---------------- dedup split HMMA GEMM (+ optional fused pool / GN stats) ----------------
template<class EF>
__global__ __launch_bounds__(256, 2) void hgemmA(const __nv_bfloat16* __restrict__ Ah_,
                                                 const __nv_bfloat16* __restrict__ Al_, int lda,
                                                 const __nv_bfloat16* __restrict__ Bh_,
                                                 const __nv_bfloat16* __restrict__ Bl_, int ldb,
                                                 int nk, EF ef) {
    extern __shared__ __nv_bfloat16 sm[];
    int tid = threadIdx.x, lane = tid & 31, wid = tid >> 5;
    int m0 = blockIdx.y << 7, n0 = blockIdx.x << 7;
    uint32_t sbase = smem_u32(sm);
    int wm = (wid & 3) << 5, wn = (wid >> 2) << 6;
    int gid = lane >> 2, tig = lane & 3;
    int lr = lane & 7, lh = (lane >> 3) & 1, lk = lane >> 4;
    uint32_t offA[2];
#pragma unroll
    for (int mf = 0; mf < 2; mf++)
        offA[mf] = (uint32_t)(((wm + (mf << 4) + lr + lh*8)*24 + lk*8) << 1);
    int lq = lane >> 3;
    uint32_t offB[4];
#pragma unroll
    for (int p = 0; p < 4; p++)
        offB[p] = (uint32_t)(((wn + (p << 4) + lr + (lq >> 1)*8)*24 + (lq & 1)*8) << 1);

    float acc[2][8][4];
#pragma unroll
    for (int mf = 0; mf < 2; mf++)
#pragma unroll
        for (int nf = 0; nf < 8; nf++)
#pragma unroll
            for (int e = 0; e < 4; e++) acc[mf][nf][e] = 0.f;

    auto prefetch = [&](int ch, int s) {
        int k0 = ch << 5;
#pragma unroll
        for (int i = 0; i < 2; i++) {
            int idx = (i << 8) + tid;
            int r = idx >> 2, c4 = idx & 3;
            int g = c4 >> 1, ke = c4 & 1;
            uint32_t da = sbase + (uint32_t)((s*24576 + (g*128 + r)*24 + ke*8) << 1);
            size_t asrc = (size_t)(m0 + r)*lda + k0 + (c4 << 3);
            size_t bsrc = (size_t)(n0 + r)*ldb + k0 + (c4 << 3);
            CP_A16(da,          Ah_ + asrc);
            CP_A16(da + 12288,  Al_ + asrc);
            CP_A16(da + 24576,  Bh_ + bsrc);
            CP_A16(da + 36864,  Bl_ + bsrc);
        }
        CP_COMMIT();
    };
    prefetch(0, 0);
    for (int ch = 0; ch < nk; ch++) {
        if (ch + 1 < nk) prefetch(ch + 1, (ch + 1) & 1);
        else CP_COMMIT();
        CP_WAIT1();
        __syncthreads();
        uint32_t stb = sbase + (uint32_t)((ch & 1)*49152);
#pragma unroll
        for (int g = 0; g < 2; g++) {
            uint32_t gb = stb + (uint32_t)(g*6144);
            uint32_t a[2][4], b[8][2];
            ldsm4(b[0][0], b[0][1], b[1][0], b[1][1], gb + 24576 + offB[0]);
            ldsm4(b[2][0], b[2][1], b[3][0], b[3][1], gb + 24576 + offB[1]);
            ldsm4(b[4][0], b[4][1], b[5][0], b[5][1], gb + 24576 + offB[2]);
            ldsm4(b[6][0], b[6][1], b[7][0], b[7][1], gb + 24576 + offB[3]);
            ldsm4(a[0][0], a[0][1], a[0][2], a[0][3], gb + offA[0]);
            ldsm4(a[1][0], a[1][1], a[1][2], a[1][3], gb + offA[1]);
#pragma unroll
            for (int mf = 0; mf < 2; mf++)
#pragma unroll
                for (int nf = 0; nf < 8; nf++)
                    mma16816(acc[mf][nf], a[mf], b[nf]);
            ldsm4(a[0][0], a[0][1], a[0][2], a[0][3], gb + 12288 + offA[0]);
            ldsm4(a[1][0], a[1][1], a[1][2], a[1][3], gb + 12288 + offA[1]);
#pragma unroll
            for (int mf = 0; mf < 2; mf++)
#pragma unroll
                for (int nf = 0; nf < 8; nf++)
                    mma16816(acc[mf][nf], a[mf], b[nf]);
            ldsm4(b[0][0], b[0][1], b[1][0], b[1][1], gb + 36864 + offB[0]);
            ldsm4(b[2][0], b[2][1], b[3][0], b[3][1], gb + 36864 + offB[1]);
            ldsm4(b[4][0], b[4][1], b[5][0], b[5][1], gb + 36864 + offB[2]);
            ldsm4(b[6][0], b[6][1], b[7][0], b[7][1], gb + 36864 + offB[3]);
            ldsm4(a[0][0], a[0][1], a[0][2], a[0][3], gb + offA[0]);
            ldsm4(a[1][0], a[1][1], a[1][2], a[1][3], gb + offA[1]);
#pragma unroll
            for (int mf = 0; mf < 2; mf++)
#pragma unroll
                for (int nf = 0; nf < 8; nf++)
                    mma16816(acc[mf][nf], a[mf], b[nf]);
        }
        __syncthreads();
    }
#pragma unroll
    for (int mf = 0; mf < 2; mf++) {
        int row0 = m0 + wm + (mf << 4) + gid;
#pragma unroll
        for (int nf = 0; nf < 8; nf++) {
            int col = n0 + wn + (nf << 3) + (tig << 1);
            ef.st2(row0,     col, 0, acc[mf][nf][0], acc[mf][nf][1]);
            ef.st2(row0 + 8, col, 0, acc[mf][nf][2], acc[mf][nf][3]);
        }
    }
    if constexpr (EF::HAS_POOL) {
        float* red = (float*)sm;
        int contrib = ((wid & 3) << 3) + gid;
#pragma unroll
        for (int nf = 0; nf < 8; nf++)
#pragma unroll
            for (int j = 0; j < 2; j++) {
                float p = acc[0][nf][j] + acc[0][nf][j+2] + acc[1][nf][j] + acc[1][nf][j+2];
                red[(wn + (nf << 3) + (tig << 1) + j)*32 + contrib] = p;
            }
        __syncthreads();
        if (tid < 128) {
            float s = 0.f;
#pragma unroll
            for (int c2 = 0; c2 < 32; c2++) s += red[tid*32 + c2];
            int slot = ef.pslot(n0 + tid, m0 >> 16);
            if (slot >= 0) atomicAdd(&g_pool[slot], s);
        }
    }
    if constexpr (EF::HAS_GN) {
        if (n0 < 256) {
            float* redS = (float*)sm;
            float* redQ = redS + 4096;
            int contrib = ((wid & 3) << 3) + gid;
#pragma unroll
            for (int nf = 0; nf < 8; nf++)
#pragma unroll
                for (int j = 0; j < 2; j++) {
                    int col = wn + (nf << 3) + (tig << 1) + j;
                    float bb = ef.gnbias(n0 + col);
                    float v0 = acc[0][nf][j]   + bb, v1 = acc[0][nf][j+2] + bb;
                    float v2 = acc[1][nf][j]   + bb, v3 = acc[1][nf][j+2] + bb;
                    redS[col*32 + contrib] = v0 + v1 + v2 + v3;
                    redQ[col*32 + contrib] = v0*v0 + v1*v1 + v2*v2 + v3*v3;
                }
            __syncthreads();
            if (tid < 128) {
                float s = 0.f, s2 = 0.f;
#pragma unroll
                for (int c2 = 0; c2 < 32; c2++) { s += redS[tid*32 + c2]; s2 += redQ[tid*32 + c2]; }
                int g = (n0 + tid) >> 4, bb = m0 >> 16;
                atomicAdd(&g_gnstats[((bb << 4) + g)*2],     s);
                atomicAdd(&g_gnstats[((bb << 4) + g)*2 + 1], s2);
            }
        }
    }
}

// ---------------- out-projection GEMM with fused NCHW roll-scatter ----------------
__global__ __launch_bounds__(256, 2) void hgemmO(const __nv_bfloat16* __restrict__ Ah_,
                                                 const __nv_bfloat16* __restrict__ Al_,
                                                 const __nv_bfloat16* __restrict__ Bh_,
                                                 const __nv_bfloat16* __restrict__ Bl_,
                                                 const float* __restrict__ bias,
                                                 float* __restrict__ out) {
    extern __shared__ __nv_bfloat16 sm[];
    int tid = threadIdx.x, lane = tid & 31, wid = tid >> 5;
    int m0 = blockIdx.y << 7, n0 = blockIdx.x << 7;
    uint32_t sbase = smem_u32(sm);
    int wm = (wid & 3) << 5, wn = (wid >> 2) << 6;
    int gid = lane >> 2, tig = lane & 3;
    int lr = lane & 7, lh = (lane >> 3) & 1, lk = lane >> 4;
    uint32_t offA[2];
#pragma unroll
    for (int mf = 0; mf < 2; mf++)
        offA[mf] = (uint32_t)(((wm + (mf << 4) + lr + lh*8)*24 + lk*8) << 1);
    int lq = lane >> 3;
    uint32_t offB[4];
#pragma unroll
    for (int p = 0; p < 4; p++)
        offB[p] = (uint32_t)(((wn + (p << 4) + lr + (lq >> 1)*8)*24 + (lq & 1)*8) << 1);

    float acc[2][8][4];
#pragma unroll
    for (int mf = 0; mf < 2; mf++)
#pragma unroll
        for (int nf = 0; nf < 8; nf++)
#pragma unroll
            for (int e = 0; e < 4; e++) acc[mf][nf][e] = 0.f;

    auto prefetch = [&](int ch, int s) {
        int k0 = ch << 5;
#pragma unroll
        for (int i = 0; i < 2; i++) {
            int idx = (i << 8) + tid;
            int r = idx >> 2, c4 = idx & 3;
            int g = c4 >> 1, ke = c4 & 1;
            uint32_t da = sbase + (uint32_t)((s*24576 + (g*128 + r)*24 + ke*8) << 1);
            size_t asrc = (size_t)(m0 + r)*256 + k0 + (c4 << 3);
            size_t bsrc = (size_t)(n0 + r)*256 + k0 + (c4 << 3);
            CP_A16(da,          Ah_ + asrc);
            CP_A16(da + 12288,  Al_ + asrc);
            CP_A16(da + 24576,  Bh_ + bsrc);
            CP_A16(da + 36864,  Bl_ + bsrc);
        }
        CP_COMMIT();
    };
    prefetch(0, 0);
    for (int ch = 0; ch < 8; ch++) {
        if (ch + 1 < 8) prefetch(ch + 1, (ch + 1) & 1);
        else CP_COMMIT();
        CP_WAIT1();
        __syncthreads();
        uint32_t stb = sbase + (uint32_t)((ch & 1)*49152);
#pragma unroll
        for (int g = 0; g < 2; g++) {
            uint32_t gb = stb + (uint32_t)(g*6144);
            uint32_t a[2][4], b[8][2];
            ldsm4(b[0][0], b[0][1], b[1][0], b[1][1], gb + 24576 + offB[0]);
            ldsm4(b[2][0], b[2][1], b[3][0], b[3][1], gb + 24576 + offB[1]);
            ldsm4(b[4][0], b[4][1], b[5][0], b[5][1], gb + 24576 + offB[2]);
            ldsm4(b[6][0], b[6][1], b[7][0], b[7][1], gb + 24576 + offB[3]);
            ldsm4(a[0][0], a[0][1], a[0][2], a[0][3], gb + offA[0]);
            ldsm4(a[1][0], a[1][1], a[1][2], a[1][3], gb + offA[1]);
#pragma unroll
            for (int mf = 0; mf < 2; mf++)
#pragma unroll
                for (int nf = 0; nf < 8; nf++)
                    mma16816(acc[mf][nf], a[mf], b[nf]);
            ldsm4(a[0][0], a[0][1], a[0][2], a[0][3], gb + 12288 + offA[0]);
            ldsm4(a[1][0], a[1][1], a[1][2], a[1][3], gb + 12288 + offA[1]);
#pragma unroll
            for (int mf = 0; mf < 2; mf++)
#pragma unroll
                for (int nf = 0; nf < 8; nf++)
                    mma16816(acc[mf][nf], a[mf], b[nf]);
            ldsm4(b[0][0], b[0][1], b[1][0], b[1][1], gb + 36864 + offB[0]);
            ldsm4(b[2][0], b[2][1], b[3][0], b[3][1], gb + 36864 + offB[1]);
            ldsm4(b[4][0], b[4][1], b[5][0], b[5][1], gb + 36864 + offB[2]);
            ldsm4(b[6][0], b[6][1], b[7][0], b[7][1], gb + 36864 + offB[3]);
            ldsm4(a[0][0], a[0][1], a[0][2], a[0][3], gb + offA[0]);
            ldsm4(a[1][0], a[1][1], a[1][2], a[1][3], gb + offA[1]);
#pragma unroll
            for (int mf = 0; mf < 2; mf++)
#pragma unroll
                for (int nf = 0; nf < 8; nf++)
                    mma16816(acc[mf][nf], a[mf], b[nf]);
        }
        __syncthreads();
    }
    const int SP = 132;
    float* stage = (float*)sm;
#pragma unroll
    for (int chunk = 0; chunk < 4; chunk++) {
#pragma unroll
        for (int mf = 0; mf < 2; mf++) {
            int r0 = wm + (mf << 4) + gid;
#pragma unroll
            for (int rr = 0; rr < 2; rr++) {
                int r = r0 + (rr << 3);
                if ((r >> 5) == chunk) {
                    int rl = r & 31;
#pragma unroll
                    for (int nf = 0; nf < 8; nf++) {
                        int cl = wn + (nf << 3) + (tig << 1);
                        stage[rl*SP + cl]     = acc[mf][nf][rr*2]     + bias[n0 + cl];
                        stage[rl*SP + cl + 1] = acc[mf][nf][rr*2 + 1] + bias[n0 + cl + 1];
                    }
                }
            }
        }
        __syncthreads();
        int m = m0 + (chunk << 5) + lane;
        int b = m >> 16, pixi = m & 65535;
        int hr = pixi >> 8, wr = pixi & 255;
        size_t pbase = (size_t)(((hr + 4) & 255) << 8) + ((wr + 4) & 255);
        for (int nl = wid; nl < 128; nl += 8)
            out[(size_t)((b << 8) + n0 + nl)*65536 + pbase] = stage[lane*SP + nl];
        __syncthreads();
    }
}

// ---------------- conv GEMM: dedup split + async gather prefetch + fused pool ----------------
__global__ __launch_bounds__(256, 2) void hgemmC(const __nv_bfloat16* __restrict__ Bh_,
                                                 const __nv_bfloat16* __restrict__ Bl_,
                                                 const float* __restrict__ bias) {
    extern __shared__ __nv_bfloat16 sm[];
    int tid = threadIdx.x, lane = tid & 31, wid = tid >> 5;
    int m0 = blockIdx.y << 7, z = blockIdx.z;
    uint32_t sbase = smem_u32(sm);
    int wm = (wid & 3) << 5, wn = (wid >> 2) << 6;
    int gid = lane >> 2, tig = lane & 3;
    int lr = lane & 7, lh = (lane >> 3) & 1, lk = lane >> 4;
    uint32_t offA[2];
#pragma unroll
    for (int mf = 0; mf < 2; mf++)
        offA[mf] = (uint32_t)(((wm + (mf << 4) + lr + lh*8)*24 + lk*8) << 1);
    int lq = lane >> 3;
    uint32_t offB[4];
#pragma unroll
    for (int p = 0; p < 4; p++)
        offB[p] = (uint32_t)(((wn + (p << 4) + lr + (lq >> 1)*8)*24 + (lq & 1)*8) << 1);

    float acc[2][8][4];
#pragma unroll
    for (int mf = 0; mf < 2; mf++)
#pragma unroll
        for (int nf = 0; nf < 8; nf++)
#pragma unroll
            for (int e = 0; e < 4; e++) acc[mf][nf][e] = 0.f;

    const __nv_bfloat16* Bzh = Bh_ + (size_t)z*128*352;
    const __nv_bfloat16* Bzl = Bl_ + (size_t)z*128*352;

    auto prefetch = [&](int ch, int s) {
        int k0 = ch << 5;
#pragma unroll
        for (int i = 0; i < 2; i++) {
            int idx = (i << 8) + tid;
            int r = idx >> 2, c4 = idx & 3;
            int g = c4 >> 1, ke = c4 & 1;
            uint32_t da = sbase + (uint32_t)((s*24576 + (g*128 + r)*24 + ke*8) << 1);
            int k = k0 + (c4 << 3);
            int m = m0 + r;
            size_t aoff; int sz = 16;
            if (k < 288) {
                int tap = k >> 5, kl0 = k & 31;
                int dy = tap/3 - 1, dx = tap - (tap/3)*3 - 1;
                int b = m >> 16;
                int hr = ((m >> 8) & 255) + dy, wr = (m & 255) + dx;
                if ((unsigned)hr > 255u || (unsigned)wr > 255u) sz = 0;
                aoff = (size_t)((b << 16) + ((hr & 255) << 8) + (wr & 255))*64 + (z << 5) + kl0;
            } else {
                aoff = (size_t)m*64 + (k - 288);
            }
            CP_A16Z(da,         g_uphi + aoff, sz);
            CP_A16Z(da + 12288, g_uplo + aoff, sz);
            size_t boff = (size_t)r*352 + k;
            CP_A16(da + 24576, Bzh + boff);
            CP_A16(da + 36864, Bzl + boff);
        }
        CP_COMMIT();
    };
    prefetch(0, 0);
    for (int ch = 0; ch < 11; ch++) {
        if (ch + 1 < 11) prefetch(ch + 1, (ch + 1) & 1);
        else CP_COMMIT();
        CP_WAIT1();
        __syncthreads();
        uint32_t stb = sbase + (uint32_t)((ch & 1)*49152);
#pragma unroll
        for (int g = 0; g < 2; g++) {
            uint32_t gb = stb + (uint32_t)(g*6144);
            uint32_t a[2][4], b[8][2];
            ldsm4(b[0][0], b[0][1], b[1][0], b[1][1], gb + 24576 + offB[0]);
            ldsm4(b[2][0], b[2][1], b[3][0], b[3][1], gb + 24576 + offB[1]);
            ldsm4(b[4][0], b[4][1], b[5][0], b[5][1], gb + 24576 + offB[2]);
            ldsm4(b[6][0], b[6][1], b[7][0], b[7][1], gb + 24576 + offB[3]);
            ldsm4(a[0][0], a[0][1], a[0][2], a[0][3], gb + offA[0]);
            ldsm4(a[1][0], a[1][1], a[1][2], a[1][3], gb + offA[1]);
#pragma unroll
            for (int mf = 0; mf < 2; mf++)
#pragma unroll
                for (int nf = 0; nf < 8; nf++)
                    mma16816(acc[mf][nf], a[mf], b[nf]);
            ldsm4(a[0][0], a[0][1], a[0][2], a[0][3], gb + 12288 + offA[0]);
            ldsm4(a[1][0], a[1][1], a[1][2], a[1][3], gb + 12288 + offA[1]);
#pragma unroll
            for (int mf = 0; mf < 2; mf++)
#pragma unroll
                for (int nf = 0; nf < 8; nf++)
                    mma16816(acc[mf][nf], a[mf], b[nf]);
            ldsm4(b[0][0], b[0][1], b[1][0], b[1][1], gb + 36864 + offB[0]);
            ldsm4(b[2][0], b[2][1], b[3][0], b[3][1], gb + 36864 + offB[1]);
            ldsm4(b[4][0], b[4][1], b[5][0], b[5][1], gb + 36864 + offB[2]);
            ldsm4(b[6][0], b[6][1], b[7][0], b[7][1], gb + 36864 + offB[3]);
            ldsm4(a[0][0], a[0][1], a[0][2], a[0][3], gb + offA[0]);
            ldsm4(a[1][0], a[1][1], a[1][2], a[1][3], gb + offA[1]);
#pragma unroll
            for (int mf = 0; mf < 2; mf++)
#pragma unroll
                for (int nf = 0; nf < 8; nf++)
                    mma16816(acc[mf][nf], a[mf], b[nf]);
        }
        __syncthreads();
    }
#pragma unroll
    for (int mf = 0; mf < 2; mf++) {
        int row0 = m0 + wm + (mf << 4) + gid;
#pragma unroll
        for (int nf = 0; nf < 8; nf++) {
            int col = wn + (nf << 3) + (tig << 1);
            int c = (z << 7) + col;
            *(float2*)&g_y1[(size_t)row0*256 + c] =
                make_float2(acc[mf][nf][0] + bias[c], acc[mf][nf][1] + bias[c+1]);
            *(float2*)&g_y1[(size_t)(row0 + 8)*256 + c] =
                make_float2(acc[mf][nf][2] + bias[c], acc[mf][nf][3] + bias[c+1]);
        }
    }
    {
        float* red = (float*)sm;
        int contrib = ((wid & 3) << 3) + gid;
#pragma unroll
        for (int nf = 0; nf < 8; nf++)
#pragma unroll
            for (int j = 0; j < 2; j++) {
                int col = wn + (nf << 3) + (tig << 1) + j;
                float bb = bias[(z << 7) + col];
                float p = acc[0][nf][j] + acc[0][nf][j+2] + acc[1][nf][j] + acc[1][nf][j+2] + 4.f*bb;
                red[col*32 + contrib] = p;
            }
        __syncthreads();
        if (tid < 128) {
            float s = 0.f;
#pragma unroll
            for (int c2 = 0; c2 < 32; c2++) s += red[tid*32 + c2];
            atomicAdd(&g_pool[((m0 >> 16) << 9) + (z << 7) + tid], s);
        }
    }
}

// ---------------- SRU / softmax ----------------
__global__ void sru_elem(const float* __restrict__ gn_w, const float* __restrict__ gn_b) {
    int i = blockIdx.x*256 + threadIdx.x;
    int t = i >> 7, cp = i & 127;
    int b = t >> 16;
    int c1 = cp, c2 = cp + 128;
    float wsum = g_misc[0];
    int g1 = c1 >> 4, g2 = c2 >> 4;
    float m1 = g_gnstats[((b<<4)+g1)*2] / GN_N;
    float v1 = g_gnstats[((b<<4)+g1)*2+1] / GN_N - m1*m1;
    float m2 = g_gnstats[((b<<4)+g2)*2] / GN_N;
    float v2 = g_gnstats[((b<<4)+g2)*2+1] / GN_N - m2*m2;
    float w1c = gn_w[c1], w2c = gn_w[c2];
    float A1 = rsqrtf(v1 + 1e-5f)*w1c, B1 = gn_b[c1] - m1*rsqrtf(v1 + 1e-5f)*w1c;
    float A2 = rsqrtf(v2 + 1e-5f)*w2c, B2 = gn_b[c2] - m2*rsqrtf(v2 + 1e-5f)*w2c;
    float x1 = g_q[(size_t)t*256 + c1], x2 = g_q[(size_t)t*256 + c2];
    float rw1 = 1.0f/(1.0f + expf(-(x1*A1 + B1)*(w1c/wsum)));
    float rw2 = 1.0f/(1.0f + expf(-(x2*A2 + B2)*(w2c/wsum)));
    float w11 = rw1 > 0.5f ? 1.0f : rw1, w21 = rw1 > 0.5f ? 0.0f : rw1;
    float w12 = rw2 > 0.5f ? 1.0f : rw2, w22 = rw2 > 0.5f ? 0.0f : rw2;
    float o1 = w11*x1 + w22*x2;
    float o2 = w12*x2 + w21*x1;
    __nv_bfloat16 h1 = __float2bfloat16(o1), h2 = __float2bfloat16(o2);
    g_qah[(size_t)t*256 + c1] = h1;
    g_qal[(size_t)t*256 + c1] = __float2bfloat16(o1 - bf2f(h1));
    g_qah[(size_t)t*256 + c2] = h2;
    g_qal[(size_t)t*256 + c2] = __float2bfloat16(o2 - bf2f(h2));
}
__global__ void softmax512() {
    int b = blockIdx.x, t = threadIdx.x;
    __shared__ float sh[512];
    float v = g_pool[(b << 9) + t] * (1.0f/65536.0f);
    sh[t] = v;
    __syncthreads();
    for (int st = 256; st > 0; st >>= 1) { if (t < st) sh[t] = fmaxf(sh[t], sh[t + st]); __syncthreads(); }
    float mx = sh[0];
    __syncthreads();
    float e = expf(v - mx);
    sh[t] = e;
    __syncthreads();
    for (int st = 256; st > 0; st >>= 1) { if (t < st) sh[t] += sh[t + st]; __syncthreads(); }
    float sum = sh[0];
    __syncthreads();
    g_pool[(b << 9) + t] = e / sum;
}

// ---------------- HMMA windowed attention (fused CRU combine in K staging) ----------------
__global__ __launch_bounds__(128) void attn_mma(const float* __restrict__ rel_pos) {
    extern __shared__ __nv_bfloat16 smb[];
    float* rps = (float*)(smb + 49152);
    int tid = threadIdx.x, lane = tid & 31, wid = tid >> 5;
    int win = blockIdx.x, hg = blockIdx.y, b = blockIdx.z;
    int wy = win >> 5, wx = win & 31;
    int t0 = (b << 16) + (wy << 11) + (wx << 3);
    // stage K hi/lo, computing cru_combine on the fly
    for (int i = 0; i < 8; i++) {
        int idx = (i << 7) + tid;
        int hh = idx >> 8, r = idx & 255;
        int tok = r >> 2, c8 = (r & 3) << 3;
        int token = t0 + ((tok >> 3) << 8) + (tok & 7);
        int cg = (((hg << 2) + hh) << 5) + c8;
        float4 ya = *(const float4*)&g_y1[(size_t)token*256 + cg];
        float4 yb = *(const float4*)&g_y1[(size_t)token*256 + cg + 4];
        float y1v[8] = {ya.x, ya.y, ya.z, ya.w, yb.x, yb.y, yb.z, yb.w};
        float y2v[8];
        if (cg < 192) {
            float4 za = *(const float4*)&g_y2[(size_t)token*192 + cg];
            float4 zb = *(const float4*)&g_y2[(size_t)token*192 + cg + 4];
            y2v[0]=za.x; y2v[1]=za.y; y2v[2]=za.z; y2v[3]=za.w;
            y2v[4]=zb.x; y2v[5]=zb.y; y2v[6]=zb.z; y2v[7]=zb.w;
        } else {
            int nl = cg - 192;
            uint4 uh = *(const uint4*)&g_ulsh[(size_t)token*64 + nl];
            uint4 ul = *(const uint4*)&g_ulsl[(size_t)token*64 + nl];
            const __nv_bfloat16* ph = (const __nv_bfloat16*)&uh;
            const __nv_bfloat16* pl = (const __nv_bfloat16*)&ul;
#pragma unroll
            for (int e = 0; e < 8; e++) y2v[e] = bf2f(ph[e]) + bf2f(pl[e]);
        }
        __nv_bfloat16 hv[8], lv[8];
#pragma unroll
        for (int e = 0; e < 8; e++) {
            float o = __ldg(&g_pool[(b << 9) + cg + e])*y1v[e]
                    + __ldg(&g_pool[(b << 9) + 256 + cg + e])*y2v[e];
            hv[e] = __float2bfloat16(o);
            lv[e] = __float2bfloat16(o - bf2f(hv[e]));
        }
        int dst = hh*12288 + ((c8 >> 4)*64 + tok)*24 + (c8 & 15);
        *(uint4*)&smb[dst]        = *(uint4*)hv;
        *(uint4*)&smb[dst + 3072] = *(uint4*)lv;
    }
    // stage V transposed
    for (int i = 0; i < 32; i++) {
        int idx = (i << 7) + tid;
        int hh = idx >> 10, r = idx & 1023;
        int tok = r >> 4, dp = (r & 15) << 1;
        int token = t0 + ((tok >> 3) << 8) + (tok & 7);
        size_t src = (size_t)token*256 + (((hg << 2) + hh) << 5) + dp;
        __nv_bfloat162 vh = *(const __nv_bfloat162*)&g_vh[src];
        __nv_bfloat162 vl = *(const __nv_bfloat162*)&g_vl[src];
        int base = hh*12288 + 6144 + (tok >> 4)*768 + (tok & 15);
        smb[base + dp*24]            = vh.x;
        smb[base + (dp+1)*24]        = vh.y;
        smb[base + 3072 + dp*24]     = vl.x;
        smb[base + 3072 + (dp+1)*24] = vl.y;
    }
    for (int i = tid; i < 900; i += 128) {
        int hh = i / 225, r = i - hh*225;
        rps[i] = rel_pos[(((hg << 2) + hh))*225 + r];
    }
    __syncthreads();

    int hh = wid;
    uint32_t tb = smem_u32(smb) + (uint32_t)(hh*24576);
    uint32_t khb = tb, klb = tb + 6144, vhb = tb + 12288, vlb = tb + 18432;
    const float* rp = rps + hh*225;
    int gid = lane >> 2, tig = lane & 3;
    int lr = lane & 7, lq = lane >> 3;
    uint32_t offK[4], offV[2];
#pragma unroll
    for (int p = 0; p < 4; p++)
        offK[p] = (uint32_t)((((p << 4) + lr + (lq >> 1)*8)*24 + (lq & 1)*8) << 1);
#pragma unroll
    for (int p = 0; p < 2; p++)
        offV[p] = (uint32_t)((((p << 4) + lr + (lq >> 1)*8)*24 + (lq & 1)*8) << 1);
    bool lrm = wy == 31, lcm = wx == 31;
    int hbc = ((hg << 2) + hh) << 5;

    for (int half = 0; half < 2; half++) {
        int rbase = half << 5;
        uint32_t qh[2][2][4], ql[2][2][4];
#pragma unroll
        for (int mt = 0; mt < 2; mt++) {
            int r0 = rbase + (mt << 4) + gid;
            int tok0 = t0 + ((r0 >> 3) << 8) + (r0 & 7);
            int r1 = r0 + 8;
            int tok1 = t0 + ((r1 >> 3) << 8) + (r1 & 7);
#pragma unroll
            for (int kf = 0; kf < 2; kf++) {
                int kc = hbc + (kf << 4) + (tig << 1);
                qh[mt][kf][0] = *(const uint32_t*)&g_qah[(size_t)tok0*256 + kc];
                qh[mt][kf][1] = *(const uint32_t*)&g_qah[(size_t)tok1*256 + kc];
                qh[mt][kf][2] = *(const uint32_t*)&g_qah[(size_t)tok0*256 + kc + 8];
                qh[mt][kf][3] = *(const uint32_t*)&g_qah[(size_t)tok1*256 + kc + 8];
                ql[mt][kf][0] = *(const uint32_t*)&g_qal[(size_t)tok0*256 + kc];
                ql[mt][kf][1] = *(const uint32_t*)&g_qal[(size_t)tok1*256 + kc];
                ql[mt][kf][2] = *(const uint32_t*)&g_qal[(size_t)tok0*256 + kc + 8];
                ql[mt][kf][3] = *(const uint32_t*)&g_qal[(size_t)tok1*256 + kc + 8];
            }
        }
        float sacc[2][8][4];
#pragma unroll
        for (int mt = 0; mt < 2; mt++)
#pragma unroll
            for (int nt = 0; nt < 8; nt++)
#pragma unroll
                for (int e = 0; e < 4; e++) sacc[mt][nt][e] = 0.f;
#pragma unroll
        for (int kg = 0; kg < 2; kg++) {
            uint32_t bk[8][2];
            uint32_t kgb = khb + (uint32_t)(kg*3072);
            ldsm4(bk[0][0], bk[0][1], bk[1][0], bk[1][1], kgb + offK[0]);
            ldsm4(bk[2][0], bk[2][1], bk[3][0], bk[3][1], kgb + offK[1]);
            ldsm4(bk[4][0], bk[4][1], bk[5][0], bk[5][1], kgb + offK[2]);
            ldsm4(bk[6][0], bk[6][1], bk[7][0], bk[7][1], kgb + offK[3]);
#pragma unroll
            for (int mt = 0; mt < 2; mt++)
#pragma unroll
                for (int nt = 0; nt < 8; nt++) {
                    mma16816(sacc[mt][nt], qh[mt][kg], bk[nt]);
                    mma16816(sacc[mt][nt], ql[mt][kg], bk[nt]);
                }
            uint32_t lgb = klb + (uint32_t)(kg*3072);
            ldsm4(bk[0][0], bk[0][1], bk[1][0], bk[1][1], lgb + offK[0]);
            ldsm4(bk[2][0], bk[2][1], bk[3][0], bk[3][1], lgb + offK[1]);
            ldsm4(bk[4][0], bk[4][1], bk[5][0], bk[5][1], lgb + offK[2]);
            ldsm4(bk[6][0], bk[6][1], bk[7][0], bk[7][1], lgb + offK[3]);
#pragma unroll
            for (int mt = 0; mt < 2; mt++)
#pragma unroll
                for (int nt = 0; nt < 8; nt++)
                    mma16816(sacc[mt][nt], qh[mt][kg], bk[nt]);
        }
#pragma unroll
        for (int mt = 0; mt < 2; mt++)
#pragma unroll
            for (int rr = 0; rr < 2; rr++) {
                int row = rbase + (mt << 4) + gid + (rr << 3);
                int ph = row >> 3, pw = row & 7;
                float vv[16];
                float mx = -1e30f;
#pragma unroll
                for (int nt = 0; nt < 8; nt++)
#pragma unroll
                    for (int j = 0; j < 2; j++) {
                        int col = (nt << 3) + (tig << 1) + j;
                        int qy = col >> 3, qw = col & 7;
                        float v = sacc[mt][nt][rr*2 + j]*SCALE + rp[(ph - qy + 7)*15 + (pw - qw + 7)];
                        if ((lrm && ((ph < 4) != (qy < 4))) || (lcm && ((pw < 4) != (qw < 4)))) v = -1e30f;
                        vv[nt*2 + j] = v;
                        mx = fmaxf(mx, v);
                    }
                mx = fmaxf(mx, __shfl_xor_sync(0xffffffff, mx, 1));
                mx = fmaxf(mx, __shfl_xor_sync(0xffffffff, mx, 2));
                float s = 0.f;
#pragma unroll
                for (int e = 0; e < 16; e++) { vv[e] = expf(vv[e] - mx); s += vv[e]; }
                s += __shfl_xor_sync(0xffffffff, s, 1);
                s += __shfl_xor_sync(0xffffffff, s, 2);
                float inv = 1.0f / s;
#pragma unroll
                for (int nt = 0; nt < 8; nt++)
#pragma unroll
                    for (int j = 0; j < 2; j++)
                        sacc[mt][nt][rr*2 + j] = vv[nt*2 + j]*inv;
            }
        float oacc[2][4][4];
#pragma unroll
        for (int mt = 0; mt < 2; mt++)
#pragma unroll
            for (int nt = 0; nt < 4; nt++)
#pragma unroll
                for (int e = 0; e < 4; e++) oacc[mt][nt][e] = 0.f;
#pragma unroll
        for (int kf = 0; kf < 4; kf++) {
            uint32_t pfh[2][4], pfl[2][4];
#pragma unroll
            for (int mt = 0; mt < 2; mt++) {
#pragma unroll
                for (int e = 0; e < 4; e++) {
                    int nt = 2*kf + (e >> 1);
                    float p0 = sacc[mt][nt][(e & 1)*2];
                    float p1 = sacc[mt][nt][(e & 1)*2 + 1];
                    __nv_bfloat162 h2 = __floats2bfloat162_rn(p0, p1);
                    pfh[mt][e] = *(uint32_t*)&h2;
                    __nv_bfloat162 l2 = __floats2bfloat162_rn(p0 - bf2f(h2.x), p1 - bf2f(h2.y));
                    pfl[mt][e] = *(uint32_t*)&l2;
                }
            }
            uint32_t bv[4][2];
            uint32_t vgb = vhb + (uint32_t)(kf*1536);
            ldsm4(bv[0][0], bv[0][1], bv[1][0], bv[1][1], vgb + offV[0]);
            ldsm4(bv[2][0], bv[2][1], bv[3][0], bv[3][1], vgb + offV[1]);
#pragma unroll
            for (int mt = 0; mt < 2; mt++)
#pragma unroll
                for (int nt = 0; nt < 4; nt++) {
                    mma16816(oacc[mt][nt], pfh[mt], bv[nt]);
                    mma16816(oacc[mt][nt], pfl[mt], bv[nt]);
                }
            uint32_t lgb = vlb + (uint32_t)(kf*1536);
            ldsm4(bv[0][0], bv[0][1], bv[1][0], bv[1][1], lgb + offV[0]);
            ldsm4(bv[2][0], bv[2][1], bv[3][0], bv[3][1], lgb + offV[1]);
#pragma unroll
            for (int mt = 0; mt < 2; mt++)
#pragma unroll
                for (int nt = 0; nt < 4; nt++)
                    mma16816(oacc[mt][nt], pfh[mt], bv[nt]);
        }
#pragma unroll
        for (int mt = 0; mt < 2; mt++) {
            int r0 = rbase + (mt << 4) + gid;
            int tok0 = t0 + ((r0 >> 3) << 8) + (r0 & 7);
            int r1 = r0 + 8;
            int tok1 = t0 + ((r1 >> 3) << 8) + (r1 & 7);
#pragma unroll
            for (int nt = 0; nt < 4; nt++) {
                int c = hbc + (nt << 3) + (tig << 1);
                float a0 = oacc[mt][nt][0], a1 = oacc[mt][nt][1];
                float a2 = oacc[mt][nt][2], a3 = oacc[mt][nt][3];
                __nv_bfloat162 h0 = __floats2bfloat162_rn(a0, a1);
                __nv_bfloat162 h1 = __floats2bfloat162_rn(a2, a3);
                *(__nv_bfloat162*)&g_atth[(size_t)tok0*256 + c] = h0;
                *(__nv_bfloat162*)&g_atth[(size_t)tok1*256 + c] = h1;
                *(__nv_bfloat162*)&g_attl[(size_t)tok0*256 + c] =
                    __floats2bfloat162_rn(a0 - bf2f(h0.x), a1 - bf2f(h0.y));
                *(__nv_bfloat162*)&g_attl[(size_t)tok1*256 + c] =
                    __floats2bfloat162_rn(a2 - bf2f(h1.x), a3 - bf2f(h1.y));
            }
        }
    }
}

// ---------------- launch ----------------
extern "C" void kernel_launch(void* const* d_in, const int* in_sizes, int n_in,
                              void* d_out, int out_size) {
    const float* x      = (const float*)d_in[0];
    const float* w_qkv  = (const float*)d_in[1];
    const float* b_qkv  = (const float*)d_in[2];
    const float* rel_pos= (const float*)d_in[3];
    const float* gn_w   = (const float*)d_in[4];
    const float* gn_b   = (const float*)d_in[5];
    const float* sq1    = (const float*)d_in[6];
    const float* sq2    = (const float*)d_in[7];
    const float* gwc    = (const float*)d_in[8];
    const float* gwc_b  = (const float*)d_in[9];
    const float* pwc1   = (const float*)d_in[10];
    const float* pwc2   = (const float*)d_in[11];
    const float* w_out  = (const float*)d_in[12];
    const float* b_out  = (const float*)d_in[13];
    float* out = (float*)d_out;

    __nv_bfloat16 *p_bqh, *p_bql, *p_bouth, *p_boutl, *p_bsqh, *p_bsql, *p_bp2h, *p_bp2l;
    __nv_bfloat16 *p_xh, *p_xl, *p_kh, *p_kl, *p_atth, *p_attl, *p_ulsh, *p_ulsl;
    __nv_bfloat16 *p_bcvh, *p_bcvl;
    cudaGetSymbolAddress((void**)&p_bqh,   g_bqh);
    cudaGetSymbolAddress((void**)&p_bql,   g_bql);
    cudaGetSymbolAddress((void**)&p_bouth, g_bouth);
    cudaGetSymbolAddress((void**)&p_boutl, g_boutl);
    cudaGetSymbolAddress((void**)&p_bsqh,  g_bsqh);
    cudaGetSymbolAddress((void**)&p_bsql,  g_bsql);
    cudaGetSymbolAddress((void**)&p_bp2h,  g_bp2h);
    cudaGetSymbolAddress((void**)&p_bp2l,  g_bp2l);
    cudaGetSymbolAddress((void**)&p_xh,    g_xh);
    cudaGetSymbolAddress((void**)&p_xl,    g_xl);
    cudaGetSymbolAddress((void**)&p_kh,    g_kh);
    cudaGetSymbolAddress((void**)&p_kl,    g_kl);
    cudaGetSymbolAddress((void**)&p_atth,  g_atth);
    cudaGetSymbolAddress((void**)&p_attl,  g_attl);
    cudaGetSymbolAddress((void**)&p_ulsh,  g_ulsh);
    cudaGetSymbolAddress((void**)&p_ulsl,  g_ulsl);
    cudaGetSymbolAddress((void**)&p_bcvh,  g_bcvh);
    cudaGetSymbolAddress((void**)&p_bcvl,  g_bcvl);

    const int DSM = 98304;
    const int ASM = 49152*2 + 900*4;
    cudaFuncSetAttribute(hgemmA<EQKVt>, cudaFuncAttributeMaxDynamicSharedMemorySize, DSM);
    cudaFuncSetAttribute(hgemmA<ESQ>,   cudaFuncAttributeMaxDynamicSharedMemorySize, DSM);
    cudaFuncSetAttribute(hgemmA<EY2h>,  cudaFuncAttributeMaxDynamicSharedMemorySize, DSM);
    cudaFuncSetAttribute(hgemmO,        cudaFuncAttributeMaxDynamicSharedMemorySize, DSM);
    cudaFuncSetAttribute(hgemmC,        cudaFuncAttributeMaxDynamicSharedMemorySize, DSM);
    cudaFuncSetAttribute(attn_mma,      cudaFuncAttributeMaxDynamicSharedMemorySize, ASM);

    zero_small<<<4, 256>>>();                                              // 0
    prep_bw<<<768, 256>>>(w_qkv, p_bqh, p_bql, 768*256);                   // 1
    xsplit<<<4096, 256>>>(x);                                              // 2
    hgemmA<EQKVt><<<dim3(6, 1024), 256, DSM>>>(p_xh, p_xl, 256,
                                               p_bqh, p_bql, 256, 8, EQKVt{b_qkv}); // 3 (profiled)

    sum_gnw<<<1, 256>>>(gn_w);
    sru_elem<<<65536, 256>>>(gn_w, gn_b);

    prep_bsq<<<128, 256>>>(sq1, sq2);
    hgemmA<ESQ><<<dim3(1, 1024), 256, DSM>>>(p_kh, p_kl, 256, p_bsqh, p_bsql, 256, 8, ESQ{});
    prep_bcv<<<(2*128*352 + 255)/256, 256>>>(gwc, pwc1);
    hgemmC<<<dim3(1, 1024, 2), 256, DSM>>>(p_bcvh, p_bcvl, gwc_b);
    prep_bp2<<<64, 256>>>(pwc2);
    hgemmA<EY2h><<<dim3(2, 1024), 256, DSM>>>(p_ulsh, p_ulsl, 64, p_bp2h, p_bp2l, 64, 2, EY2h{});

    softmax512<<<2, 512>>>();

    attn_mma<<<dim3(1024, 2, 2), 128, ASM>>>(rel_pos);
    prep_bw<<<256, 256>>>(w_out, p_bouth, p_boutl, 256*256);
    hgemmO<<<dim3(2, 1024), 256, DSM>>>(p_atth, p_attl, p_bouth, p_boutl, b_out, out);
}